// round 1
// baseline (speedup 1.0000x reference)
#include <cuda_runtime.h>
#include <cuda_bf16.h>
#include <math.h>

// ---------------- problem constants (fixed shapes) ----------------
#define BATCH   8
#define HH      128
#define WW      128
#define CC      256
#define NHEAD   8
#define HDIM    32
#define WSZ     8
#define SSHIFT  4
#define NTOK    64                 // tokens per window
#define NWIN    2048               // total windows (8 * 16 * 16)
#define TTOT    131072             // total tokens (8*128*128)
#define SCALE_F 0.1767766952966369f // 32^-0.5
#define EPS_F   1e-5f

// ---------------- scratch (device globals; no allocation) ----------------
__device__ float g_hw[TTOT * CC];        // LN1 output (windowed order); reused for LN2 output
__device__ float g_qkv[TTOT * 3 * CC];   // qkv (windowed order)
__device__ float g_o[TTOT * CC];         // attn out (windowed); reused for fc1 out
__device__ float g_proj[TTOT * CC];      // proj out (windowed)
__device__ float g_x2[TTOT * CC];        // x + attn (original order)

// ---------------- LayerNorm (optionally gathering into shifted-window order) ---
template <bool GATHER>
__global__ void ln_kernel(const float* __restrict__ x,
                          const float* __restrict__ gamma,
                          const float* __restrict__ beta,
                          float* __restrict__ out)
{
    __shared__ float sh[8], sh2[8];
    int row = blockIdx.x;              // destination row
    long src_row;
    if (GATHER) {
        int token = row & 63;
        int wg    = row >> 6;
        int batch = wg >> 8;           // /256 windows per image
        int win   = wg & 255;
        int ys = ((win >> 4) << 3) + (token >> 3);
        int xs = ((win & 15) << 3) + (token & 7);
        int y  = (ys + SSHIFT) & 127;  // reverse of roll(-SS)
        int xx = (xs + SSHIFT) & 127;
        src_row = (long)batch * (HH * WW) + y * WW + xx;
    } else {
        src_row = row;
    }
    int c = threadIdx.x;               // 256 threads == channels
    float v = x[src_row * CC + c];
    float s = v, s2 = v * v;
    #pragma unroll
    for (int o = 16; o > 0; o >>= 1) {
        s  += __shfl_xor_sync(0xffffffffu, s,  o);
        s2 += __shfl_xor_sync(0xffffffffu, s2, o);
    }
    if ((c & 31) == 0) { sh[c >> 5] = s; sh2[c >> 5] = s2; }
    __syncthreads();
    float t = 0.f, t2 = 0.f;
    #pragma unroll
    for (int i = 0; i < 8; i++) { t += sh[i]; t2 += sh2[i]; }
    float mean = t * (1.0f / CC);
    float var  = t2 * (1.0f / CC) - mean * mean;
    float inv  = rsqrtf(var + EPS_F);
    out[(long)row * CC + c] = (v - mean) * inv * gamma[c] + beta[c];
}

// ---------------- generic fp32 tiled GEMM: C = A[M,K] @ B[K,N] + bias -----------
// optional exact-erf GELU, optional residual add (same row order as C)
#define BM 64
#define BN 64
#define BK 16

template <bool GELU, bool RESID>
__global__ void gemm_kernel(const float* __restrict__ A,
                            const float* __restrict__ Bw,
                            const float* __restrict__ bias,
                            const float* __restrict__ R,
                            float* __restrict__ C,
                            int M, int N, int K)
{
    __shared__ float As[BK][BM + 4];
    __shared__ float Bs[BK][BN + 4];

    int tid = threadIdx.x;
    int bm = blockIdx.y * BM;
    int bn = blockIdx.x * BN;
    int tx = tid & 15, ty = tid >> 4;

    const int lmA = tid >> 2;          // 0..63
    const int lkA = (tid & 3) << 2;    // 0,4,8,12
    const int lkB = tid >> 4;          // 0..15
    const int lnB = (tid & 15) << 2;   // 0..60

    float acc[4][4] = {};

    for (int k0 = 0; k0 < K; k0 += BK) {
        float4 a = *(const float4*)(A + (long)(bm + lmA) * K + k0 + lkA);
        As[lkA + 0][lmA] = a.x;
        As[lkA + 1][lmA] = a.y;
        As[lkA + 2][lmA] = a.z;
        As[lkA + 3][lmA] = a.w;
        float4 b = *(const float4*)(Bw + (long)(k0 + lkB) * N + bn + lnB);
        *(float4*)&Bs[lkB][lnB] = b;
        __syncthreads();
        #pragma unroll
        for (int k = 0; k < BK; k++) {
            float4 av = *(const float4*)&As[k][ty << 2];
            float4 bv = *(const float4*)&Bs[k][tx << 2];
            float ar[4] = {av.x, av.y, av.z, av.w};
            float br[4] = {bv.x, bv.y, bv.z, bv.w};
            #pragma unroll
            for (int i = 0; i < 4; i++)
                #pragma unroll
                for (int j = 0; j < 4; j++)
                    acc[i][j] = fmaf(ar[i], br[j], acc[i][j]);
        }
        __syncthreads();
    }

    #pragma unroll
    for (int i = 0; i < 4; i++) {
        int r = bm + (ty << 2) + i;
        #pragma unroll
        for (int j = 0; j < 4; j++) {
            int c = bn + (tx << 2) + j;
            float v = acc[i][j] + bias[c];
            if (GELU) v = 0.5f * v * (1.0f + erff(v * 0.70710678118654752f));
            if (RESID) v += R[(long)r * N + c];
            C[(long)r * N + c] = v;
        }
    }
}

// ---------------- windowed attention: one block per (window, head) --------------
__global__ void attn_kernel(const float* __restrict__ qkv,
                            const float* __restrict__ rel_bias,
                            float* __restrict__ out)
{
    __shared__ float qs[64][33];
    __shared__ float ks[64][33];
    __shared__ float vs[64][33];

    int bx = blockIdx.x;
    int h  = bx & 7;
    long wg = bx >> 3;
    int tid = threadIdx.x;

    for (int e = tid; e < 64 * 32; e += 256) {
        int m = e >> 5, d = e & 31;
        long base = (wg * 64 + m) * (3 * CC) + h * HDIM + d;
        qs[m][d] = qkv[base] * SCALE_F;
        ks[m][d] = qkv[base + CC];
        vs[m][d] = qkv[base + 2 * CC];
    }
    __syncthreads();

    int r = tid >> 2;   // query row 0..63
    int g = tid & 3;    // 4-lane group handles 16 keys each
    int rh = r >> 3, rw = r & 7;

    float s[16];
    #pragma unroll
    for (int mi = 0; mi < 16; mi++) {
        int m = g * 16 + mi;
        float a = 0.f;
        #pragma unroll
        for (int d = 0; d < 32; d++) a = fmaf(qs[r][d], ks[m][d], a);
        int mh = m >> 3, mw = m & 7;
        int idx = (rh - mh + 7) * 15 + (rw - mw + 7);
        s[mi] = a + rel_bias[idx * NHEAD + h];
    }

    float mx = s[0];
    #pragma unroll
    for (int i = 1; i < 16; i++) mx = fmaxf(mx, s[i]);
    mx = fmaxf(mx, __shfl_xor_sync(0xffffffffu, mx, 1));
    mx = fmaxf(mx, __shfl_xor_sync(0xffffffffu, mx, 2));

    float sum = 0.f;
    #pragma unroll
    for (int i = 0; i < 16; i++) { s[i] = __expf(s[i] - mx); sum += s[i]; }
    sum += __shfl_xor_sync(0xffffffffu, sum, 1);
    sum += __shfl_xor_sync(0xffffffffu, sum, 2);
    float inv = 1.0f / sum;

    float acc[32];
    #pragma unroll
    for (int d = 0; d < 32; d++) acc[d] = 0.f;
    #pragma unroll
    for (int mi = 0; mi < 16; mi++) {
        int m = g * 16 + mi;
        float p = s[mi] * inv;
        #pragma unroll
        for (int d = 0; d < 32; d++) acc[d] = fmaf(p, vs[m][d], acc[d]);
    }
    #pragma unroll
    for (int d = 0; d < 32; d++) {
        acc[d] += __shfl_xor_sync(0xffffffffu, acc[d], 1);
        acc[d] += __shfl_xor_sync(0xffffffffu, acc[d], 2);
    }
    #pragma unroll
    for (int j = 0; j < 8; j++) {
        int d = g * 8 + j;
        out[(wg * 64 + r) * CC + h * HDIM + d] = acc[d];
    }
}

// ---------------- un-window (reverse shift) + shortcut residual -----------------
__global__ void unwindow_add(const float* __restrict__ x,
                             const float* __restrict__ proj,
                             float* __restrict__ out)
{
    int t = blockIdx.x;                 // original token index
    int batch = t >> 14;
    int pos   = t & 16383;
    int y  = pos >> 7, xx = pos & 127;
    int ys = (y - SSHIFT) & 127;
    int xs = (xx - SSHIFT) & 127;
    long wrow = ((long)batch * 256 + (ys >> 3) * 16 + (xs >> 3)) * 64
              + (ys & 7) * 8 + (xs & 7);
    int c = threadIdx.x;
    out[(long)t * CC + c] = x[(long)t * CC + c] + proj[wrow * CC + c];
}

// ---------------- launch ----------------
extern "C" void kernel_launch(void* const* d_in, const int* in_sizes, int n_in,
                              void* d_out, int out_size)
{
    const float* x       = (const float*)d_in[0];
    const float* norm1_g = (const float*)d_in[1];
    const float* norm1_b = (const float*)d_in[2];
    const float* qkv_w   = (const float*)d_in[3];
    const float* qkv_b   = (const float*)d_in[4];
    const float* rel_b   = (const float*)d_in[5];
    const float* proj_w  = (const float*)d_in[6];
    const float* proj_b  = (const float*)d_in[7];
    const float* norm2_g = (const float*)d_in[8];
    const float* norm2_b = (const float*)d_in[9];
    const float* fc1_w   = (const float*)d_in[10];
    const float* fc1_b   = (const float*)d_in[11];
    const float* fc2_w   = (const float*)d_in[12];
    const float* fc2_b   = (const float*)d_in[13];
    float* out = (float*)d_out;

    float *p_hw, *p_qkv, *p_o, *p_proj, *p_x2;
    cudaGetSymbolAddress((void**)&p_hw,   g_hw);
    cudaGetSymbolAddress((void**)&p_qkv,  g_qkv);
    cudaGetSymbolAddress((void**)&p_o,    g_o);
    cudaGetSymbolAddress((void**)&p_proj, g_proj);
    cudaGetSymbolAddress((void**)&p_x2,   g_x2);

    // 1) LN1 + shifted-window gather
    ln_kernel<true><<<TTOT, 256>>>(x, norm1_g, norm1_b, p_hw);

    // 2) QKV GEMM: [131072,256] @ [256,768]
    gemm_kernel<false, false><<<dim3(768 / BN, TTOT / BM), 256>>>(
        p_hw, qkv_w, qkv_b, nullptr, p_qkv, TTOT, 768, CC);

    // 3) windowed attention
    attn_kernel<<<NWIN * NHEAD, 256>>>(p_qkv, rel_b, p_o);

    // 4) proj GEMM (windowed order)
    gemm_kernel<false, false><<<dim3(CC / BN, TTOT / BM), 256>>>(
        p_o, proj_w, proj_b, nullptr, p_proj, TTOT, CC, CC);

    // 5) un-window + shortcut residual -> x2
    unwindow_add<<<TTOT, 256>>>(x, p_proj, p_x2);

    // 6) LN2
    ln_kernel<false><<<TTOT, 256>>>(p_x2, norm2_g, norm2_b, p_hw);

    // 7) fc1 + exact GELU
    gemm_kernel<true, false><<<dim3(CC / BN, TTOT / BM), 256>>>(
        p_hw, fc1_w, fc1_b, nullptr, p_o, TTOT, CC, CC);

    // 8) fc2 + residual -> out
    gemm_kernel<false, true><<<dim3(CC / BN, TTOT / BM), 256>>>(
        p_o, fc2_w, fc2_b, p_x2, out, TTOT, CC, CC);
}

// round 3
// speedup vs baseline: 3.1106x; 3.1106x over previous
#include <cuda_runtime.h>
#include <math.h>
#include <stdint.h>

// ---------------- problem constants ----------------
#define CC      256
#define NHEAD   8
#define HDIM    32
#define SSHIFT  4
#define NWIN    2048
#define TTOT    131072
#define SCALE_F 0.1767766952966369f
#define EPS_F   1e-5f

// ---------------- scratch ----------------
__device__ float g_hw[TTOT * CC];
__device__ float g_qkv[TTOT * 3 * CC];
__device__ float g_o[TTOT * CC];
__device__ float g_proj[TTOT * CC];
__device__ float g_x2[TTOT * CC];

// ---------------- helpers ----------------
__device__ __forceinline__ uint32_t tf32_bits(float x) {
    uint32_t r;
    asm("cvt.rna.tf32.f32 %0, %1;" : "=r"(r) : "f"(x));
    return r;
}

__device__ __forceinline__ void mma_tf32_16n8k8(float c[4],
                                                uint32_t a0, uint32_t a1, uint32_t a2, uint32_t a3,
                                                uint32_t b0, uint32_t b1) {
    asm volatile(
        "mma.sync.aligned.m16n8k8.row.col.f32.tf32.tf32.f32 "
        "{%0,%1,%2,%3}, {%4,%5,%6,%7}, {%8,%9}, {%0,%1,%2,%3};"
        : "+f"(c[0]), "+f"(c[1]), "+f"(c[2]), "+f"(c[3])
        : "r"(a0), "r"(a1), "r"(a2), "r"(a3), "r"(b0), "r"(b1));
}

// ================ TF32 mma.sync GEMM: C[M,N] = A[M,K] @ B[K,N] + bias ================
// CTA tile 128x128, BK=32, 8 warps (4 m x 2 n), warp tile 32x64.
#define BMT 128
#define BNT 128
#define BKT 32
#define AS_STRIDE 36          // words per A row (pad 4)
#define BS_STRIDE 136         // words per B row (pad 8)
#define ABUF_W (128 * AS_STRIDE)
#define BBUF_W (32 * BS_STRIDE)
#define BUF_W  (ABUF_W + BBUF_W)

template <bool GELU, bool RESID>
__global__ __launch_bounds__(256, 2)
void gemm_mma(const float* __restrict__ A, const float* __restrict__ Bw,
              const float* __restrict__ bias, const float* __restrict__ R,
              float* __restrict__ C, int M, int N, int K)
{
    extern __shared__ float sm[];

    int tid  = threadIdx.x;
    int bn   = blockIdx.x * BNT;
    int bm   = blockIdx.y * BMT;
    int warp = tid >> 5, lane = tid & 31;
    int wm   = (warp & 3) * 32;       // warp row offset in tile
    int wn   = (warp >> 2) * 64;      // warp col offset in tile
    int g    = lane >> 2;             // groupID 0..7
    int t    = lane & 3;              // thread-in-group 0..3

    float c[2][8][4];
    #pragma unroll
    for (int mi = 0; mi < 2; mi++)
        #pragma unroll
        for (int ni = 0; ni < 8; ni++)
            #pragma unroll
            for (int r = 0; r < 4; r++) c[mi][ni][r] = 0.f;

    // ---- stage loader ----
    auto load_stage = [&](int buf, int k0) {
        float* As = sm + buf * BUF_W;
        float* Bs = As + ABUF_W;
        #pragma unroll
        for (int i = 0; i < 4; i++) {
            int fid = tid + i * 256;
            int row = fid >> 3, kq = fid & 7;
            float4 v = *(const float4*)(A + (size_t)(bm + row) * K + k0 + kq * 4);
            v.x = __uint_as_float(tf32_bits(v.x));
            v.y = __uint_as_float(tf32_bits(v.y));
            v.z = __uint_as_float(tf32_bits(v.z));
            v.w = __uint_as_float(tf32_bits(v.w));
            *(float4*)(As + row * AS_STRIDE + kq * 4) = v;
        }
        #pragma unroll
        for (int i = 0; i < 4; i++) {
            int fid = tid + i * 256;
            int k = fid >> 5, nq = fid & 31;
            float4 v = *(const float4*)(Bw + (size_t)(k0 + k) * N + bn + nq * 4);
            v.x = __uint_as_float(tf32_bits(v.x));
            v.y = __uint_as_float(tf32_bits(v.y));
            v.z = __uint_as_float(tf32_bits(v.z));
            v.w = __uint_as_float(tf32_bits(v.w));
            *(float4*)(Bs + k * BS_STRIDE + nq * 4) = v;
        }
    };

    auto compute_stage = [&](int buf) {
        const float* As = sm + buf * BUF_W;
        const float* Bs = As + ABUF_W;
        #pragma unroll
        for (int kt = 0; kt < 4; kt++) {
            int kb = kt * 8;
            uint32_t a[2][4];
            #pragma unroll
            for (int mi = 0; mi < 2; mi++) {
                const float* ar = As + (wm + mi * 16) * AS_STRIDE + kb;
                a[mi][0] = __float_as_uint(ar[g * AS_STRIDE + t]);
                a[mi][1] = __float_as_uint(ar[(g + 8) * AS_STRIDE + t]);
                a[mi][2] = __float_as_uint(ar[g * AS_STRIDE + t + 4]);
                a[mi][3] = __float_as_uint(ar[(g + 8) * AS_STRIDE + t + 4]);
            }
            #pragma unroll
            for (int ni = 0; ni < 8; ni++) {
                const float* br = Bs + kb * BS_STRIDE + wn + ni * 8 + g;
                uint32_t b0 = __float_as_uint(br[t * BS_STRIDE]);
                uint32_t b1 = __float_as_uint(br[(t + 4) * BS_STRIDE]);
                mma_tf32_16n8k8(c[0][ni], a[0][0], a[0][1], a[0][2], a[0][3], b0, b1);
                mma_tf32_16n8k8(c[1][ni], a[1][0], a[1][1], a[1][2], a[1][3], b0, b1);
            }
        }
    };

    const int niter = K / BKT;
    load_stage(0, 0);
    __syncthreads();
    for (int it = 0; it < niter; ++it) {
        if (it + 1 < niter) load_stage((it + 1) & 1, (it + 1) * BKT);
        compute_stage(it & 1);
        __syncthreads();
    }

    // ---- epilogue: direct float2 stores, fused bias/gelu/resid ----
    #pragma unroll
    for (int mi = 0; mi < 2; mi++) {
        int row0 = bm + wm + mi * 16 + g;
        #pragma unroll
        for (int ni = 0; ni < 8; ni++) {
            int col = bn + wn + ni * 8 + 2 * t;
            float b0 = bias[col], b1 = bias[col + 1];
            float v0 = c[mi][ni][0] + b0;
            float v1 = c[mi][ni][1] + b1;
            float v2 = c[mi][ni][2] + b0;
            float v3 = c[mi][ni][3] + b1;
            if (GELU) {
                v0 = 0.5f * v0 * (1.0f + erff(v0 * 0.70710678118654752f));
                v1 = 0.5f * v1 * (1.0f + erff(v1 * 0.70710678118654752f));
                v2 = 0.5f * v2 * (1.0f + erff(v2 * 0.70710678118654752f));
                v3 = 0.5f * v3 * (1.0f + erff(v3 * 0.70710678118654752f));
            }
            if (RESID) {
                float2 r0 = *(const float2*)(R + (size_t)row0 * N + col);
                float2 r1 = *(const float2*)(R + (size_t)(row0 + 8) * N + col);
                v0 += r0.x; v1 += r0.y; v2 += r1.x; v3 += r1.y;
            }
            *(float2*)(C + (size_t)row0 * N + col)       = make_float2(v0, v1);
            *(float2*)(C + (size_t)(row0 + 8) * N + col) = make_float2(v2, v3);
        }
    }
}

// ================ LayerNorm (warp per row), optional shifted-window gather ================
template <bool GATHER>
__global__ void ln8(const float* __restrict__ x,
                    const float* __restrict__ gamma,
                    const float* __restrict__ beta,
                    float* __restrict__ out)
{
    int w = threadIdx.x >> 5, lane = threadIdx.x & 31;
    long drow = (long)blockIdx.x * 8 + w;
    long srow;
    if (GATHER) {
        int token = (int)(drow & 63);
        int wg = (int)(drow >> 6);
        int batch = wg >> 8, win = wg & 255;
        int ys = ((win >> 4) << 3) + (token >> 3);
        int xs = ((win & 15) << 3) + (token & 7);
        int y  = (ys + SSHIFT) & 127;
        int xx = (xs + SSHIFT) & 127;
        srow = (long)batch * 16384 + y * 128 + xx;
    } else srow = drow;

    const float4* px = (const float4*)(x + srow * CC);
    float4 v0 = px[lane], v1 = px[lane + 32];
    float s  = v0.x + v0.y + v0.z + v0.w + v1.x + v1.y + v1.z + v1.w;
    float s2 = v0.x*v0.x + v0.y*v0.y + v0.z*v0.z + v0.w*v0.w
             + v1.x*v1.x + v1.y*v1.y + v1.z*v1.z + v1.w*v1.w;
    #pragma unroll
    for (int o = 16; o > 0; o >>= 1) {
        s  += __shfl_xor_sync(0xffffffffu, s,  o);
        s2 += __shfl_xor_sync(0xffffffffu, s2, o);
    }
    float mean = s * (1.0f / CC);
    float inv = rsqrtf(s2 * (1.0f / CC) - mean * mean + EPS_F);
    float4 g0 = *(const float4*)(gamma + lane * 4), g1 = *(const float4*)(gamma + 128 + lane * 4);
    float4 b0 = *(const float4*)(beta  + lane * 4), b1 = *(const float4*)(beta  + 128 + lane * 4);
    float4 o0, o1;
    o0.x = (v0.x - mean) * inv * g0.x + b0.x; o0.y = (v0.y - mean) * inv * g0.y + b0.y;
    o0.z = (v0.z - mean) * inv * g0.z + b0.z; o0.w = (v0.w - mean) * inv * g0.w + b0.w;
    o1.x = (v1.x - mean) * inv * g1.x + b1.x; o1.y = (v1.y - mean) * inv * g1.y + b1.y;
    o1.z = (v1.z - mean) * inv * g1.z + b1.z; o1.w = (v1.w - mean) * inv * g1.w + b1.w;
    float4* po = (float4*)(out + drow * CC);
    po[lane] = o0; po[lane + 32] = o1;
}

// ======== fused: x2 = x + unwindow(proj); ln_out = LN(x2) (warp per row) ========
__global__ void fuse_res_ln(const float* __restrict__ x,
                            const float* __restrict__ proj,
                            const float* __restrict__ gamma,
                            const float* __restrict__ beta,
                            float* __restrict__ x2,
                            float* __restrict__ ln_out)
{
    int w = threadIdx.x >> 5, lane = threadIdx.x & 31;
    long t = (long)blockIdx.x * 8 + w;
    int batch = (int)(t >> 14);
    int pos = (int)(t & 16383);
    int y = pos >> 7, xx = pos & 127;
    int ys = (y - SSHIFT) & 127;
    int xs = (xx - SSHIFT) & 127;
    long wrow = ((long)batch * 256 + (ys >> 3) * 16 + (xs >> 3)) * 64 + (ys & 7) * 8 + (xs & 7);

    const float4* px = (const float4*)(x + t * CC);
    const float4* pp = (const float4*)(proj + wrow * CC);
    float4 v0 = px[lane], v1 = px[lane + 32];
    float4 p0 = pp[lane], p1 = pp[lane + 32];
    v0.x += p0.x; v0.y += p0.y; v0.z += p0.z; v0.w += p0.w;
    v1.x += p1.x; v1.y += p1.y; v1.z += p1.z; v1.w += p1.w;
    float4* px2 = (float4*)(x2 + t * CC);
    px2[lane] = v0; px2[lane + 32] = v1;

    float s  = v0.x + v0.y + v0.z + v0.w + v1.x + v1.y + v1.z + v1.w;
    float s2 = v0.x*v0.x + v0.y*v0.y + v0.z*v0.z + v0.w*v0.w
             + v1.x*v1.x + v1.y*v1.y + v1.z*v1.z + v1.w*v1.w;
    #pragma unroll
    for (int o = 16; o > 0; o >>= 1) {
        s  += __shfl_xor_sync(0xffffffffu, s,  o);
        s2 += __shfl_xor_sync(0xffffffffu, s2, o);
    }
    float mean = s * (1.0f / CC);
    float inv = rsqrtf(s2 * (1.0f / CC) - mean * mean + EPS_F);
    float4 g0 = *(const float4*)(gamma + lane * 4), g1 = *(const float4*)(gamma + 128 + lane * 4);
    float4 b0 = *(const float4*)(beta  + lane * 4), b1 = *(const float4*)(beta  + 128 + lane * 4);
    float4 o0, o1;
    o0.x = (v0.x - mean) * inv * g0.x + b0.x; o0.y = (v0.y - mean) * inv * g0.y + b0.y;
    o0.z = (v0.z - mean) * inv * g0.z + b0.z; o0.w = (v0.w - mean) * inv * g0.w + b0.w;
    o1.x = (v1.x - mean) * inv * g1.x + b1.x; o1.y = (v1.y - mean) * inv * g1.y + b1.y;
    o1.z = (v1.z - mean) * inv * g1.z + b1.z; o1.w = (v1.w - mean) * inv * g1.w + b1.w;
    float4* po = (float4*)(ln_out + t * CC);
    po[lane] = o0; po[lane + 32] = o1;
}

// ================ register-tiled windowed attention ================
__global__ __launch_bounds__(256)
void attn_kernel(const float* __restrict__ qkv,
                 const float* __restrict__ rel_bias,
                 float* __restrict__ out)
{
    __shared__ float qs_t[32][68];   // [d][m]
    __shared__ float ks_t[32][68];
    __shared__ float vs[64][36];     // [m][d]
    __shared__ float ps[64][68];     // [r][m]
    __shared__ float bt[225];

    int bx = blockIdx.x;
    int h = bx & 7;
    long wg = bx >> 3;
    int tid = threadIdx.x;

    for (int e = tid; e < 64 * 32; e += 256) {
        int m = e >> 5, d = e & 31;
        size_t base = ((size_t)wg * 64 + m) * (3 * CC) + h * HDIM + d;
        qs_t[d][m] = qkv[base] * SCALE_F;
        ks_t[d][m] = qkv[base + CC];
        vs[m][d]   = qkv[base + 2 * CC];
    }
    if (tid < 225) bt[tid] = rel_bias[tid * NHEAD + h];
    __syncthreads();

    int ty = tid >> 4, tx = tid & 15;

    float s[4][4] = {};
    #pragma unroll
    for (int d = 0; d < 32; d++) {
        float4 a = *(const float4*)&qs_t[d][4 * ty];
        float4 b = *(const float4*)&ks_t[d][4 * tx];
        float ar[4] = {a.x, a.y, a.z, a.w};
        float br[4] = {b.x, b.y, b.z, b.w};
        #pragma unroll
        for (int i = 0; i < 4; i++)
            #pragma unroll
            for (int j = 0; j < 4; j++)
                s[i][j] = fmaf(ar[i], br[j], s[i][j]);
    }
    float rmax[4];
    #pragma unroll
    for (int i = 0; i < 4; i++) {
        int r = 4 * ty + i, rh = r >> 3, rw = r & 7;
        float mx = -1e30f;
        #pragma unroll
        for (int j = 0; j < 4; j++) {
            int m = 4 * tx + j, mh = m >> 3, mw = m & 7;
            s[i][j] += bt[(rh - mh + 7) * 15 + (rw - mw + 7)];
            mx = fmaxf(mx, s[i][j]);
        }
        rmax[i] = mx;
    }
    #pragma unroll
    for (int o = 1; o < 16; o <<= 1)
        #pragma unroll
        for (int i = 0; i < 4; i++)
            rmax[i] = fmaxf(rmax[i], __shfl_xor_sync(0xffffffffu, rmax[i], o));
    float rsum[4] = {};
    #pragma unroll
    for (int i = 0; i < 4; i++)
        #pragma unroll
        for (int j = 0; j < 4; j++) {
            s[i][j] = __expf(s[i][j] - rmax[i]);
            rsum[i] += s[i][j];
        }
    #pragma unroll
    for (int o = 1; o < 16; o <<= 1)
        #pragma unroll
        for (int i = 0; i < 4; i++)
            rsum[i] += __shfl_xor_sync(0xffffffffu, rsum[i], o);
    #pragma unroll
    for (int i = 0; i < 4; i++) {
        float inv = 1.0f / rsum[i];
        float4 pv = make_float4(s[i][0] * inv, s[i][1] * inv, s[i][2] * inv, s[i][3] * inv);
        *(float4*)&ps[4 * ty + i][4 * tx] = pv;
    }
    __syncthreads();

    int tyA = tid >> 3, txA = tid & 7;
    float o0[4] = {}, o1[4] = {};
    #pragma unroll
    for (int m = 0; m < 64; m++) {
        float a0 = ps[2 * tyA][m];
        float a1 = ps[2 * tyA + 1][m];
        float4 v = *(const float4*)&vs[m][4 * txA];
        o0[0] = fmaf(a0, v.x, o0[0]); o0[1] = fmaf(a0, v.y, o0[1]);
        o0[2] = fmaf(a0, v.z, o0[2]); o0[3] = fmaf(a0, v.w, o0[3]);
        o1[0] = fmaf(a1, v.x, o1[0]); o1[1] = fmaf(a1, v.y, o1[1]);
        o1[2] = fmaf(a1, v.z, o1[2]); o1[3] = fmaf(a1, v.w, o1[3]);
    }
    size_t ob = ((size_t)wg * 64 + 2 * tyA) * CC + h * HDIM + 4 * txA;
    *(float4*)(out + ob)      = make_float4(o0[0], o0[1], o0[2], o0[3]);
    *(float4*)(out + ob + CC) = make_float4(o1[0], o1[1], o1[2], o1[3]);
}

// ---------------- launch ----------------
extern "C" void kernel_launch(void* const* d_in, const int* in_sizes, int n_in,
                              void* d_out, int out_size)
{
    const float* x       = (const float*)d_in[0];
    const float* norm1_g = (const float*)d_in[1];
    const float* norm1_b = (const float*)d_in[2];
    const float* qkv_w   = (const float*)d_in[3];
    const float* qkv_b   = (const float*)d_in[4];
    const float* rel_b   = (const float*)d_in[5];
    const float* proj_w  = (const float*)d_in[6];
    const float* proj_b  = (const float*)d_in[7];
    const float* norm2_g = (const float*)d_in[8];
    const float* norm2_b = (const float*)d_in[9];
    const float* fc1_w   = (const float*)d_in[10];
    const float* fc1_b   = (const float*)d_in[11];
    const float* fc2_w   = (const float*)d_in[12];
    const float* fc2_b   = (const float*)d_in[13];
    float* out = (float*)d_out;

    float *p_hw, *p_qkv, *p_o, *p_proj, *p_x2;
    cudaGetSymbolAddress((void**)&p_hw,   g_hw);
    cudaGetSymbolAddress((void**)&p_qkv,  g_qkv);
    cudaGetSymbolAddress((void**)&p_o,    g_o);
    cudaGetSymbolAddress((void**)&p_proj, g_proj);
    cudaGetSymbolAddress((void**)&p_x2,   g_x2);

    const int SMEM = 2 * BUF_W * 4;  // 71680 bytes
    cudaFuncSetAttribute(gemm_mma<false, false>, cudaFuncAttributeMaxDynamicSharedMemorySize, SMEM);
    cudaFuncSetAttribute(gemm_mma<true,  false>, cudaFuncAttributeMaxDynamicSharedMemorySize, SMEM);
    cudaFuncSetAttribute(gemm_mma<false, true >, cudaFuncAttributeMaxDynamicSharedMemorySize, SMEM);

    // 1) LN1 + shifted-window gather
    ln8<true><<<TTOT / 8, 256>>>(x, norm1_g, norm1_b, p_hw);

    // 2) QKV GEMM [131072,256]x[256,768]
    gemm_mma<false, false><<<dim3(6, TTOT / 128), 256, SMEM>>>(
        p_hw, qkv_w, qkv_b, nullptr, p_qkv, TTOT, 768, CC);

    // 3) windowed attention
    attn_kernel<<<NWIN * NHEAD, 256>>>(p_qkv, rel_b, p_o);

    // 4) proj GEMM
    gemm_mma<false, false><<<dim3(2, TTOT / 128), 256, SMEM>>>(
        p_o, proj_w, proj_b, nullptr, p_proj, TTOT, CC, CC);

    // 5) fused unwindow + residual + LN2
    fuse_res_ln<<<TTOT / 8, 256>>>(x, p_proj, norm2_g, norm2_b, p_x2, p_hw);

    // 6) fc1 + GELU
    gemm_mma<true, false><<<dim3(2, TTOT / 128), 256, SMEM>>>(
        p_hw, fc1_w, fc1_b, nullptr, p_o, TTOT, CC, CC);

    // 7) fc2 + residual -> out
    gemm_mma<false, true><<<dim3(2, TTOT / 128), 256, SMEM>>>(
        p_o, fc2_w, fc2_b, p_x2, out, TTOT, CC, CC);
}

// round 4
// speedup vs baseline: 3.5768x; 1.1499x over previous
#include <cuda_runtime.h>
#include <math.h>
#include <stdint.h>

// ---------------- problem constants ----------------
#define CC      256
#define NHEAD   8
#define HDIM    32
#define SSHIFT  4
#define NWIN    2048
#define TTOT    131072
#define SCALE_F 0.1767766952966369f
#define EPS_F   1e-5f

// ---------------- scratch ----------------
__device__ float g_hw[TTOT * CC];
__device__ float g_qkv[TTOT * 3 * CC];
__device__ float g_o[TTOT * CC];
__device__ float g_proj[TTOT * CC];
__device__ float g_x2[TTOT * CC];

// ---------------- helpers ----------------
__device__ __forceinline__ uint32_t smem_u32(const void* p) {
    uint32_t a;
    asm("{ .reg .u64 t; cvta.to.shared.u64 t, %1; cvt.u32.u64 %0, t; }" : "=r"(a) : "l"(p));
    return a;
}
__device__ __forceinline__ float tf32r(float x) {
    float r; asm("cvt.rna.tf32.f32 %0, %1;" : "=f"(r) : "f"(x)); return r;
}
__device__ __forceinline__ void mma_tf32_16n8k8(float c[4],
                                                uint32_t a0, uint32_t a1, uint32_t a2, uint32_t a3,
                                                uint32_t b0, uint32_t b1) {
    asm volatile(
        "mma.sync.aligned.m16n8k8.row.col.f32.tf32.tf32.f32 "
        "{%0,%1,%2,%3}, {%4,%5,%6,%7}, {%8,%9}, {%0,%1,%2,%3};"
        : "+f"(c[0]), "+f"(c[1]), "+f"(c[2]), "+f"(c[3])
        : "r"(a0), "r"(a1), "r"(a2), "r"(a3), "r"(b0), "r"(b1));
}
#define CP16(dst, src) \
    asm volatile("cp.async.cg.shared.global [%0], [%1], 16;" :: "r"(dst), "l"(src) : "memory")
#define CP_COMMIT() asm volatile("cp.async.commit_group;" ::: "memory")
#define CP_WAIT1()  asm volatile("cp.async.wait_group 1;" ::: "memory")
#define CP_WAIT0()  asm volatile("cp.async.wait_group 0;" ::: "memory")

// ================ TF32 mma.sync GEMM with cp.async double buffer ================
// CTA tile 128x128, BK=32, 8 warps (4 m x 2 n), warp tile 32x64, 2 CTAs/SM.
#define BMT 128
#define BNT 128
#define BKT 32
#define AS_STRIDE 36
#define BS_STRIDE 136
#define ABUF_W (128 * AS_STRIDE)
#define BBUF_W (32 * BS_STRIDE)
#define BUF_W  (ABUF_W + BBUF_W)

template <bool GELU, bool RESID>
__global__ __launch_bounds__(256, 2)
void gemm_cp(const float* __restrict__ A, const float* __restrict__ Bw,
             const float* __restrict__ bias, const float* __restrict__ R,
             float* __restrict__ C, int M, int N, int K)
{
    extern __shared__ float sm[];
    uint32_t sm0 = smem_u32(sm);

    int tid  = threadIdx.x;
    int bn   = blockIdx.x * BNT;
    int bm   = blockIdx.y * BMT;
    int warp = tid >> 5, lane = tid & 31;
    int wm   = (warp & 3) * 32;
    int wn   = (warp >> 2) * 64;
    int g    = lane >> 2;
    int t    = lane & 3;

    // per-thread load coords
    const int arow = tid >> 3, akq = (tid & 7) * 4;        // A: 32 rows per pass, 4 passes
    const int bk   = tid >> 5, bnq = (tid & 31) * 4;       // B: 8 k-rows per pass, 4 passes

    float c[2][8][4];
    #pragma unroll
    for (int mi = 0; mi < 2; mi++)
        #pragma unroll
        for (int ni = 0; ni < 8; ni++)
            #pragma unroll
            for (int r = 0; r < 4; r++) c[mi][ni][r] = 0.f;

    auto load_stage = [&](int buf, int k0) {
        uint32_t As = sm0 + buf * (BUF_W * 4);
        uint32_t Bs = As + ABUF_W * 4;
        #pragma unroll
        for (int i = 0; i < 4; i++) {
            int row = arow + i * 32;
            CP16(As + (row * AS_STRIDE + akq) * 4,
                 A + (size_t)(bm + row) * K + k0 + akq);
        }
        #pragma unroll
        for (int i = 0; i < 4; i++) {
            int k = bk + i * 8;
            CP16(Bs + (k * BS_STRIDE + bnq) * 4,
                 Bw + (size_t)(k0 + k) * N + bn + bnq);
        }
        CP_COMMIT();
    };

    auto compute_stage = [&](int buf) {
        const uint32_t* As = (const uint32_t*)(sm + buf * BUF_W);
        const uint32_t* Bs = As + ABUF_W;
        #pragma unroll
        for (int kt = 0; kt < 4; kt++) {
            int kb = kt * 8;
            uint32_t a[2][4];
            #pragma unroll
            for (int mi = 0; mi < 2; mi++) {
                const uint32_t* ar = As + (wm + mi * 16) * AS_STRIDE + kb;
                a[mi][0] = ar[g * AS_STRIDE + t];
                a[mi][1] = ar[(g + 8) * AS_STRIDE + t];
                a[mi][2] = ar[g * AS_STRIDE + t + 4];
                a[mi][3] = ar[(g + 8) * AS_STRIDE + t + 4];
            }
            #pragma unroll
            for (int ni = 0; ni < 8; ni++) {
                const uint32_t* br = Bs + kb * BS_STRIDE + wn + ni * 8 + g;
                uint32_t b0 = br[t * BS_STRIDE];
                uint32_t b1 = br[(t + 4) * BS_STRIDE];
                mma_tf32_16n8k8(c[0][ni], a[0][0], a[0][1], a[0][2], a[0][3], b0, b1);
                mma_tf32_16n8k8(c[1][ni], a[1][0], a[1][1], a[1][2], a[1][3], b0, b1);
            }
        }
    };

    const int niter = K / BKT;
    load_stage(0, 0);
    for (int it = 0; it < niter; ++it) {
        if (it + 1 < niter) {
            load_stage((it + 1) & 1, (it + 1) * BKT);
            CP_WAIT1();
        } else {
            CP_WAIT0();
        }
        __syncthreads();
        compute_stage(it & 1);
        __syncthreads();
    }

    // ---- epilogue ----
    #pragma unroll
    for (int mi = 0; mi < 2; mi++) {
        int row0 = bm + wm + mi * 16 + g;
        #pragma unroll
        for (int ni = 0; ni < 8; ni++) {
            int col = bn + wn + ni * 8 + 2 * t;
            float b0 = bias[col], b1 = bias[col + 1];
            float v0 = c[mi][ni][0] + b0;
            float v1 = c[mi][ni][1] + b1;
            float v2 = c[mi][ni][2] + b0;
            float v3 = c[mi][ni][3] + b1;
            if (GELU) {
                v0 = 0.5f * v0 * (1.0f + erff(v0 * 0.70710678118654752f));
                v1 = 0.5f * v1 * (1.0f + erff(v1 * 0.70710678118654752f));
                v2 = 0.5f * v2 * (1.0f + erff(v2 * 0.70710678118654752f));
                v3 = 0.5f * v3 * (1.0f + erff(v3 * 0.70710678118654752f));
            }
            if (RESID) {
                float2 r0 = *(const float2*)(R + (size_t)row0 * N + col);
                float2 r1 = *(const float2*)(R + (size_t)(row0 + 8) * N + col);
                v0 += r0.x; v1 += r0.y; v2 += r1.x; v3 += r1.y;
            }
            *(float2*)(C + (size_t)row0 * N + col)       = make_float2(v0, v1);
            *(float2*)(C + (size_t)(row0 + 8) * N + col) = make_float2(v2, v3);
        }
    }
}

// ================ tensor-core windowed attention (one block per window,head) =====
__global__ __launch_bounds__(128)
void attn_mma(const float* __restrict__ qkv,
              const float* __restrict__ rel_bias,
              float* __restrict__ out)
{
    __shared__ float qs[64][36];   // Q [m][d] * SCALE (tf32)
    __shared__ float kst[32][68];  // K^T [d][m] (tf32)
    __shared__ float vs[64][36];   // V [m][d]  (tf32)
    __shared__ float ps[64][68];   // P [r][m]  (tf32)
    __shared__ float bt[225];

    int bx = blockIdx.x;
    int h = bx & 7;
    long wg = bx >> 3;
    int tid = threadIdx.x;
    int warp = tid >> 5, lane = tid & 31;
    int g = lane >> 2, t = lane & 3;

    for (int e = tid; e < 64 * 32; e += 128) {
        int m = e >> 5, d = e & 31;
        size_t base = ((size_t)wg * 64 + m) * (3 * CC) + h * HDIM + d;
        qs[m][d]  = tf32r(qkv[base] * SCALE_F);
        kst[d][m] = tf32r(qkv[base + CC]);
        vs[m][d]  = tf32r(qkv[base + 2 * CC]);
    }
    for (int i = tid; i < 225; i += 128) bt[i] = rel_bias[i * NHEAD + h];
    __syncthreads();

    int wm = warp * 16;

    // ---- S = Q @ K^T ----
    float s[8][4];
    #pragma unroll
    for (int ni = 0; ni < 8; ni++)
        #pragma unroll
        for (int r = 0; r < 4; r++) s[ni][r] = 0.f;

    #pragma unroll
    for (int kt = 0; kt < 4; kt++) {
        int kb = kt * 8;
        uint32_t a0 = __float_as_uint(qs[wm + g][kb + t]);
        uint32_t a1 = __float_as_uint(qs[wm + g + 8][kb + t]);
        uint32_t a2 = __float_as_uint(qs[wm + g][kb + t + 4]);
        uint32_t a3 = __float_as_uint(qs[wm + g + 8][kb + t + 4]);
        #pragma unroll
        for (int ni = 0; ni < 8; ni++) {
            uint32_t b0 = __float_as_uint(kst[kb + t][ni * 8 + g]);
            uint32_t b1 = __float_as_uint(kst[kb + t + 4][ni * 8 + g]);
            mma_tf32_16n8k8(s[ni], a0, a1, a2, a3, b0, b1);
        }
    }

    // ---- bias + softmax on fragments ----
    int r0 = wm + g, r1 = wm + g + 8;
    int rh0 = r0 >> 3, rw0 = r0 & 7;
    int rh1 = r1 >> 3, rw1 = r1 & 7;
    float mx0 = -1e30f, mx1 = -1e30f;
    #pragma unroll
    for (int ni = 0; ni < 8; ni++) {
        #pragma unroll
        for (int cc2 = 0; cc2 < 2; cc2++) {
            int col = ni * 8 + 2 * t + cc2;
            int mh = col >> 3, mw = col & 7;
            s[ni][cc2]     += bt[(rh0 - mh + 7) * 15 + (rw0 - mw + 7)];
            s[ni][2 + cc2] += bt[(rh1 - mh + 7) * 15 + (rw1 - mw + 7)];
            mx0 = fmaxf(mx0, s[ni][cc2]);
            mx1 = fmaxf(mx1, s[ni][2 + cc2]);
        }
    }
    mx0 = fmaxf(mx0, __shfl_xor_sync(0xffffffffu, mx0, 1));
    mx0 = fmaxf(mx0, __shfl_xor_sync(0xffffffffu, mx0, 2));
    mx1 = fmaxf(mx1, __shfl_xor_sync(0xffffffffu, mx1, 1));
    mx1 = fmaxf(mx1, __shfl_xor_sync(0xffffffffu, mx1, 2));
    float sum0 = 0.f, sum1 = 0.f;
    #pragma unroll
    for (int ni = 0; ni < 8; ni++) {
        s[ni][0] = __expf(s[ni][0] - mx0); sum0 += s[ni][0];
        s[ni][1] = __expf(s[ni][1] - mx0); sum0 += s[ni][1];
        s[ni][2] = __expf(s[ni][2] - mx1); sum1 += s[ni][2];
        s[ni][3] = __expf(s[ni][3] - mx1); sum1 += s[ni][3];
    }
    sum0 += __shfl_xor_sync(0xffffffffu, sum0, 1);
    sum0 += __shfl_xor_sync(0xffffffffu, sum0, 2);
    sum1 += __shfl_xor_sync(0xffffffffu, sum1, 1);
    sum1 += __shfl_xor_sync(0xffffffffu, sum1, 2);
    float inv0 = 1.0f / sum0, inv1 = 1.0f / sum1;
    #pragma unroll
    for (int ni = 0; ni < 8; ni++) {
        int col = ni * 8 + 2 * t;
        *(float2*)&ps[r0][col] = make_float2(tf32r(s[ni][0] * inv0), tf32r(s[ni][1] * inv0));
        *(float2*)&ps[r1][col] = make_float2(tf32r(s[ni][2] * inv1), tf32r(s[ni][3] * inv1));
    }
    __syncwarp();

    // ---- O = P @ V ----
    float o[4][4];
    #pragma unroll
    for (int ni = 0; ni < 4; ni++)
        #pragma unroll
        for (int r = 0; r < 4; r++) o[ni][r] = 0.f;
    #pragma unroll
    for (int kt = 0; kt < 8; kt++) {
        int kb = kt * 8;
        uint32_t a0 = __float_as_uint(ps[wm + g][kb + t]);
        uint32_t a1 = __float_as_uint(ps[wm + g + 8][kb + t]);
        uint32_t a2 = __float_as_uint(ps[wm + g][kb + t + 4]);
        uint32_t a3 = __float_as_uint(ps[wm + g + 8][kb + t + 4]);
        #pragma unroll
        for (int ni = 0; ni < 4; ni++) {
            uint32_t b0 = __float_as_uint(vs[kb + t][ni * 8 + g]);
            uint32_t b1 = __float_as_uint(vs[kb + t + 4][ni * 8 + g]);
            mma_tf32_16n8k8(o[ni], a0, a1, a2, a3, b0, b1);
        }
    }
    size_t ob0 = ((size_t)wg * 64 + r0) * CC + h * HDIM;
    size_t ob1 = ((size_t)wg * 64 + r1) * CC + h * HDIM;
    #pragma unroll
    for (int ni = 0; ni < 4; ni++) {
        int col = ni * 8 + 2 * t;
        *(float2*)(out + ob0 + col) = make_float2(o[ni][0], o[ni][1]);
        *(float2*)(out + ob1 + col) = make_float2(o[ni][2], o[ni][3]);
    }
}

// ================ LayerNorm (warp per row), optional shifted-window gather ================
template <bool GATHER>
__global__ void ln8(const float* __restrict__ x,
                    const float* __restrict__ gamma,
                    const float* __restrict__ beta,
                    float* __restrict__ out)
{
    int w = threadIdx.x >> 5, lane = threadIdx.x & 31;
    long drow = (long)blockIdx.x * 8 + w;
    long srow;
    if (GATHER) {
        int token = (int)(drow & 63);
        int wg = (int)(drow >> 6);
        int batch = wg >> 8, win = wg & 255;
        int ys = ((win >> 4) << 3) + (token >> 3);
        int xs = ((win & 15) << 3) + (token & 7);
        int y  = (ys + SSHIFT) & 127;
        int xx = (xs + SSHIFT) & 127;
        srow = (long)batch * 16384 + y * 128 + xx;
    } else srow = drow;

    const float4* px = (const float4*)(x + srow * CC);
    float4 v0 = px[lane], v1 = px[lane + 32];
    float s  = v0.x + v0.y + v0.z + v0.w + v1.x + v1.y + v1.z + v1.w;
    float s2 = v0.x*v0.x + v0.y*v0.y + v0.z*v0.z + v0.w*v0.w
             + v1.x*v1.x + v1.y*v1.y + v1.z*v1.z + v1.w*v1.w;
    #pragma unroll
    for (int o = 16; o > 0; o >>= 1) {
        s  += __shfl_xor_sync(0xffffffffu, s,  o);
        s2 += __shfl_xor_sync(0xffffffffu, s2, o);
    }
    float mean = s * (1.0f / CC);
    float inv = rsqrtf(s2 * (1.0f / CC) - mean * mean + EPS_F);
    float4 g0 = *(const float4*)(gamma + lane * 4), g1 = *(const float4*)(gamma + 128 + lane * 4);
    float4 b0 = *(const float4*)(beta  + lane * 4), b1 = *(const float4*)(beta  + 128 + lane * 4);
    float4 o0, o1;
    o0.x = (v0.x - mean) * inv * g0.x + b0.x; o0.y = (v0.y - mean) * inv * g0.y + b0.y;
    o0.z = (v0.z - mean) * inv * g0.z + b0.z; o0.w = (v0.w - mean) * inv * g0.w + b0.w;
    o1.x = (v1.x - mean) * inv * g1.x + b1.x; o1.y = (v1.y - mean) * inv * g1.y + b1.y;
    o1.z = (v1.z - mean) * inv * g1.z + b1.z; o1.w = (v1.w - mean) * inv * g1.w + b1.w;
    float4* po = (float4*)(out + drow * CC);
    po[lane] = o0; po[lane + 32] = o1;
}

// ======== fused: x2 = x + unwindow(proj); ln_out = LN(x2) (warp per row) ========
__global__ void fuse_res_ln(const float* __restrict__ x,
                            const float* __restrict__ proj,
                            const float* __restrict__ gamma,
                            const float* __restrict__ beta,
                            float* __restrict__ x2,
                            float* __restrict__ ln_out)
{
    int w = threadIdx.x >> 5, lane = threadIdx.x & 31;
    long t = (long)blockIdx.x * 8 + w;
    int batch = (int)(t >> 14);
    int pos = (int)(t & 16383);
    int y = pos >> 7, xx = pos & 127;
    int ys = (y - SSHIFT) & 127;
    int xs = (xx - SSHIFT) & 127;
    long wrow = ((long)batch * 256 + (ys >> 3) * 16 + (xs >> 3)) * 64 + (ys & 7) * 8 + (xs & 7);

    const float4* px = (const float4*)(x + t * CC);
    const float4* pp = (const float4*)(proj + wrow * CC);
    float4 v0 = px[lane], v1 = px[lane + 32];
    float4 p0 = pp[lane], p1 = pp[lane + 32];
    v0.x += p0.x; v0.y += p0.y; v0.z += p0.z; v0.w += p0.w;
    v1.x += p1.x; v1.y += p1.y; v1.z += p1.z; v1.w += p1.w;
    float4* px2 = (float4*)(x2 + t * CC);
    px2[lane] = v0; px2[lane + 32] = v1;

    float s  = v0.x + v0.y + v0.z + v0.w + v1.x + v1.y + v1.z + v1.w;
    float s2 = v0.x*v0.x + v0.y*v0.y + v0.z*v0.z + v0.w*v0.w
             + v1.x*v1.x + v1.y*v1.y + v1.z*v1.z + v1.w*v1.w;
    #pragma unroll
    for (int o = 16; o > 0; o >>= 1) {
        s  += __shfl_xor_sync(0xffffffffu, s,  o);
        s2 += __shfl_xor_sync(0xffffffffu, s2, o);
    }
    float mean = s * (1.0f / CC);
    float inv = rsqrtf(s2 * (1.0f / CC) - mean * mean + EPS_F);
    float4 g0 = *(const float4*)(gamma + lane * 4), g1 = *(const float4*)(gamma + 128 + lane * 4);
    float4 b0 = *(const float4*)(beta  + lane * 4), b1 = *(const float4*)(beta  + 128 + lane * 4);
    float4 o0, o1;
    o0.x = (v0.x - mean) * inv * g0.x + b0.x; o0.y = (v0.y - mean) * inv * g0.y + b0.y;
    o0.z = (v0.z - mean) * inv * g0.z + b0.z; o0.w = (v0.w - mean) * inv * g0.w + b0.w;
    o1.x = (v1.x - mean) * inv * g1.x + b1.x; o1.y = (v1.y - mean) * inv * g1.y + b1.y;
    o1.z = (v1.z - mean) * inv * g1.z + b1.z; o1.w = (v1.w - mean) * inv * g1.w + b1.w;
    float4* po = (float4*)(ln_out + t * CC);
    po[lane] = o0; po[lane + 32] = o1;
}

// ---------------- launch ----------------
extern "C" void kernel_launch(void* const* d_in, const int* in_sizes, int n_in,
                              void* d_out, int out_size)
{
    const float* x       = (const float*)d_in[0];
    const float* norm1_g = (const float*)d_in[1];
    const float* norm1_b = (const float*)d_in[2];
    const float* qkv_w   = (const float*)d_in[3];
    const float* qkv_b   = (const float*)d_in[4];
    const float* rel_b   = (const float*)d_in[5];
    const float* proj_w  = (const float*)d_in[6];
    const float* proj_b  = (const float*)d_in[7];
    const float* norm2_g = (const float*)d_in[8];
    const float* norm2_b = (const float*)d_in[9];
    const float* fc1_w   = (const float*)d_in[10];
    const float* fc1_b   = (const float*)d_in[11];
    const float* fc2_w   = (const float*)d_in[12];
    const float* fc2_b   = (const float*)d_in[13];
    float* out = (float*)d_out;

    float *p_hw, *p_qkv, *p_o, *p_proj, *p_x2;
    cudaGetSymbolAddress((void**)&p_hw,   g_hw);
    cudaGetSymbolAddress((void**)&p_qkv,  g_qkv);
    cudaGetSymbolAddress((void**)&p_o,    g_o);
    cudaGetSymbolAddress((void**)&p_proj, g_proj);
    cudaGetSymbolAddress((void**)&p_x2,   g_x2);

    const int SMEM = 2 * BUF_W * 4;  // 71680 bytes
    cudaFuncSetAttribute(gemm_cp<false, false>, cudaFuncAttributeMaxDynamicSharedMemorySize, SMEM);
    cudaFuncSetAttribute(gemm_cp<true,  false>, cudaFuncAttributeMaxDynamicSharedMemorySize, SMEM);
    cudaFuncSetAttribute(gemm_cp<false, true >, cudaFuncAttributeMaxDynamicSharedMemorySize, SMEM);

    // 1) LN1 + shifted-window gather
    ln8<true><<<TTOT / 8, 256>>>(x, norm1_g, norm1_b, p_hw);

    // 2) QKV GEMM [131072,256]x[256,768]
    gemm_cp<false, false><<<dim3(6, TTOT / 128), 256, SMEM>>>(
        p_hw, qkv_w, qkv_b, nullptr, p_qkv, TTOT, 768, CC);

    // 3) tensor-core windowed attention
    attn_mma<<<NWIN * NHEAD, 128>>>(p_qkv, rel_b, p_o);

    // 4) proj GEMM
    gemm_cp<false, false><<<dim3(2, TTOT / 128), 256, SMEM>>>(
        p_o, proj_w, proj_b, nullptr, p_proj, TTOT, CC, CC);

    // 5) fused unwindow + residual + LN2
    fuse_res_ln<<<TTOT / 8, 256>>>(x, p_proj, norm2_g, norm2_b, p_x2, p_hw);

    // 6) fc1 + GELU
    gemm_cp<true, false><<<dim3(2, TTOT / 128), 256, SMEM>>>(
        p_hw, fc1_w, fc1_b, nullptr, p_o, TTOT, CC, CC);

    // 7) fc2 + residual -> out
    gemm_cp<false, true><<<dim3(2, TTOT / 128), 256, SMEM>>>(
        p_o, fc2_w, fc2_b, p_x2, out, TTOT, CC, CC);
}

// round 5
// speedup vs baseline: 5.7722x; 1.6138x over previous
#include <cuda_runtime.h>
#include <cuda_bf16.h>
#include <math.h>
#include <stdint.h>

// ---------------- problem constants ----------------
#define CC      256
#define NHEAD   8
#define HDIM    32
#define SSHIFT  4
#define NWIN    2048
#define TTOT    131072
#define SCALE_F 0.1767766952966369f
#define EPS_F   1e-5f

typedef __nv_bfloat16 bf16;
typedef __nv_bfloat162 bf162;

// ---------------- scratch ----------------
__device__ __align__(16) bf16  g_hw[TTOT * CC];          // LN outputs (bf16 GEMM A)
__device__ __align__(16) bf16  g_qkv[TTOT * 3 * CC];     // qkv bf16
__device__ __align__(16) bf16  g_ob[TTOT * CC];          // attn out / fc1 out (bf16)
__device__ __align__(16) float g_proj[TTOT * CC];        // proj out fp32
__device__ __align__(16) float g_x2[TTOT * CC];          // residual fp32
__device__ __align__(16) bf16  g_wt[768 * 256 + 3 * 256 * 256]; // transposed bf16 weights

#define WT_QKV  0
#define WT_PROJ (768 * 256)
#define WT_FC1  (WT_PROJ + 256 * 256)
#define WT_FC2  (WT_FC1 + 256 * 256)

// ---------------- helpers ----------------
__device__ __forceinline__ uint32_t smem_u32(const void* p) {
    uint32_t a;
    asm("{ .reg .u64 t; cvta.to.shared.u64 t, %1; cvt.u32.u64 %0, t; }" : "=r"(a) : "l"(p));
    return a;
}
__device__ __forceinline__ void mma_bf16(float c[4],
                                         uint32_t a0, uint32_t a1, uint32_t a2, uint32_t a3,
                                         uint32_t b0, uint32_t b1) {
    asm volatile(
        "mma.sync.aligned.m16n8k16.row.col.f32.bf16.bf16.f32 "
        "{%0,%1,%2,%3}, {%4,%5,%6,%7}, {%8,%9}, {%0,%1,%2,%3};"
        : "+f"(c[0]), "+f"(c[1]), "+f"(c[2]), "+f"(c[3])
        : "r"(a0), "r"(a1), "r"(a2), "r"(a3), "r"(b0), "r"(b1));
}
__device__ __forceinline__ uint32_t pack_bf16(float x, float y) {
    bf162 v = __floats2bfloat162_rn(x, y);
    return *(uint32_t*)&v;
}
#define CP16(dst, src) \
    asm volatile("cp.async.cg.shared.global [%0], [%1], 16;" :: "r"(dst), "l"(src) : "memory")
#define CP_COMMIT() asm volatile("cp.async.commit_group;" ::: "memory")
#define CP_WAIT1()  asm volatile("cp.async.wait_group 1;" ::: "memory")

// ================ bf16 mma GEMM: C[M,N] = A[M,K] @ Wt[N,K]^T + bias ================
// CTA 128x128, BK=32, 3-stage cp.async, 8 warps (4m x 2n), warp tile 32x64.
#define BKT 32
#define ROW_WORDS 20            // 40 bf16 per row (32 + 8 pad) = 80 B = 20 words
#define STAGE_WORDS (256 * ROW_WORDS)   // A(128 rows) + B(128 rows)
#define STAGE_BYTES (STAGE_WORDS * 4)
#define GSMEM (3 * STAGE_BYTES)         // 61440 bytes

template <bool GELU, bool RESID, bool OUTBF>
__global__ __launch_bounds__(256, 2)
void gemm_bf(const bf16* __restrict__ A, const bf16* __restrict__ Bt,
             const float* __restrict__ bias, const float* __restrict__ R,
             float* __restrict__ C, bf16* __restrict__ Cb, int M, int N, int K)
{
    extern __shared__ float sm[];
    uint32_t sm0 = smem_u32(sm);

    int tid  = threadIdx.x;
    int bn   = blockIdx.x * 128;
    int bm   = blockIdx.y * 128;
    int warp = tid >> 5, lane = tid & 31;
    int wm   = (warp & 3) * 32;
    int wn   = (warp >> 2) * 64;
    int g    = lane >> 2;
    int t    = lane & 3;

    const int lrow = tid >> 2, lch = (tid & 3) * 8;   // 64 rows per pass, 2 passes per matrix

    float c[2][8][4];
    #pragma unroll
    for (int mi = 0; mi < 2; mi++)
        #pragma unroll
        for (int ni = 0; ni < 8; ni++)
            #pragma unroll
            for (int r = 0; r < 4; r++) c[mi][ni][r] = 0.f;

    auto load_stage = [&](int buf, int k0) {
        uint32_t As = sm0 + buf * STAGE_BYTES;
        uint32_t Bs = As + 128 * 80;
        #pragma unroll
        for (int i = 0; i < 2; i++) {
            int row = lrow + i * 64;
            CP16(As + row * 80 + lch * 2, A  + (size_t)(bm + row) * K + k0 + lch);
            CP16(Bs + row * 80 + lch * 2, Bt + (size_t)(bn + row) * K + k0 + lch);
        }
    };

    auto compute_stage = [&](int buf) {
        const uint32_t* As = (const uint32_t*)sm + buf * STAGE_WORDS;
        const uint32_t* Bs = As + 128 * ROW_WORDS;
        #pragma unroll
        for (int kt = 0; kt < 2; kt++) {
            int kw = kt * 8;
            uint32_t a[2][4];
            #pragma unroll
            for (int mi = 0; mi < 2; mi++) {
                const uint32_t* ar = As + (wm + mi * 16) * ROW_WORDS + kw + t;
                a[mi][0] = ar[g * ROW_WORDS];
                a[mi][1] = ar[(g + 8) * ROW_WORDS];
                a[mi][2] = ar[g * ROW_WORDS + 4];
                a[mi][3] = ar[(g + 8) * ROW_WORDS + 4];
            }
            #pragma unroll
            for (int ni = 0; ni < 8; ni++) {
                const uint32_t* br = Bs + (wn + ni * 8 + g) * ROW_WORDS + kw + t;
                uint32_t b0 = br[0];
                uint32_t b1 = br[4];
                mma_bf16(c[0][ni], a[0][0], a[0][1], a[0][2], a[0][3], b0, b1);
                mma_bf16(c[1][ni], a[1][0], a[1][1], a[1][2], a[1][3], b0, b1);
            }
        }
    };

    const int niter = K / BKT;   // 8
    load_stage(0, 0); CP_COMMIT();
    load_stage(1, BKT); CP_COMMIT();
    CP_WAIT1();
    __syncthreads();
    for (int it = 0; it < niter; ++it) {
        if (it + 2 < niter) load_stage((it + 2) % 3, (it + 2) * BKT);
        CP_COMMIT();
        compute_stage(it % 3);
        CP_WAIT1();
        __syncthreads();
    }

    // ---- epilogue ----
    #pragma unroll
    for (int mi = 0; mi < 2; mi++) {
        int row0 = bm + wm + mi * 16 + g;
        #pragma unroll
        for (int ni = 0; ni < 8; ni++) {
            int col = bn + wn + ni * 8 + 2 * t;
            float b0 = bias[col], b1 = bias[col + 1];
            float v0 = c[mi][ni][0] + b0;
            float v1 = c[mi][ni][1] + b1;
            float v2 = c[mi][ni][2] + b0;
            float v3 = c[mi][ni][3] + b1;
            if (GELU) {
                v0 = 0.5f * v0 * (1.0f + erff(v0 * 0.70710678118654752f));
                v1 = 0.5f * v1 * (1.0f + erff(v1 * 0.70710678118654752f));
                v2 = 0.5f * v2 * (1.0f + erff(v2 * 0.70710678118654752f));
                v3 = 0.5f * v3 * (1.0f + erff(v3 * 0.70710678118654752f));
            }
            if (OUTBF) {
                *(uint32_t*)(Cb + (size_t)row0 * N + col)       = pack_bf16(v0, v1);
                *(uint32_t*)(Cb + (size_t)(row0 + 8) * N + col) = pack_bf16(v2, v3);
            } else {
                if (RESID) {
                    float2 r0 = *(const float2*)(R + (size_t)row0 * N + col);
                    float2 r1 = *(const float2*)(R + (size_t)(row0 + 8) * N + col);
                    v0 += r0.x; v1 += r0.y; v2 += r1.x; v3 += r1.y;
                }
                *(float2*)(C + (size_t)row0 * N + col)       = make_float2(v0, v1);
                *(float2*)(C + (size_t)(row0 + 8) * N + col) = make_float2(v2, v3);
            }
        }
    }
}

// ================ weight convert + transpose: W[K][N] f32 -> Wt[N][K] bf16 ========
__global__ void cvt_w(const float* __restrict__ W, bf16* __restrict__ Wt, int K, int N)
{
    __shared__ float tsm[32][33];
    int k0 = blockIdx.y * 32, n0 = blockIdx.x * 32;
    int tx = threadIdx.x, ty = threadIdx.y;
    tsm[ty][tx] = W[(size_t)(k0 + ty) * N + n0 + tx];
    __syncthreads();
    Wt[(size_t)(n0 + ty) * K + k0 + tx] = __float2bfloat16_rn(tsm[tx][ty]);
}

// ================ bf16 tensor-core windowed attention ================
__global__ __launch_bounds__(128)
void attn_mma(const bf16* __restrict__ qkv,
              const float* __restrict__ rel_bias,
              bf16* __restrict__ out)
{
    __shared__ bf16 qs[64][40];    // [m][d], 20 words/row
    __shared__ bf16 ks[64][40];
    __shared__ bf16 vst[32][72];   // [d][m], 36 words/row
    __shared__ bf16 ps[64][72];    // [r][m], 36 words/row
    __shared__ float bt[225];

    int bx = blockIdx.x;
    int h = bx & 7;
    long wg = bx >> 3;
    int tid = threadIdx.x;
    int warp = tid >> 5, lane = tid & 31;
    int g = lane >> 2, t = lane & 3;

    #pragma unroll
    for (int i = 0; i < 2; i++) {
        int fid = tid + i * 128;
        int m = fid >> 2, ch = (fid & 3) * 8;
        size_t base = ((size_t)wg * 64 + m) * (3 * CC) + h * HDIM + ch;
        *(uint4*)&qs[m][ch] = *(const uint4*)(qkv + base);
        *(uint4*)&ks[m][ch] = *(const uint4*)(qkv + base + CC);
        uint4 vv = *(const uint4*)(qkv + base + 2 * CC);
        bf16* ve = (bf16*)&vv;
        #pragma unroll
        for (int j = 0; j < 8; j++) vst[ch + j][m] = ve[j];
    }
    for (int i = tid; i < 225; i += 128) bt[i] = rel_bias[i * NHEAD + h];
    __syncthreads();

    int wm = warp * 16;
    const uint32_t* qsW = (const uint32_t*)qs;
    const uint32_t* ksW = (const uint32_t*)ks;
    const uint32_t* vstW = (const uint32_t*)vst;
    uint32_t* psW = (uint32_t*)ps;

    // ---- S = Q @ K^T (bf16), scale+bias in fp32 ----
    float s[8][4];
    #pragma unroll
    for (int ni = 0; ni < 8; ni++)
        #pragma unroll
        for (int r = 0; r < 4; r++) s[ni][r] = 0.f;

    #pragma unroll
    for (int kt = 0; kt < 2; kt++) {
        int kw = kt * 8;
        uint32_t a0 = qsW[(wm + g) * 20 + kw + t];
        uint32_t a1 = qsW[(wm + g + 8) * 20 + kw + t];
        uint32_t a2 = qsW[(wm + g) * 20 + kw + t + 4];
        uint32_t a3 = qsW[(wm + g + 8) * 20 + kw + t + 4];
        #pragma unroll
        for (int ni = 0; ni < 8; ni++) {
            uint32_t b0 = ksW[(ni * 8 + g) * 20 + kw + t];
            uint32_t b1 = ksW[(ni * 8 + g) * 20 + kw + t + 4];
            mma_bf16(s[ni], a0, a1, a2, a3, b0, b1);
        }
    }

    int r0 = wm + g, r1 = wm + g + 8;
    int rh0 = r0 >> 3, rw0 = r0 & 7;
    int rh1 = r1 >> 3, rw1 = r1 & 7;
    float mx0 = -1e30f, mx1 = -1e30f;
    #pragma unroll
    for (int ni = 0; ni < 8; ni++) {
        #pragma unroll
        for (int cc2 = 0; cc2 < 2; cc2++) {
            int col = ni * 8 + 2 * t + cc2;
            int mh = col >> 3, mw = col & 7;
            s[ni][cc2]     = s[ni][cc2]     * SCALE_F + bt[(rh0 - mh + 7) * 15 + (rw0 - mw + 7)];
            s[ni][2 + cc2] = s[ni][2 + cc2] * SCALE_F + bt[(rh1 - mh + 7) * 15 + (rw1 - mw + 7)];
            mx0 = fmaxf(mx0, s[ni][cc2]);
            mx1 = fmaxf(mx1, s[ni][2 + cc2]);
        }
    }
    mx0 = fmaxf(mx0, __shfl_xor_sync(0xffffffffu, mx0, 1));
    mx0 = fmaxf(mx0, __shfl_xor_sync(0xffffffffu, mx0, 2));
    mx1 = fmaxf(mx1, __shfl_xor_sync(0xffffffffu, mx1, 1));
    mx1 = fmaxf(mx1, __shfl_xor_sync(0xffffffffu, mx1, 2));
    float sum0 = 0.f, sum1 = 0.f;
    #pragma unroll
    for (int ni = 0; ni < 8; ni++) {
        s[ni][0] = __expf(s[ni][0] - mx0); sum0 += s[ni][0];
        s[ni][1] = __expf(s[ni][1] - mx0); sum0 += s[ni][1];
        s[ni][2] = __expf(s[ni][2] - mx1); sum1 += s[ni][2];
        s[ni][3] = __expf(s[ni][3] - mx1); sum1 += s[ni][3];
    }
    sum0 += __shfl_xor_sync(0xffffffffu, sum0, 1);
    sum0 += __shfl_xor_sync(0xffffffffu, sum0, 2);
    sum1 += __shfl_xor_sync(0xffffffffu, sum1, 1);
    sum1 += __shfl_xor_sync(0xffffffffu, sum1, 2);
    float inv0 = 1.0f / sum0, inv1 = 1.0f / sum1;
    #pragma unroll
    for (int ni = 0; ni < 8; ni++) {
        psW[r0 * 36 + ni * 4 + t] = pack_bf16(s[ni][0] * inv0, s[ni][1] * inv0);
        psW[r1 * 36 + ni * 4 + t] = pack_bf16(s[ni][2] * inv1, s[ni][3] * inv1);
    }
    __syncwarp();

    // ---- O = P @ V ----
    float o[4][4];
    #pragma unroll
    for (int ni = 0; ni < 4; ni++)
        #pragma unroll
        for (int r = 0; r < 4; r++) o[ni][r] = 0.f;
    #pragma unroll
    for (int kt = 0; kt < 4; kt++) {
        int kw = kt * 8;
        uint32_t a0 = psW[(wm + g) * 36 + kw + t];
        uint32_t a1 = psW[(wm + g + 8) * 36 + kw + t];
        uint32_t a2 = psW[(wm + g) * 36 + kw + t + 4];
        uint32_t a3 = psW[(wm + g + 8) * 36 + kw + t + 4];
        #pragma unroll
        for (int ni = 0; ni < 4; ni++) {
            uint32_t b0 = vstW[(ni * 8 + g) * 36 + kw + t];
            uint32_t b1 = vstW[(ni * 8 + g) * 36 + kw + t + 4];
            mma_bf16(o[ni], a0, a1, a2, a3, b0, b1);
        }
    }
    size_t ob0 = ((size_t)wg * 64 + r0) * CC + h * HDIM;
    size_t ob1 = ((size_t)wg * 64 + r1) * CC + h * HDIM;
    #pragma unroll
    for (int ni = 0; ni < 4; ni++) {
        int col = ni * 8 + 2 * t;
        *(uint32_t*)(out + ob0 + col) = pack_bf16(o[ni][0], o[ni][1]);
        *(uint32_t*)(out + ob1 + col) = pack_bf16(o[ni][2], o[ni][3]);
    }
}

// ================ LN (warp/row) -> bf16, optional shifted-window gather ================
template <bool GATHER>
__global__ void ln8(const float* __restrict__ x,
                    const float* __restrict__ gamma,
                    const float* __restrict__ beta,
                    bf16* __restrict__ out)
{
    int w = threadIdx.x >> 5, lane = threadIdx.x & 31;
    long drow = (long)blockIdx.x * 8 + w;
    long srow;
    if (GATHER) {
        int token = (int)(drow & 63);
        int wg = (int)(drow >> 6);
        int batch = wg >> 8, win = wg & 255;
        int ys = ((win >> 4) << 3) + (token >> 3);
        int xs = ((win & 15) << 3) + (token & 7);
        int y  = (ys + SSHIFT) & 127;
        int xx = (xs + SSHIFT) & 127;
        srow = (long)batch * 16384 + y * 128 + xx;
    } else srow = drow;

    const float4* px = (const float4*)(x + srow * CC);
    float4 v0 = px[lane], v1 = px[lane + 32];
    float s  = v0.x + v0.y + v0.z + v0.w + v1.x + v1.y + v1.z + v1.w;
    float s2 = v0.x*v0.x + v0.y*v0.y + v0.z*v0.z + v0.w*v0.w
             + v1.x*v1.x + v1.y*v1.y + v1.z*v1.z + v1.w*v1.w;
    #pragma unroll
    for (int o = 16; o > 0; o >>= 1) {
        s  += __shfl_xor_sync(0xffffffffu, s,  o);
        s2 += __shfl_xor_sync(0xffffffffu, s2, o);
    }
    float mean = s * (1.0f / CC);
    float inv = rsqrtf(s2 * (1.0f / CC) - mean * mean + EPS_F);
    float4 g0 = *(const float4*)(gamma + lane * 4), g1 = *(const float4*)(gamma + 128 + lane * 4);
    float4 b0 = *(const float4*)(beta  + lane * 4), b1 = *(const float4*)(beta  + 128 + lane * 4);
    uint2 o0, o1;
    o0.x = pack_bf16((v0.x - mean) * inv * g0.x + b0.x, (v0.y - mean) * inv * g0.y + b0.y);
    o0.y = pack_bf16((v0.z - mean) * inv * g0.z + b0.z, (v0.w - mean) * inv * g0.w + b0.w);
    o1.x = pack_bf16((v1.x - mean) * inv * g1.x + b1.x, (v1.y - mean) * inv * g1.y + b1.y);
    o1.y = pack_bf16((v1.z - mean) * inv * g1.z + b1.z, (v1.w - mean) * inv * g1.w + b1.w);
    *(uint2*)(out + drow * CC + lane * 4)       = o0;
    *(uint2*)(out + drow * CC + 128 + lane * 4) = o1;
}

// ======== fused: x2 = x + unwindow(proj); ln_out = LN(x2) bf16 ========
__global__ void fuse_res_ln(const float* __restrict__ x,
                            const float* __restrict__ proj,
                            const float* __restrict__ gamma,
                            const float* __restrict__ beta,
                            float* __restrict__ x2,
                            bf16* __restrict__ ln_out)
{
    int w = threadIdx.x >> 5, lane = threadIdx.x & 31;
    long t = (long)blockIdx.x * 8 + w;
    int batch = (int)(t >> 14);
    int pos = (int)(t & 16383);
    int y = pos >> 7, xx = pos & 127;
    int ys = (y - SSHIFT) & 127;
    int xs = (xx - SSHIFT) & 127;
    long wrow = ((long)batch * 256 + (ys >> 3) * 16 + (xs >> 3)) * 64 + (ys & 7) * 8 + (xs & 7);

    const float4* px = (const float4*)(x + t * CC);
    const float4* pp = (const float4*)(proj + wrow * CC);
    float4 v0 = px[lane], v1 = px[lane + 32];
    float4 p0 = pp[lane], p1 = pp[lane + 32];
    v0.x += p0.x; v0.y += p0.y; v0.z += p0.z; v0.w += p0.w;
    v1.x += p1.x; v1.y += p1.y; v1.z += p1.z; v1.w += p1.w;
    float4* px2 = (float4*)(x2 + t * CC);
    px2[lane] = v0; px2[lane + 32] = v1;

    float s  = v0.x + v0.y + v0.z + v0.w + v1.x + v1.y + v1.z + v1.w;
    float s2 = v0.x*v0.x + v0.y*v0.y + v0.z*v0.z + v0.w*v0.w
             + v1.x*v1.x + v1.y*v1.y + v1.z*v1.z + v1.w*v1.w;
    #pragma unroll
    for (int o = 16; o > 0; o >>= 1) {
        s  += __shfl_xor_sync(0xffffffffu, s,  o);
        s2 += __shfl_xor_sync(0xffffffffu, s2, o);
    }
    float mean = s * (1.0f / CC);
    float inv = rsqrtf(s2 * (1.0f / CC) - mean * mean + EPS_F);
    float4 g0 = *(const float4*)(gamma + lane * 4), g1 = *(const float4*)(gamma + 128 + lane * 4);
    float4 b0 = *(const float4*)(beta  + lane * 4), b1 = *(const float4*)(beta  + 128 + lane * 4);
    uint2 o0, o1;
    o0.x = pack_bf16((v0.x - mean) * inv * g0.x + b0.x, (v0.y - mean) * inv * g0.y + b0.y);
    o0.y = pack_bf16((v0.z - mean) * inv * g0.z + b0.z, (v0.w - mean) * inv * g0.w + b0.w);
    o1.x = pack_bf16((v1.x - mean) * inv * g1.x + b1.x, (v1.y - mean) * inv * g1.y + b1.y);
    o1.y = pack_bf16((v1.z - mean) * inv * g1.z + b1.z, (v1.w - mean) * inv * g1.w + b1.w);
    *(uint2*)(ln_out + t * CC + lane * 4)       = o0;
    *(uint2*)(ln_out + t * CC + 128 + lane * 4) = o1;
}

// ---------------- launch ----------------
extern "C" void kernel_launch(void* const* d_in, const int* in_sizes, int n_in,
                              void* d_out, int out_size)
{
    const float* x       = (const float*)d_in[0];
    const float* norm1_g = (const float*)d_in[1];
    const float* norm1_b = (const float*)d_in[2];
    const float* qkv_w   = (const float*)d_in[3];
    const float* qkv_b   = (const float*)d_in[4];
    const float* rel_b   = (const float*)d_in[5];
    const float* proj_w  = (const float*)d_in[6];
    const float* proj_b  = (const float*)d_in[7];
    const float* norm2_g = (const float*)d_in[8];
    const float* norm2_b = (const float*)d_in[9];
    const float* fc1_w   = (const float*)d_in[10];
    const float* fc1_b   = (const float*)d_in[11];
    const float* fc2_w   = (const float*)d_in[12];
    const float* fc2_b   = (const float*)d_in[13];
    float* out = (float*)d_out;

    bf16 *p_hw, *p_qkv, *p_ob, *p_wt;
    float *p_proj, *p_x2;
    cudaGetSymbolAddress((void**)&p_hw,   g_hw);
    cudaGetSymbolAddress((void**)&p_qkv,  g_qkv);
    cudaGetSymbolAddress((void**)&p_ob,   g_ob);
    cudaGetSymbolAddress((void**)&p_proj, g_proj);
    cudaGetSymbolAddress((void**)&p_x2,   g_x2);
    cudaGetSymbolAddress((void**)&p_wt,   g_wt);

    cudaFuncSetAttribute(gemm_bf<false, false, true >, cudaFuncAttributeMaxDynamicSharedMemorySize, GSMEM);
    cudaFuncSetAttribute(gemm_bf<false, false, false>, cudaFuncAttributeMaxDynamicSharedMemorySize, GSMEM);
    cudaFuncSetAttribute(gemm_bf<true,  false, true >, cudaFuncAttributeMaxDynamicSharedMemorySize, GSMEM);
    cudaFuncSetAttribute(gemm_bf<false, true,  false>, cudaFuncAttributeMaxDynamicSharedMemorySize, GSMEM);

    // 0) convert + transpose weights to bf16
    dim3 cb(32, 32);
    cvt_w<<<dim3(768 / 32, 256 / 32), cb>>>(qkv_w,  p_wt + WT_QKV, 256, 768);
    cvt_w<<<dim3(256 / 32, 256 / 32), cb>>>(proj_w, p_wt + WT_PROJ, 256, 256);
    cvt_w<<<dim3(256 / 32, 256 / 32), cb>>>(fc1_w,  p_wt + WT_FC1, 256, 256);
    cvt_w<<<dim3(256 / 32, 256 / 32), cb>>>(fc2_w,  p_wt + WT_FC2, 256, 256);

    // 1) LN1 + shifted-window gather -> bf16
    ln8<true><<<TTOT / 8, 256>>>(x, norm1_g, norm1_b, p_hw);

    // 2) QKV GEMM -> bf16
    gemm_bf<false, false, true><<<dim3(6, TTOT / 128), 256, GSMEM>>>(
        p_hw, p_wt + WT_QKV, qkv_b, nullptr, nullptr, p_qkv, TTOT, 768, CC);

    // 3) bf16 tensor-core windowed attention -> bf16
    attn_mma<<<NWIN * NHEAD, 128>>>(p_qkv, rel_b, p_ob);

    // 4) proj GEMM -> fp32
    gemm_bf<false, false, false><<<dim3(2, TTOT / 128), 256, GSMEM>>>(
        p_ob, p_wt + WT_PROJ, proj_b, nullptr, p_proj, nullptr, TTOT, CC, CC);

    // 5) fused unwindow + residual + LN2 -> x2 fp32, ln bf16
    fuse_res_ln<<<TTOT / 8, 256>>>(x, p_proj, norm2_g, norm2_b, p_x2, p_hw);

    // 6) fc1 + GELU -> bf16
    gemm_bf<true, false, true><<<dim3(2, TTOT / 128), 256, GSMEM>>>(
        p_hw, p_wt + WT_FC1, fc1_b, nullptr, nullptr, p_ob, TTOT, CC, CC);

    // 7) fc2 + residual -> fp32 out
    gemm_bf<false, true, false><<<dim3(2, TTOT / 128), 256, GSMEM>>>(
        p_ob, p_wt + WT_FC2, fc2_b, p_x2, out, nullptr, TTOT, CC, CC);
}

// round 6
// speedup vs baseline: 5.9222x; 1.0260x over previous
#include <cuda_runtime.h>
#include <cuda_bf16.h>
#include <math.h>
#include <stdint.h>

// ---------------- problem constants ----------------
#define CC      256
#define NHEAD   8
#define HDIM    32
#define SSHIFT  4
#define NWIN    2048
#define TTOT    131072
#define SCALE_F 0.1767766952966369f
#define EPS_F   1e-5f

typedef __nv_bfloat16 bf16;
typedef __nv_bfloat162 bf162;

// ---------------- scratch ----------------
__device__ __align__(16) bf16  g_hw[TTOT * CC];          // LN outputs (bf16 GEMM A)
__device__ __align__(16) bf16  g_qkv[TTOT * 3 * CC];     // qkv bf16
__device__ __align__(16) bf16  g_ob[TTOT * CC];          // attn out / fc1 out (bf16)
__device__ __align__(16) float g_x2[TTOT * CC];          // residual fp32
__device__ __align__(16) bf16  g_wt[768 * 256 + 3 * 256 * 256]; // transposed bf16 weights

#define WT_QKV  0
#define WT_PROJ (768 * 256)
#define WT_FC1  (WT_PROJ + 256 * 256)
#define WT_FC2  (WT_FC1 + 256 * 256)

// ---------------- helpers ----------------
__device__ __forceinline__ uint32_t smem_u32(const void* p) {
    uint32_t a;
    asm("{ .reg .u64 t; cvta.to.shared.u64 t, %1; cvt.u32.u64 %0, t; }" : "=r"(a) : "l"(p));
    return a;
}
__device__ __forceinline__ void mma_bf16(float c[4],
                                         uint32_t a0, uint32_t a1, uint32_t a2, uint32_t a3,
                                         uint32_t b0, uint32_t b1) {
    asm volatile(
        "mma.sync.aligned.m16n8k16.row.col.f32.bf16.bf16.f32 "
        "{%0,%1,%2,%3}, {%4,%5,%6,%7}, {%8,%9}, {%0,%1,%2,%3};"
        : "+f"(c[0]), "+f"(c[1]), "+f"(c[2]), "+f"(c[3])
        : "r"(a0), "r"(a1), "r"(a2), "r"(a3), "r"(b0), "r"(b1));
}
__device__ __forceinline__ uint32_t pack_bf16(float x, float y) {
    bf162 v = __floats2bfloat162_rn(x, y);
    return *(uint32_t*)&v;
}
#define CP16(dst, src) \
    asm volatile("cp.async.cg.shared.global [%0], [%1], 16;" :: "r"(dst), "l"(src) : "memory")
#define CP_COMMIT() asm volatile("cp.async.commit_group;" ::: "memory")
#define CP_WAIT1()  asm volatile("cp.async.wait_group 1;" ::: "memory")

// windowed row -> original token row (reverse shift)
__device__ __forceinline__ long unwin_row(long wr) {
    int batch = (int)(wr >> 14);
    int win   = ((int)wr >> 6) & 255;
    int token = (int)wr & 63;
    int ys = ((win >> 4) << 3) + (token >> 3);
    int xs = ((win & 15) << 3) + (token & 7);
    int y  = (ys + SSHIFT) & 127;
    int xx = (xs + SSHIFT) & 127;
    return (long)batch * 16384 + y * 128 + xx;
}

#define ROW_WORDS 20            // 40 bf16 per row (32 + 8 pad) = 80 B = 20 words
#define BKT 32

// ================ bf16 mma GEMM 128x128: C = A @ Wt^T + bias ================
#define STAGE_WORDS (256 * ROW_WORDS)
#define STAGE_BYTES (STAGE_WORDS * 4)
#define GSMEM (3 * STAGE_BYTES)         // 61440 bytes

template <bool GELU, bool RESID, bool OUTBF>
__global__ __launch_bounds__(256, 2)
void gemm_bf(const bf16* __restrict__ A, const bf16* __restrict__ Bt,
             const float* __restrict__ bias, const float* __restrict__ R,
             float* __restrict__ C, bf16* __restrict__ Cb, int M, int N, int K)
{
    extern __shared__ float sm[];
    uint32_t sm0 = smem_u32(sm);

    int tid  = threadIdx.x;
    int bn   = blockIdx.x * 128;
    int bm   = blockIdx.y * 128;
    int warp = tid >> 5, lane = tid & 31;
    int wm   = (warp & 3) * 32;
    int wn   = (warp >> 2) * 64;
    int g    = lane >> 2;
    int t    = lane & 3;

    const int lrow = tid >> 2, lch = (tid & 3) * 8;

    float c[2][8][4];
    #pragma unroll
    for (int mi = 0; mi < 2; mi++)
        #pragma unroll
        for (int ni = 0; ni < 8; ni++)
            #pragma unroll
            for (int r = 0; r < 4; r++) c[mi][ni][r] = 0.f;

    auto load_stage = [&](int buf, int k0) {
        uint32_t As = sm0 + buf * STAGE_BYTES;
        uint32_t Bs = As + 128 * 80;
        #pragma unroll
        for (int i = 0; i < 2; i++) {
            int row = lrow + i * 64;
            CP16(As + row * 80 + lch * 2, A  + (size_t)(bm + row) * K + k0 + lch);
            CP16(Bs + row * 80 + lch * 2, Bt + (size_t)(bn + row) * K + k0 + lch);
        }
    };

    auto compute_stage = [&](int buf) {
        const uint32_t* As = (const uint32_t*)sm + buf * STAGE_WORDS;
        const uint32_t* Bs = As + 128 * ROW_WORDS;
        #pragma unroll
        for (int kt = 0; kt < 2; kt++) {
            int kw = kt * 8;
            uint32_t a[2][4];
            #pragma unroll
            for (int mi = 0; mi < 2; mi++) {
                const uint32_t* ar = As + (wm + mi * 16) * ROW_WORDS + kw + t;
                a[mi][0] = ar[g * ROW_WORDS];
                a[mi][1] = ar[(g + 8) * ROW_WORDS];
                a[mi][2] = ar[g * ROW_WORDS + 4];
                a[mi][3] = ar[(g + 8) * ROW_WORDS + 4];
            }
            #pragma unroll
            for (int ni = 0; ni < 8; ni++) {
                const uint32_t* br = Bs + (wn + ni * 8 + g) * ROW_WORDS + kw + t;
                uint32_t b0 = br[0];
                uint32_t b1 = br[4];
                mma_bf16(c[0][ni], a[0][0], a[0][1], a[0][2], a[0][3], b0, b1);
                mma_bf16(c[1][ni], a[1][0], a[1][1], a[1][2], a[1][3], b0, b1);
            }
        }
    };

    const int niter = K / BKT;
    load_stage(0, 0); CP_COMMIT();
    load_stage(1, BKT); CP_COMMIT();
    CP_WAIT1();
    __syncthreads();
    for (int it = 0; it < niter; ++it) {
        if (it + 2 < niter) load_stage((it + 2) % 3, (it + 2) * BKT);
        CP_COMMIT();
        compute_stage(it % 3);
        CP_WAIT1();
        __syncthreads();
    }

    #pragma unroll
    for (int mi = 0; mi < 2; mi++) {
        int row0 = bm + wm + mi * 16 + g;
        #pragma unroll
        for (int ni = 0; ni < 8; ni++) {
            int col = bn + wn + ni * 8 + 2 * t;
            float b0 = bias[col], b1 = bias[col + 1];
            float v0 = c[mi][ni][0] + b0;
            float v1 = c[mi][ni][1] + b1;
            float v2 = c[mi][ni][2] + b0;
            float v3 = c[mi][ni][3] + b1;
            if (GELU) {
                v0 = 0.5f * v0 * (1.0f + erff(v0 * 0.70710678118654752f));
                v1 = 0.5f * v1 * (1.0f + erff(v1 * 0.70710678118654752f));
                v2 = 0.5f * v2 * (1.0f + erff(v2 * 0.70710678118654752f));
                v3 = 0.5f * v3 * (1.0f + erff(v3 * 0.70710678118654752f));
            }
            if (OUTBF) {
                *(uint32_t*)(Cb + (size_t)row0 * N + col)       = pack_bf16(v0, v1);
                *(uint32_t*)(Cb + (size_t)(row0 + 8) * N + col) = pack_bf16(v2, v3);
            } else {
                if (RESID) {
                    float2 r0 = *(const float2*)(R + (size_t)row0 * N + col);
                    float2 r1 = *(const float2*)(R + (size_t)(row0 + 8) * N + col);
                    v0 += r0.x; v1 += r0.y; v2 += r1.x; v3 += r1.y;
                }
                *(float2*)(C + (size_t)row0 * N + col)       = make_float2(v0, v1);
                *(float2*)(C + (size_t)(row0 + 8) * N + col) = make_float2(v2, v3);
            }
        }
    }
}

// ================ fused proj GEMM (64x256 tile) + unwindow residual + LN2 ========
// A: attn out bf16 (windowed), Bt: proj Wt[N][K], outputs x2 fp32 + ln bf16 (orig order)
#define PSTAGE_WORDS (320 * ROW_WORDS)      // A 64 rows + B 256 rows
#define PSTAGE_BYTES (PSTAGE_WORDS * 4)     // 25600
#define PTS 260                             // epilogue tile stride (words)
#define PSMEM (3 * PSTAGE_BYTES)            // 76800 bytes

__global__ __launch_bounds__(256, 2)
void proj_fused(const bf16* __restrict__ A, const bf16* __restrict__ Bt,
                const float* __restrict__ bias,
                const float* __restrict__ x,
                const float* __restrict__ gamma, const float* __restrict__ beta,
                float* __restrict__ x2, bf16* __restrict__ ln_out)
{
    extern __shared__ float sm[];
    uint32_t sm0 = smem_u32(sm);

    const int K = 256, N = 256;
    int tid  = threadIdx.x;
    long bm  = (long)blockIdx.x * 64;
    int warp = tid >> 5, lane = tid & 31;
    int wm   = (warp & 1) * 32;
    int wn   = (warp >> 1) * 64;
    int g    = lane >> 2;
    int t    = lane & 3;

    float c[2][8][4];
    #pragma unroll
    for (int mi = 0; mi < 2; mi++)
        #pragma unroll
        for (int ni = 0; ni < 8; ni++)
            #pragma unroll
            for (int r = 0; r < 4; r++) c[mi][ni][r] = 0.f;

    const int lrow = tid >> 2, lch = (tid & 3) * 8;

    auto load_stage = [&](int buf, int k0) {
        uint32_t As = sm0 + buf * PSTAGE_BYTES;
        uint32_t Bs = As + 64 * 80;
        CP16(As + lrow * 80 + lch * 2, A + (size_t)(bm + lrow) * K + k0 + lch);
        #pragma unroll
        for (int i = 0; i < 4; i++) {
            int row = lrow + i * 64;
            CP16(Bs + row * 80 + lch * 2, Bt + (size_t)row * K + k0 + lch);
        }
    };

    auto compute_stage = [&](int buf) {
        const uint32_t* As = (const uint32_t*)sm + buf * PSTAGE_WORDS;
        const uint32_t* Bs = As + 64 * ROW_WORDS;
        #pragma unroll
        for (int kt = 0; kt < 2; kt++) {
            int kw = kt * 8;
            uint32_t a[2][4];
            #pragma unroll
            for (int mi = 0; mi < 2; mi++) {
                const uint32_t* ar = As + (wm + mi * 16) * ROW_WORDS + kw + t;
                a[mi][0] = ar[g * ROW_WORDS];
                a[mi][1] = ar[(g + 8) * ROW_WORDS];
                a[mi][2] = ar[g * ROW_WORDS + 4];
                a[mi][3] = ar[(g + 8) * ROW_WORDS + 4];
            }
            #pragma unroll
            for (int ni = 0; ni < 8; ni++) {
                const uint32_t* br = Bs + (wn + ni * 8 + g) * ROW_WORDS + kw + t;
                uint32_t b0 = br[0];
                uint32_t b1 = br[4];
                mma_bf16(c[0][ni], a[0][0], a[0][1], a[0][2], a[0][3], b0, b1);
                mma_bf16(c[1][ni], a[1][0], a[1][1], a[1][2], a[1][3], b0, b1);
            }
        }
    };

    const int niter = 8;
    load_stage(0, 0); CP_COMMIT();
    load_stage(1, BKT); CP_COMMIT();
    CP_WAIT1();
    __syncthreads();
    for (int it = 0; it < niter; ++it) {
        if (it + 2 < niter) load_stage((it + 2) % 3, (it + 2) * BKT);
        CP_COMMIT();
        compute_stage(it % 3);
        CP_WAIT1();
        __syncthreads();
    }

    // ---- epilogue phase 1: bias + residual gather, write x2, stage fp32 tile ----
    #pragma unroll
    for (int mi = 0; mi < 2; mi++) {
        int lr0 = wm + mi * 16 + g;
        int lr1 = lr0 + 8;
        long t0 = unwin_row(bm + lr0);
        long t1 = unwin_row(bm + lr1);
        #pragma unroll
        for (int ni = 0; ni < 8; ni++) {
            int col = wn + ni * 8 + 2 * t;
            float b0 = bias[col], b1 = bias[col + 1];
            float2 r0 = *(const float2*)(x + t0 * 256 + col);
            float2 r1 = *(const float2*)(x + t1 * 256 + col);
            float v0 = c[mi][ni][0] + b0 + r0.x;
            float v1 = c[mi][ni][1] + b1 + r0.y;
            float v2 = c[mi][ni][2] + b0 + r1.x;
            float v3 = c[mi][ni][3] + b1 + r1.y;
            *(float2*)(x2 + t0 * 256 + col) = make_float2(v0, v1);
            *(float2*)(x2 + t1 * 256 + col) = make_float2(v2, v3);
            *(float2*)(sm + lr0 * PTS + col) = make_float2(v0, v1);
            *(float2*)(sm + lr1 * PTS + col) = make_float2(v2, v3);
        }
    }
    __syncthreads();

    // ---- epilogue phase 2: LN over smem tile (warp per row, 8 rows per warp) ----
    #pragma unroll
    for (int i = 0; i < 8; i++) {
        int row = warp + i * 8;
        const float* pr = sm + row * PTS + lane * 8;
        float4 v0 = *(const float4*)pr;
        float4 v1 = *(const float4*)(pr + 4);
        float s  = v0.x + v0.y + v0.z + v0.w + v1.x + v1.y + v1.z + v1.w;
        float s2 = v0.x*v0.x + v0.y*v0.y + v0.z*v0.z + v0.w*v0.w
                 + v1.x*v1.x + v1.y*v1.y + v1.z*v1.z + v1.w*v1.w;
        #pragma unroll
        for (int o = 16; o > 0; o >>= 1) {
            s  += __shfl_xor_sync(0xffffffffu, s,  o);
            s2 += __shfl_xor_sync(0xffffffffu, s2, o);
        }
        float mean = s * (1.0f / 256.0f);
        float inv = rsqrtf(s2 * (1.0f / 256.0f) - mean * mean + EPS_F);
        float4 ga = *(const float4*)(gamma + lane * 8);
        float4 gb = *(const float4*)(gamma + lane * 8 + 4);
        float4 ba = *(const float4*)(beta + lane * 8);
        float4 bb = *(const float4*)(beta + lane * 8 + 4);
        uint4 o4;
        o4.x = pack_bf16((v0.x - mean) * inv * ga.x + ba.x, (v0.y - mean) * inv * ga.y + ba.y);
        o4.y = pack_bf16((v0.z - mean) * inv * ga.z + ba.z, (v0.w - mean) * inv * ga.w + ba.w);
        o4.z = pack_bf16((v1.x - mean) * inv * gb.x + bb.x, (v1.y - mean) * inv * gb.y + bb.y);
        o4.w = pack_bf16((v1.z - mean) * inv * gb.z + bb.z, (v1.w - mean) * inv * gb.w + bb.w);
        long to = unwin_row(bm + row);
        *(uint4*)(ln_out + to * 256 + lane * 8) = o4;
    }
}

// ================ weight convert + transpose: W[K][N] f32 -> Wt[N][K] bf16 ========
__global__ void cvt_w(const float* __restrict__ W, bf16* __restrict__ Wt, int K, int N)
{
    __shared__ float tsm[32][33];
    int k0 = blockIdx.y * 32, n0 = blockIdx.x * 32;
    int tx = threadIdx.x, ty = threadIdx.y;
    tsm[ty][tx] = W[(size_t)(k0 + ty) * N + n0 + tx];
    __syncthreads();
    Wt[(size_t)(n0 + ty) * K + k0 + tx] = __float2bfloat16_rn(tsm[tx][ty]);
}

// ================ bf16 tensor-core windowed attention ================
__global__ __launch_bounds__(128)
void attn_mma(const bf16* __restrict__ qkv,
              const float* __restrict__ rel_bias,
              bf16* __restrict__ out)
{
    __shared__ bf16 qs[64][40];
    __shared__ bf16 ks[64][40];
    __shared__ bf16 vst[32][72];
    __shared__ bf16 ps[64][72];
    __shared__ float bt[225];

    int bx = blockIdx.x;
    int h = bx & 7;
    long wg = bx >> 3;
    int tid = threadIdx.x;
    int warp = tid >> 5, lane = tid & 31;
    int g = lane >> 2, t = lane & 3;

    #pragma unroll
    for (int i = 0; i < 2; i++) {
        int fid = tid + i * 128;
        int m = fid >> 2, ch = (fid & 3) * 8;
        size_t base = ((size_t)wg * 64 + m) * (3 * CC) + h * HDIM + ch;
        *(uint4*)&qs[m][ch] = *(const uint4*)(qkv + base);
        *(uint4*)&ks[m][ch] = *(const uint4*)(qkv + base + CC);
        uint4 vv = *(const uint4*)(qkv + base + 2 * CC);
        bf16* ve = (bf16*)&vv;
        #pragma unroll
        for (int j = 0; j < 8; j++) vst[ch + j][m] = ve[j];
    }
    for (int i = tid; i < 225; i += 128) bt[i] = rel_bias[i * NHEAD + h];
    __syncthreads();

    int wm = warp * 16;
    const uint32_t* qsW = (const uint32_t*)qs;
    const uint32_t* ksW = (const uint32_t*)ks;
    const uint32_t* vstW = (const uint32_t*)vst;
    uint32_t* psW = (uint32_t*)ps;

    float s[8][4];
    #pragma unroll
    for (int ni = 0; ni < 8; ni++)
        #pragma unroll
        for (int r = 0; r < 4; r++) s[ni][r] = 0.f;

    #pragma unroll
    for (int kt = 0; kt < 2; kt++) {
        int kw = kt * 8;
        uint32_t a0 = qsW[(wm + g) * 20 + kw + t];
        uint32_t a1 = qsW[(wm + g + 8) * 20 + kw + t];
        uint32_t a2 = qsW[(wm + g) * 20 + kw + t + 4];
        uint32_t a3 = qsW[(wm + g + 8) * 20 + kw + t + 4];
        #pragma unroll
        for (int ni = 0; ni < 8; ni++) {
            uint32_t b0 = ksW[(ni * 8 + g) * 20 + kw + t];
            uint32_t b1 = ksW[(ni * 8 + g) * 20 + kw + t + 4];
            mma_bf16(s[ni], a0, a1, a2, a3, b0, b1);
        }
    }

    int r0 = wm + g, r1 = wm + g + 8;
    int rh0 = r0 >> 3, rw0 = r0 & 7;
    int rh1 = r1 >> 3, rw1 = r1 & 7;
    float mx0 = -1e30f, mx1 = -1e30f;
    #pragma unroll
    for (int ni = 0; ni < 8; ni++) {
        #pragma unroll
        for (int cc2 = 0; cc2 < 2; cc2++) {
            int col = ni * 8 + 2 * t + cc2;
            int mh = col >> 3, mw = col & 7;
            s[ni][cc2]     = s[ni][cc2]     * SCALE_F + bt[(rh0 - mh + 7) * 15 + (rw0 - mw + 7)];
            s[ni][2 + cc2] = s[ni][2 + cc2] * SCALE_F + bt[(rh1 - mh + 7) * 15 + (rw1 - mw + 7)];
            mx0 = fmaxf(mx0, s[ni][cc2]);
            mx1 = fmaxf(mx1, s[ni][2 + cc2]);
        }
    }
    mx0 = fmaxf(mx0, __shfl_xor_sync(0xffffffffu, mx0, 1));
    mx0 = fmaxf(mx0, __shfl_xor_sync(0xffffffffu, mx0, 2));
    mx1 = fmaxf(mx1, __shfl_xor_sync(0xffffffffu, mx1, 1));
    mx1 = fmaxf(mx1, __shfl_xor_sync(0xffffffffu, mx1, 2));
    float sum0 = 0.f, sum1 = 0.f;
    #pragma unroll
    for (int ni = 0; ni < 8; ni++) {
        s[ni][0] = __expf(s[ni][0] - mx0); sum0 += s[ni][0];
        s[ni][1] = __expf(s[ni][1] - mx0); sum0 += s[ni][1];
        s[ni][2] = __expf(s[ni][2] - mx1); sum1 += s[ni][2];
        s[ni][3] = __expf(s[ni][3] - mx1); sum1 += s[ni][3];
    }
    sum0 += __shfl_xor_sync(0xffffffffu, sum0, 1);
    sum0 += __shfl_xor_sync(0xffffffffu, sum0, 2);
    sum1 += __shfl_xor_sync(0xffffffffu, sum1, 1);
    sum1 += __shfl_xor_sync(0xffffffffu, sum1, 2);
    float inv0 = 1.0f / sum0, inv1 = 1.0f / sum1;
    #pragma unroll
    for (int ni = 0; ni < 8; ni++) {
        psW[r0 * 36 + ni * 4 + t] = pack_bf16(s[ni][0] * inv0, s[ni][1] * inv0);
        psW[r1 * 36 + ni * 4 + t] = pack_bf16(s[ni][2] * inv1, s[ni][3] * inv1);
    }
    __syncwarp();

    float o[4][4];
    #pragma unroll
    for (int ni = 0; ni < 4; ni++)
        #pragma unroll
        for (int r = 0; r < 4; r++) o[ni][r] = 0.f;
    #pragma unroll
    for (int kt = 0; kt < 4; kt++) {
        int kw = kt * 8;
        uint32_t a0 = psW[(wm + g) * 36 + kw + t];
        uint32_t a1 = psW[(wm + g + 8) * 36 + kw + t];
        uint32_t a2 = psW[(wm + g) * 36 + kw + t + 4];
        uint32_t a3 = psW[(wm + g + 8) * 36 + kw + t + 4];
        #pragma unroll
        for (int ni = 0; ni < 4; ni++) {
            uint32_t b0 = vstW[(ni * 8 + g) * 36 + kw + t];
            uint32_t b1 = vstW[(ni * 8 + g) * 36 + kw + t + 4];
            mma_bf16(o[ni], a0, a1, a2, a3, b0, b1);
        }
    }
    size_t ob0 = ((size_t)wg * 64 + r0) * CC + h * HDIM;
    size_t ob1 = ((size_t)wg * 64 + r1) * CC + h * HDIM;
    #pragma unroll
    for (int ni = 0; ni < 4; ni++) {
        int col = ni * 8 + 2 * t;
        *(uint32_t*)(out + ob0 + col) = pack_bf16(o[ni][0], o[ni][1]);
        *(uint32_t*)(out + ob1 + col) = pack_bf16(o[ni][2], o[ni][3]);
    }
}

// ================ LN (warp/row) -> bf16, shifted-window gather ================
__global__ void ln8g(const float* __restrict__ x,
                     const float* __restrict__ gamma,
                     const float* __restrict__ beta,
                     bf16* __restrict__ out)
{
    int w = threadIdx.x >> 5, lane = threadIdx.x & 31;
    long drow = (long)blockIdx.x * 8 + w;
    long srow = unwin_row(drow);

    const float4* px = (const float4*)(x + srow * CC);
    float4 v0 = px[lane], v1 = px[lane + 32];
    float s  = v0.x + v0.y + v0.z + v0.w + v1.x + v1.y + v1.z + v1.w;
    float s2 = v0.x*v0.x + v0.y*v0.y + v0.z*v0.z + v0.w*v0.w
             + v1.x*v1.x + v1.y*v1.y + v1.z*v1.z + v1.w*v1.w;
    #pragma unroll
    for (int o = 16; o > 0; o >>= 1) {
        s  += __shfl_xor_sync(0xffffffffu, s,  o);
        s2 += __shfl_xor_sync(0xffffffffu, s2, o);
    }
    float mean = s * (1.0f / CC);
    float inv = rsqrtf(s2 * (1.0f / CC) - mean * mean + EPS_F);
    float4 g0 = *(const float4*)(gamma + lane * 4), g1 = *(const float4*)(gamma + 128 + lane * 4);
    float4 b0 = *(const float4*)(beta  + lane * 4), b1 = *(const float4*)(beta  + 128 + lane * 4);
    uint2 o0, o1;
    o0.x = pack_bf16((v0.x - mean) * inv * g0.x + b0.x, (v0.y - mean) * inv * g0.y + b0.y);
    o0.y = pack_bf16((v0.z - mean) * inv * g0.z + b0.z, (v0.w - mean) * inv * g0.w + b0.w);
    o1.x = pack_bf16((v1.x - mean) * inv * g1.x + b1.x, (v1.y - mean) * inv * g1.y + b1.y);
    o1.y = pack_bf16((v1.z - mean) * inv * g1.z + b1.z, (v1.w - mean) * inv * g1.w + b1.w);
    *(uint2*)(out + drow * CC + lane * 4)       = o0;
    *(uint2*)(out + drow * CC + 128 + lane * 4) = o1;
}

// ---------------- launch ----------------
extern "C" void kernel_launch(void* const* d_in, const int* in_sizes, int n_in,
                              void* d_out, int out_size)
{
    const float* x       = (const float*)d_in[0];
    const float* norm1_g = (const float*)d_in[1];
    const float* norm1_b = (const float*)d_in[2];
    const float* qkv_w   = (const float*)d_in[3];
    const float* qkv_b   = (const float*)d_in[4];
    const float* rel_b   = (const float*)d_in[5];
    const float* proj_w  = (const float*)d_in[6];
    const float* proj_b  = (const float*)d_in[7];
    const float* norm2_g = (const float*)d_in[8];
    const float* norm2_b = (const float*)d_in[9];
    const float* fc1_w   = (const float*)d_in[10];
    const float* fc1_b   = (const float*)d_in[11];
    const float* fc2_w   = (const float*)d_in[12];
    const float* fc2_b   = (const float*)d_in[13];
    float* out = (float*)d_out;

    bf16 *p_hw, *p_qkv, *p_ob, *p_wt;
    float *p_x2;
    cudaGetSymbolAddress((void**)&p_hw,   g_hw);
    cudaGetSymbolAddress((void**)&p_qkv,  g_qkv);
    cudaGetSymbolAddress((void**)&p_ob,   g_ob);
    cudaGetSymbolAddress((void**)&p_x2,   g_x2);
    cudaGetSymbolAddress((void**)&p_wt,   g_wt);

    cudaFuncSetAttribute(gemm_bf<false, false, true >, cudaFuncAttributeMaxDynamicSharedMemorySize, GSMEM);
    cudaFuncSetAttribute(gemm_bf<true,  false, true >, cudaFuncAttributeMaxDynamicSharedMemorySize, GSMEM);
    cudaFuncSetAttribute(gemm_bf<false, true,  false>, cudaFuncAttributeMaxDynamicSharedMemorySize, GSMEM);
    cudaFuncSetAttribute(proj_fused, cudaFuncAttributeMaxDynamicSharedMemorySize, PSMEM);

    // 0) convert + transpose weights to bf16
    dim3 cb(32, 32);
    cvt_w<<<dim3(768 / 32, 256 / 32), cb>>>(qkv_w,  p_wt + WT_QKV, 256, 768);
    cvt_w<<<dim3(256 / 32, 256 / 32), cb>>>(proj_w, p_wt + WT_PROJ, 256, 256);
    cvt_w<<<dim3(256 / 32, 256 / 32), cb>>>(fc1_w,  p_wt + WT_FC1, 256, 256);
    cvt_w<<<dim3(256 / 32, 256 / 32), cb>>>(fc2_w,  p_wt + WT_FC2, 256, 256);

    // 1) LN1 + shifted-window gather -> bf16 (windowed order)
    ln8g<<<TTOT / 8, 256>>>(x, norm1_g, norm1_b, p_hw);

    // 2) QKV GEMM -> bf16
    gemm_bf<false, false, true><<<dim3(6, TTOT / 128), 256, GSMEM>>>(
        p_hw, p_wt + WT_QKV, qkv_b, nullptr, nullptr, p_qkv, TTOT, 768, CC);

    // 3) bf16 tensor-core windowed attention -> bf16
    attn_mma<<<NWIN * NHEAD, 128>>>(p_qkv, rel_b, p_ob);

    // 4) fused proj GEMM + unwindow residual + LN2 -> x2 fp32, ln bf16 (orig order)
    proj_fused<<<TTOT / 64, 256, PSMEM>>>(
        p_ob, p_wt + WT_PROJ, proj_b, x, norm2_g, norm2_b, p_x2, p_hw);

    // 5) fc1 + GELU -> bf16
    gemm_bf<true, false, true><<<dim3(2, TTOT / 128), 256, GSMEM>>>(
        p_hw, p_wt + WT_FC1, fc1_b, nullptr, nullptr, p_ob, TTOT, CC, CC);

    // 6) fc2 + residual -> fp32 out
    gemm_bf<false, true, false><<<dim3(2, TTOT / 128), 256, GSMEM>>>(
        p_ob, p_wt + WT_FC2, fc2_b, p_x2, out, nullptr, TTOT, CC, CC);
}

// round 7
// speedup vs baseline: 5.9866x; 1.0109x over previous
#include <cuda_runtime.h>
#include <cuda_bf16.h>
#include <math.h>
#include <stdint.h>

// ---------------- problem constants ----------------
#define CC      256
#define NHEAD   8
#define HDIM    32
#define SSHIFT  4
#define NWIN    2048
#define TTOT    131072
#define SCALE_F 0.1767766952966369f
#define EPS_F   1e-5f

typedef __nv_bfloat16 bf16;
typedef __nv_bfloat162 bf162;

// ---------------- scratch ----------------
__device__ __align__(16) bf16  g_hw[TTOT * CC];          // LN2 output (fc1 input)
__device__ __align__(16) bf16  g_ob[TTOT * CC];          // attn out / fc1 out (bf16)
__device__ __align__(16) float g_x2[TTOT * CC];          // residual fp32
__device__ __align__(16) bf16  g_wt[768 * 256 + 3 * 256 * 256]; // bf16 weights

#define WT_QKV  0
#define WT_PROJ (768 * 256)
#define WT_FC1  (WT_PROJ + 256 * 256)
#define WT_FC2  (WT_FC1 + 256 * 256)

// ---------------- helpers ----------------
__device__ __forceinline__ uint32_t smem_u32(const void* p) {
    uint32_t a;
    asm("{ .reg .u64 t; cvta.to.shared.u64 t, %1; cvt.u32.u64 %0, t; }" : "=r"(a) : "l"(p));
    return a;
}
__device__ __forceinline__ void mma_bf16(float c[4],
                                         uint32_t a0, uint32_t a1, uint32_t a2, uint32_t a3,
                                         uint32_t b0, uint32_t b1) {
    asm volatile(
        "mma.sync.aligned.m16n8k16.row.col.f32.bf16.bf16.f32 "
        "{%0,%1,%2,%3}, {%4,%5,%6,%7}, {%8,%9}, {%0,%1,%2,%3};"
        : "+f"(c[0]), "+f"(c[1]), "+f"(c[2]), "+f"(c[3])
        : "r"(a0), "r"(a1), "r"(a2), "r"(a3), "r"(b0), "r"(b1));
}
__device__ __forceinline__ uint32_t pack_bf16(float x, float y) {
    bf162 v = __floats2bfloat162_rn(x, y);
    return *(uint32_t*)&v;
}
#define CP16(dst, src) \
    asm volatile("cp.async.cg.shared.global [%0], [%1], 16;" :: "r"(dst), "l"(src) : "memory")
#define CP_COMMIT() asm volatile("cp.async.commit_group;" ::: "memory")
#define CP_WAIT1()  asm volatile("cp.async.wait_group 1;" ::: "memory")
#define CP_WAIT0()  asm volatile("cp.async.wait_group 0;" ::: "memory")

// windowed row -> original token row (reverse shift)
__device__ __forceinline__ long unwin_row(long wr) {
    int batch = (int)(wr >> 14);
    int win   = ((int)wr >> 6) & 255;
    int token = (int)wr & 63;
    int ys = ((win >> 4) << 3) + (token >> 3);
    int xs = ((win & 15) << 3) + (token & 7);
    int y  = (ys + SSHIFT) & 127;
    int xx = (xs + SSHIFT) & 127;
    return (long)batch * 16384 + y * 128 + xx;
}

#define ROW_WORDS 20
#define BKT 32

// ================ fused LN1 + QKV GEMM + windowed attention ================
// One CTA = 128 windowed rows = 2 windows. Loops over 8 heads.
#define QA_A    0                        // A tile: 128 x 264 bf16 (132 words/row)
#define QA_B    67584                    // B: 2 x 96 x 264 bf16
#define QA_QS   168960                   // q staging: 128 x 40 bf16 (20 w/row)
#define QA_KS   179200
#define QA_VST  189440                   // v^T: 32 x 152 bf16 (76 w/row)
#define QA_PS   199168                   // P: 128 x 72 bf16 (36 w/row)
#define QA_LUT  217600                   // rel bias LUT (225 f32)
#define QA_QB   218624                   // qkv bias (768 f32)
#define QA_SMEM 221696

__global__ __launch_bounds__(256)
void qkv_attn(const float* __restrict__ x,
              const float* __restrict__ g1, const float* __restrict__ b1v,
              const bf16* __restrict__ Wt3, const float* __restrict__ qkvb,
              const float* __restrict__ rel_bias, bf16* __restrict__ out)
{
    extern __shared__ char smc[];
    float*    smF = (float*)smc;
    uint32_t* smW = (uint32_t*)smc;
    bf16*     smH = (bf16*)smc;
    uint32_t  sm0 = smem_u32(smc);

    int tid = threadIdx.x, warp = tid >> 5, lane = tid & 31;
    int g = lane >> 2, t = lane & 3;
    long bm = (long)blockIdx.x * 128;

    float* qb  = smF + QA_QB / 4;
    float* lut = smF + QA_LUT / 4;

    #pragma unroll
    for (int i = 0; i < 3; i++) qb[tid + i * 256] = qkvb[tid + i * 256];

    // ---- phase 0: LN1 + shifted-window gather into A tile (warp per row) ----
    for (int i = 0; i < 16; i++) {
        int r = warp * 16 + i;
        long srow = unwin_row(bm + r);
        const float4* px = (const float4*)(x + srow * 256);
        float4 v0 = px[lane * 2], v1 = px[lane * 2 + 1];
        float s  = v0.x + v0.y + v0.z + v0.w + v1.x + v1.y + v1.z + v1.w;
        float s2 = v0.x*v0.x + v0.y*v0.y + v0.z*v0.z + v0.w*v0.w
                 + v1.x*v1.x + v1.y*v1.y + v1.z*v1.z + v1.w*v1.w;
        #pragma unroll
        for (int o = 16; o > 0; o >>= 1) {
            s  += __shfl_xor_sync(0xffffffffu, s,  o);
            s2 += __shfl_xor_sync(0xffffffffu, s2, o);
        }
        float mean = s * (1.0f / 256.0f);
        float inv = rsqrtf(s2 * (1.0f / 256.0f) - mean * mean + EPS_F);
        float4 ga = *(const float4*)(g1 + lane * 8);
        float4 gb = *(const float4*)(g1 + lane * 8 + 4);
        float4 ba = *(const float4*)(b1v + lane * 8);
        float4 bb = *(const float4*)(b1v + lane * 8 + 4);
        uint4 o4;
        o4.x = pack_bf16((v0.x - mean) * inv * ga.x + ba.x, (v0.y - mean) * inv * ga.y + ba.y);
        o4.y = pack_bf16((v0.z - mean) * inv * ga.z + ba.z, (v0.w - mean) * inv * ga.w + ba.w);
        o4.z = pack_bf16((v1.x - mean) * inv * gb.x + bb.x, (v1.y - mean) * inv * gb.y + bb.y);
        o4.w = pack_bf16((v1.z - mean) * inv * gb.z + bb.z, (v1.w - mean) * inv * gb.w + bb.w);
        *(uint4*)(smH + r * 264 + lane * 8) = o4;
    }
    __syncthreads();

    auto loadB = [&](int buf, int h) {
        uint32_t Bs = sm0 + QA_B + buf * 50688;
        const bf16* src = Wt3 + (size_t)h * 96 * 256;
        #pragma unroll
        for (int i = 0; i < 12; i++) {
            int e = tid + i * 256;
            int row = e >> 5, off = (e & 31) * 8;
            CP16(Bs + row * 528 + off * 2, src + row * 256 + off);
        }
    };

    int wm = (warp & 3) * 32;
    int wn = (warp >> 2) * 48;
    int w  = warp >> 2;           // attention window
    int wm2 = (warp & 3) * 16;

    loadB(0, 0); CP_COMMIT();

    for (int h = 0; h < 8; h++) {
        if (h < 7) { loadB((h + 1) & 1, h + 1); CP_COMMIT(); CP_WAIT1(); }
        else CP_WAIT0();
        __syncthreads();

        // ---- qkv GEMM for head h: 128x96x256 ----
        float c[2][6][4];
        #pragma unroll
        for (int mi = 0; mi < 2; mi++)
            #pragma unroll
            for (int ni = 0; ni < 6; ni++)
                #pragma unroll
                for (int r = 0; r < 4; r++) c[mi][ni][r] = 0.f;

        {
            const uint32_t* As = smW;
            const uint32_t* Bs = smW + QA_B / 4 + (h & 1) * 12672;
            #pragma unroll
            for (int ks = 0; ks < 16; ks++) {
                int kw = ks * 8;
                uint32_t a[2][4];
                #pragma unroll
                for (int mi = 0; mi < 2; mi++) {
                    const uint32_t* ar = As + (wm + mi * 16) * 132 + kw + t;
                    a[mi][0] = ar[g * 132];
                    a[mi][1] = ar[(g + 8) * 132];
                    a[mi][2] = ar[g * 132 + 4];
                    a[mi][3] = ar[(g + 8) * 132 + 4];
                }
                #pragma unroll
                for (int ni = 0; ni < 6; ni++) {
                    const uint32_t* br = Bs + (wn + ni * 8 + g) * 132 + kw + t;
                    uint32_t b0 = br[0];
                    uint32_t b1 = br[4];
                    mma_bf16(c[0][ni], a[0][0], a[0][1], a[0][2], a[0][3], b0, b1);
                    mma_bf16(c[1][ni], a[1][0], a[1][1], a[1][2], a[1][3], b0, b1);
                }
            }
        }
        __syncthreads();   // all warps done with B[h&1] & previous attention

        // ---- stage q/k/v (+bias) into smem ----
        #pragma unroll
        for (int mi = 0; mi < 2; mi++) {
            int lr0 = wm + mi * 16 + g, lr1 = lr0 + 8;
            #pragma unroll
            for (int ni = 0; ni < 6; ni++) {
                int col = wn + ni * 8 + 2 * t;
                int mat = col >> 5, cj = col & 31;
                float bb0 = qb[mat * 256 + h * 32 + cj];
                float bb1 = qb[mat * 256 + h * 32 + cj + 1];
                float v0 = c[mi][ni][0] + bb0, v1 = c[mi][ni][1] + bb1;
                float v2 = c[mi][ni][2] + bb0, v3 = c[mi][ni][3] + bb1;
                if (mat == 0) {
                    smW[QA_QS / 4 + lr0 * 20 + (cj >> 1)] = pack_bf16(v0, v1);
                    smW[QA_QS / 4 + lr1 * 20 + (cj >> 1)] = pack_bf16(v2, v3);
                } else if (mat == 1) {
                    smW[QA_KS / 4 + lr0 * 20 + (cj >> 1)] = pack_bf16(v0, v1);
                    smW[QA_KS / 4 + lr1 * 20 + (cj >> 1)] = pack_bf16(v2, v3);
                } else {
                    bf16* ve = smH + QA_VST / 2;
                    ve[cj * 152 + lr0]       = __float2bfloat16_rn(v0);
                    ve[(cj + 1) * 152 + lr0] = __float2bfloat16_rn(v1);
                    ve[cj * 152 + lr1]       = __float2bfloat16_rn(v2);
                    ve[(cj + 1) * 152 + lr1] = __float2bfloat16_rn(v3);
                }
            }
        }
        if (tid < 225) lut[tid] = rel_bias[tid * 8 + h];
        __syncthreads();

        // ---- attention for window w, head h ----
        float s[8][4];
        #pragma unroll
        for (int ni = 0; ni < 8; ni++)
            #pragma unroll
            for (int r = 0; r < 4; r++) s[ni][r] = 0.f;

        #pragma unroll
        for (int kt = 0; kt < 2; kt++) {
            int kw = kt * 8;
            uint32_t a0 = smW[QA_QS / 4 + (w * 64 + wm2 + g) * 20 + kw + t];
            uint32_t a1 = smW[QA_QS / 4 + (w * 64 + wm2 + g + 8) * 20 + kw + t];
            uint32_t a2 = smW[QA_QS / 4 + (w * 64 + wm2 + g) * 20 + kw + t + 4];
            uint32_t a3 = smW[QA_QS / 4 + (w * 64 + wm2 + g + 8) * 20 + kw + t + 4];
            #pragma unroll
            for (int ni = 0; ni < 8; ni++) {
                uint32_t b0 = smW[QA_KS / 4 + (w * 64 + ni * 8 + g) * 20 + kw + t];
                uint32_t b1 = smW[QA_KS / 4 + (w * 64 + ni * 8 + g) * 20 + kw + t + 4];
                mma_bf16(s[ni], a0, a1, a2, a3, b0, b1);
            }
        }

        int r0 = wm2 + g, r1 = wm2 + g + 8;
        int rh0 = r0 >> 3, rw0 = r0 & 7;
        int rh1 = r1 >> 3, rw1 = r1 & 7;
        float mx0 = -1e30f, mx1 = -1e30f;
        #pragma unroll
        for (int ni = 0; ni < 8; ni++) {
            #pragma unroll
            for (int cc2 = 0; cc2 < 2; cc2++) {
                int col = ni * 8 + 2 * t + cc2;
                int mh = col >> 3, mw = col & 7;
                s[ni][cc2]     = s[ni][cc2]     * SCALE_F + lut[(rh0 - mh + 7) * 15 + (rw0 - mw + 7)];
                s[ni][2 + cc2] = s[ni][2 + cc2] * SCALE_F + lut[(rh1 - mh + 7) * 15 + (rw1 - mw + 7)];
                mx0 = fmaxf(mx0, s[ni][cc2]);
                mx1 = fmaxf(mx1, s[ni][2 + cc2]);
            }
        }
        mx0 = fmaxf(mx0, __shfl_xor_sync(0xffffffffu, mx0, 1));
        mx0 = fmaxf(mx0, __shfl_xor_sync(0xffffffffu, mx0, 2));
        mx1 = fmaxf(mx1, __shfl_xor_sync(0xffffffffu, mx1, 1));
        mx1 = fmaxf(mx1, __shfl_xor_sync(0xffffffffu, mx1, 2));
        float sum0 = 0.f, sum1 = 0.f;
        #pragma unroll
        for (int ni = 0; ni < 8; ni++) {
            s[ni][0] = __expf(s[ni][0] - mx0); sum0 += s[ni][0];
            s[ni][1] = __expf(s[ni][1] - mx0); sum0 += s[ni][1];
            s[ni][2] = __expf(s[ni][2] - mx1); sum1 += s[ni][2];
            s[ni][3] = __expf(s[ni][3] - mx1); sum1 += s[ni][3];
        }
        sum0 += __shfl_xor_sync(0xffffffffu, sum0, 1);
        sum0 += __shfl_xor_sync(0xffffffffu, sum0, 2);
        sum1 += __shfl_xor_sync(0xffffffffu, sum1, 1);
        sum1 += __shfl_xor_sync(0xffffffffu, sum1, 2);
        float inv0 = 1.0f / sum0, inv1 = 1.0f / sum1;
        #pragma unroll
        for (int ni = 0; ni < 8; ni++) {
            smW[QA_PS / 4 + (w * 64 + r0) * 36 + ni * 4 + t] = pack_bf16(s[ni][0] * inv0, s[ni][1] * inv0);
            smW[QA_PS / 4 + (w * 64 + r1) * 36 + ni * 4 + t] = pack_bf16(s[ni][2] * inv1, s[ni][3] * inv1);
        }
        __syncwarp();

        float o[4][4];
        #pragma unroll
        for (int ni = 0; ni < 4; ni++)
            #pragma unroll
            for (int r = 0; r < 4; r++) o[ni][r] = 0.f;
        #pragma unroll
        for (int kt = 0; kt < 4; kt++) {
            int kw = kt * 8;
            uint32_t a0 = smW[QA_PS / 4 + (w * 64 + wm2 + g) * 36 + kw + t];
            uint32_t a1 = smW[QA_PS / 4 + (w * 64 + wm2 + g + 8) * 36 + kw + t];
            uint32_t a2 = smW[QA_PS / 4 + (w * 64 + wm2 + g) * 36 + kw + t + 4];
            uint32_t a3 = smW[QA_PS / 4 + (w * 64 + wm2 + g + 8) * 36 + kw + t + 4];
            #pragma unroll
            for (int ni = 0; ni < 4; ni++) {
                uint32_t b0 = smW[QA_VST / 4 + (ni * 8 + g) * 76 + w * 32 + kw + t];
                uint32_t b1 = smW[QA_VST / 4 + (ni * 8 + g) * 76 + w * 32 + kw + t + 4];
                mma_bf16(o[ni], a0, a1, a2, a3, b0, b1);
            }
        }
        size_t ob0 = (size_t)(bm + w * 64 + r0) * 256 + h * 32;
        size_t ob1 = (size_t)(bm + w * 64 + r1) * 256 + h * 32;
        #pragma unroll
        for (int ni = 0; ni < 4; ni++) {
            int col = ni * 8 + 2 * t;
            *(uint32_t*)(out + ob0 + col) = pack_bf16(o[ni][0], o[ni][1]);
            *(uint32_t*)(out + ob1 + col) = pack_bf16(o[ni][2], o[ni][3]);
        }
    }
}

// ================ bf16 mma GEMM 128x128 (fc1/fc2) ================
#define STAGE_WORDS (256 * ROW_WORDS)
#define STAGE_BYTES (STAGE_WORDS * 4)
#define GSMEM (3 * STAGE_BYTES)

template <bool GELU, bool RESID, bool OUTBF>
__global__ __launch_bounds__(256, 2)
void gemm_bf(const bf16* __restrict__ A, const bf16* __restrict__ Bt,
             const float* __restrict__ bias, const float* __restrict__ R,
             float* __restrict__ C, bf16* __restrict__ Cb, int M, int N, int K)
{
    extern __shared__ float sm[];
    uint32_t sm0 = smem_u32(sm);

    int tid  = threadIdx.x;
    int bn   = blockIdx.x * 128;
    int bm   = blockIdx.y * 128;
    int warp = tid >> 5, lane = tid & 31;
    int wm   = (warp & 3) * 32;
    int wn   = (warp >> 2) * 64;
    int g    = lane >> 2;
    int t    = lane & 3;

    const int lrow = tid >> 2, lch = (tid & 3) * 8;

    float c[2][8][4];
    #pragma unroll
    for (int mi = 0; mi < 2; mi++)
        #pragma unroll
        for (int ni = 0; ni < 8; ni++)
            #pragma unroll
            for (int r = 0; r < 4; r++) c[mi][ni][r] = 0.f;

    auto load_stage = [&](int buf, int k0) {
        uint32_t As = sm0 + buf * STAGE_BYTES;
        uint32_t Bs = As + 128 * 80;
        #pragma unroll
        for (int i = 0; i < 2; i++) {
            int row = lrow + i * 64;
            CP16(As + row * 80 + lch * 2, A  + (size_t)(bm + row) * K + k0 + lch);
            CP16(Bs + row * 80 + lch * 2, Bt + (size_t)(bn + row) * K + k0 + lch);
        }
    };

    auto compute_stage = [&](int buf) {
        const uint32_t* As = (const uint32_t*)sm + buf * STAGE_WORDS;
        const uint32_t* Bs = As + 128 * ROW_WORDS;
        #pragma unroll
        for (int kt = 0; kt < 2; kt++) {
            int kw = kt * 8;
            uint32_t a[2][4];
            #pragma unroll
            for (int mi = 0; mi < 2; mi++) {
                const uint32_t* ar = As + (wm + mi * 16) * ROW_WORDS + kw + t;
                a[mi][0] = ar[g * ROW_WORDS];
                a[mi][1] = ar[(g + 8) * ROW_WORDS];
                a[mi][2] = ar[g * ROW_WORDS + 4];
                a[mi][3] = ar[(g + 8) * ROW_WORDS + 4];
            }
            #pragma unroll
            for (int ni = 0; ni < 8; ni++) {
                const uint32_t* br = Bs + (wn + ni * 8 + g) * ROW_WORDS + kw + t;
                uint32_t b0 = br[0];
                uint32_t b1 = br[4];
                mma_bf16(c[0][ni], a[0][0], a[0][1], a[0][2], a[0][3], b0, b1);
                mma_bf16(c[1][ni], a[1][0], a[1][1], a[1][2], a[1][3], b0, b1);
            }
        }
    };

    const int niter = K / BKT;
    load_stage(0, 0); CP_COMMIT();
    load_stage(1, BKT); CP_COMMIT();
    CP_WAIT1();
    __syncthreads();
    for (int it = 0; it < niter; ++it) {
        if (it + 2 < niter) load_stage((it + 2) % 3, (it + 2) * BKT);
        CP_COMMIT();
        compute_stage(it % 3);
        CP_WAIT1();
        __syncthreads();
    }

    #pragma unroll
    for (int mi = 0; mi < 2; mi++) {
        int row0 = bm + wm + mi * 16 + g;
        #pragma unroll
        for (int ni = 0; ni < 8; ni++) {
            int col = bn + wn + ni * 8 + 2 * t;
            float b0 = bias[col], b1 = bias[col + 1];
            float v0 = c[mi][ni][0] + b0;
            float v1 = c[mi][ni][1] + b1;
            float v2 = c[mi][ni][2] + b0;
            float v3 = c[mi][ni][3] + b1;
            if (GELU) {
                v0 = 0.5f * v0 * (1.0f + erff(v0 * 0.70710678118654752f));
                v1 = 0.5f * v1 * (1.0f + erff(v1 * 0.70710678118654752f));
                v2 = 0.5f * v2 * (1.0f + erff(v2 * 0.70710678118654752f));
                v3 = 0.5f * v3 * (1.0f + erff(v3 * 0.70710678118654752f));
            }
            if (OUTBF) {
                *(uint32_t*)(Cb + (size_t)row0 * N + col)       = pack_bf16(v0, v1);
                *(uint32_t*)(Cb + (size_t)(row0 + 8) * N + col) = pack_bf16(v2, v3);
            } else {
                if (RESID) {
                    float2 r0 = *(const float2*)(R + (size_t)row0 * N + col);
                    float2 r1 = *(const float2*)(R + (size_t)(row0 + 8) * N + col);
                    v0 += r0.x; v1 += r0.y; v2 += r1.x; v3 += r1.y;
                }
                *(float2*)(C + (size_t)row0 * N + col)       = make_float2(v0, v1);
                *(float2*)(C + (size_t)(row0 + 8) * N + col) = make_float2(v2, v3);
            }
        }
    }
}

// ================ fused proj GEMM + unwindow residual + LN2 ================
#define PSTAGE_WORDS (320 * ROW_WORDS)
#define PSTAGE_BYTES (PSTAGE_WORDS * 4)
#define PTS 260
#define PSMEM (3 * PSTAGE_BYTES)

__global__ __launch_bounds__(256, 2)
void proj_fused(const bf16* __restrict__ A, const bf16* __restrict__ Bt,
                const float* __restrict__ bias,
                const float* __restrict__ x,
                const float* __restrict__ gamma, const float* __restrict__ beta,
                float* __restrict__ x2, bf16* __restrict__ ln_out)
{
    extern __shared__ float sm[];
    uint32_t sm0 = smem_u32(sm);

    const int K = 256, N = 256;
    int tid  = threadIdx.x;
    long bm  = (long)blockIdx.x * 64;
    int warp = tid >> 5, lane = tid & 31;
    int wm   = (warp & 1) * 32;
    int wn   = (warp >> 1) * 64;
    int g    = lane >> 2;
    int t    = lane & 3;

    float c[2][8][4];
    #pragma unroll
    for (int mi = 0; mi < 2; mi++)
        #pragma unroll
        for (int ni = 0; ni < 8; ni++)
            #pragma unroll
            for (int r = 0; r < 4; r++) c[mi][ni][r] = 0.f;

    const int lrow = tid >> 2, lch = (tid & 3) * 8;

    auto load_stage = [&](int buf, int k0) {
        uint32_t As = sm0 + buf * PSTAGE_BYTES;
        uint32_t Bs = As + 64 * 80;
        CP16(As + lrow * 80 + lch * 2, A + (size_t)(bm + lrow) * K + k0 + lch);
        #pragma unroll
        for (int i = 0; i < 4; i++) {
            int row = lrow + i * 64;
            CP16(Bs + row * 80 + lch * 2, Bt + (size_t)row * K + k0 + lch);
        }
    };

    auto compute_stage = [&](int buf) {
        const uint32_t* As = (const uint32_t*)sm + buf * PSTAGE_WORDS;
        const uint32_t* Bs = As + 64 * ROW_WORDS;
        #pragma unroll
        for (int kt = 0; kt < 2; kt++) {
            int kw = kt * 8;
            uint32_t a[2][4];
            #pragma unroll
            for (int mi = 0; mi < 2; mi++) {
                const uint32_t* ar = As + (wm + mi * 16) * ROW_WORDS + kw + t;
                a[mi][0] = ar[g * ROW_WORDS];
                a[mi][1] = ar[(g + 8) * ROW_WORDS];
                a[mi][2] = ar[g * ROW_WORDS + 4];
                a[mi][3] = ar[(g + 8) * ROW_WORDS + 4];
            }
            #pragma unroll
            for (int ni = 0; ni < 8; ni++) {
                const uint32_t* br = Bs + (wn + ni * 8 + g) * ROW_WORDS + kw + t;
                uint32_t b0 = br[0];
                uint32_t b1 = br[4];
                mma_bf16(c[0][ni], a[0][0], a[0][1], a[0][2], a[0][3], b0, b1);
                mma_bf16(c[1][ni], a[1][0], a[1][1], a[1][2], a[1][3], b0, b1);
            }
        }
    };

    const int niter = 8;
    load_stage(0, 0); CP_COMMIT();
    load_stage(1, BKT); CP_COMMIT();
    CP_WAIT1();
    __syncthreads();
    for (int it = 0; it < niter; ++it) {
        if (it + 2 < niter) load_stage((it + 2) % 3, (it + 2) * BKT);
        CP_COMMIT();
        compute_stage(it % 3);
        CP_WAIT1();
        __syncthreads();
    }

    #pragma unroll
    for (int mi = 0; mi < 2; mi++) {
        int lr0 = wm + mi * 16 + g;
        int lr1 = lr0 + 8;
        long t0 = unwin_row(bm + lr0);
        long t1 = unwin_row(bm + lr1);
        #pragma unroll
        for (int ni = 0; ni < 8; ni++) {
            int col = wn + ni * 8 + 2 * t;
            float b0 = bias[col], b1 = bias[col + 1];
            float2 r0 = *(const float2*)(x + t0 * 256 + col);
            float2 r1 = *(const float2*)(x + t1 * 256 + col);
            float v0 = c[mi][ni][0] + b0 + r0.x;
            float v1 = c[mi][ni][1] + b1 + r0.y;
            float v2 = c[mi][ni][2] + b0 + r1.x;
            float v3 = c[mi][ni][3] + b1 + r1.y;
            *(float2*)(x2 + t0 * 256 + col) = make_float2(v0, v1);
            *(float2*)(x2 + t1 * 256 + col) = make_float2(v2, v3);
            *(float2*)(sm + lr0 * PTS + col) = make_float2(v0, v1);
            *(float2*)(sm + lr1 * PTS + col) = make_float2(v2, v3);
        }
    }
    __syncthreads();

    #pragma unroll
    for (int i = 0; i < 8; i++) {
        int row = warp + i * 8;
        const float* pr = sm + row * PTS + lane * 8;
        float4 v0 = *(const float4*)pr;
        float4 v1 = *(const float4*)(pr + 4);
        float s  = v0.x + v0.y + v0.z + v0.w + v1.x + v1.y + v1.z + v1.w;
        float s2 = v0.x*v0.x + v0.y*v0.y + v0.z*v0.z + v0.w*v0.w
                 + v1.x*v1.x + v1.y*v1.y + v1.z*v1.z + v1.w*v1.w;
        #pragma unroll
        for (int o = 16; o > 0; o >>= 1) {
            s  += __shfl_xor_sync(0xffffffffu, s,  o);
            s2 += __shfl_xor_sync(0xffffffffu, s2, o);
        }
        float mean = s * (1.0f / 256.0f);
        float inv = rsqrtf(s2 * (1.0f / 256.0f) - mean * mean + EPS_F);
        float4 ga = *(const float4*)(gamma + lane * 8);
        float4 gb = *(const float4*)(gamma + lane * 8 + 4);
        float4 ba = *(const float4*)(beta + lane * 8);
        float4 bb = *(const float4*)(beta + lane * 8 + 4);
        uint4 o4;
        o4.x = pack_bf16((v0.x - mean) * inv * ga.x + ba.x, (v0.y - mean) * inv * ga.y + ba.y);
        o4.y = pack_bf16((v0.z - mean) * inv * ga.z + ba.z, (v0.w - mean) * inv * ga.w + ba.w);
        o4.z = pack_bf16((v1.x - mean) * inv * gb.x + bb.x, (v1.y - mean) * inv * gb.y + bb.y);
        o4.w = pack_bf16((v1.z - mean) * inv * gb.z + bb.z, (v1.w - mean) * inv * gb.w + bb.w);
        long to = unwin_row(bm + row);
        *(uint4*)(ln_out + to * 256 + lane * 8) = o4;
    }
}

// ================ weight converts ================
__global__ void cvt_w(const float* __restrict__ W, bf16* __restrict__ Wt, int K, int N)
{
    __shared__ float tsm[32][33];
    int k0 = blockIdx.y * 32, n0 = blockIdx.x * 32;
    int tx = threadIdx.x, ty = threadIdx.y;
    tsm[ty][tx] = W[(size_t)(k0 + ty) * N + n0 + tx];
    __syncthreads();
    Wt[(size_t)(n0 + ty) * K + k0 + tx] = __float2bfloat16_rn(tsm[tx][ty]);
}

// qkv weights -> per-head layout: Wt3[h][96][256], rows [q0..31,k0..31,v0..31]
__global__ void cvt_wqkv(const float* __restrict__ W, bf16* __restrict__ Wt3)
{
    __shared__ float tsm[32][33];
    int n0 = blockIdx.x * 32, k0 = blockIdx.y * 32;
    int tx = threadIdx.x, ty = threadIdx.y;
    int n = n0 + tx;
    int h = n / 96, j = n % 96;
    int cidx = (j >> 5) * 256 + h * 32 + (j & 31);
    tsm[ty][tx] = W[(size_t)(k0 + ty) * 768 + cidx];
    __syncthreads();
    Wt3[(size_t)(n0 + ty) * 256 + k0 + tx] = __float2bfloat16_rn(tsm[tx][ty]);
}

// ---------------- launch ----------------
extern "C" void kernel_launch(void* const* d_in, const int* in_sizes, int n_in,
                              void* d_out, int out_size)
{
    const float* x       = (const float*)d_in[0];
    const float* norm1_g = (const float*)d_in[1];
    const float* norm1_b = (const float*)d_in[2];
    const float* qkv_w   = (const float*)d_in[3];
    const float* qkv_b   = (const float*)d_in[4];
    const float* rel_b   = (const float*)d_in[5];
    const float* proj_w  = (const float*)d_in[6];
    const float* proj_b  = (const float*)d_in[7];
    const float* norm2_g = (const float*)d_in[8];
    const float* norm2_b = (const float*)d_in[9];
    const float* fc1_w   = (const float*)d_in[10];
    const float* fc1_b   = (const float*)d_in[11];
    const float* fc2_w   = (const float*)d_in[12];
    const float* fc2_b   = (const float*)d_in[13];
    float* out = (float*)d_out;

    bf16 *p_hw, *p_ob, *p_wt;
    float *p_x2;
    cudaGetSymbolAddress((void**)&p_hw, g_hw);
    cudaGetSymbolAddress((void**)&p_ob, g_ob);
    cudaGetSymbolAddress((void**)&p_x2, g_x2);
    cudaGetSymbolAddress((void**)&p_wt, g_wt);

    cudaFuncSetAttribute(qkv_attn, cudaFuncAttributeMaxDynamicSharedMemorySize, QA_SMEM);
    cudaFuncSetAttribute(gemm_bf<true,  false, true >, cudaFuncAttributeMaxDynamicSharedMemorySize, GSMEM);
    cudaFuncSetAttribute(gemm_bf<false, true,  false>, cudaFuncAttributeMaxDynamicSharedMemorySize, GSMEM);
    cudaFuncSetAttribute(proj_fused, cudaFuncAttributeMaxDynamicSharedMemorySize, PSMEM);

    // 0) weight converts
    dim3 cb(32, 32);
    cvt_wqkv<<<dim3(768 / 32, 256 / 32), cb>>>(qkv_w, p_wt + WT_QKV);
    cvt_w<<<dim3(256 / 32, 256 / 32), cb>>>(proj_w, p_wt + WT_PROJ, 256, 256);
    cvt_w<<<dim3(256 / 32, 256 / 32), cb>>>(fc1_w,  p_wt + WT_FC1, 256, 256);
    cvt_w<<<dim3(256 / 32, 256 / 32), cb>>>(fc2_w,  p_wt + WT_FC2, 256, 256);

    // 1) fused LN1 + QKV + attention -> attn out bf16 (windowed)
    qkv_attn<<<TTOT / 128, 256, QA_SMEM>>>(
        x, norm1_g, norm1_b, p_wt + WT_QKV, qkv_b, rel_b, p_ob);

    // 2) fused proj GEMM + unwindow residual + LN2
    proj_fused<<<TTOT / 64, 256, PSMEM>>>(
        p_ob, p_wt + WT_PROJ, proj_b, x, norm2_g, norm2_b, p_x2, p_hw);

    // 3) fc1 + GELU -> bf16
    gemm_bf<true, false, true><<<dim3(2, TTOT / 128), 256, GSMEM>>>(
        p_hw, p_wt + WT_FC1, fc1_b, nullptr, nullptr, p_ob, TTOT, CC, CC);

    // 4) fc2 + residual -> fp32 out
    gemm_bf<false, true, false><<<dim3(2, TTOT / 128), 256, GSMEM>>>(
        p_ob, p_wt + WT_FC2, fc2_b, p_x2, out, nullptr, TTOT, CC, CC);
}

// round 8
// speedup vs baseline: 6.1857x; 1.0333x over previous
#include <cuda_runtime.h>
#include <cuda_bf16.h>
#include <math.h>
#include <stdint.h>

// ---------------- problem constants ----------------
#define CC      256
#define NHEAD   8
#define HDIM    32
#define SSHIFT  4
#define NWIN    2048
#define TTOT    131072
#define SCALE_F 0.1767766952966369f
#define EPS_F   1e-5f

typedef __nv_bfloat16 bf16;
typedef __nv_bfloat162 bf162;

// ---------------- scratch ----------------
__device__ __align__(16) bf16  g_ob[TTOT * CC];          // attn out (bf16, windowed)
__device__ __align__(16) bf16  g_wt[768 * 256 + 3 * 256 * 256]; // bf16 weights

#define WT_QKV  0
#define WT_PROJ (768 * 256)
#define WT_FC1  (WT_PROJ + 256 * 256)
#define WT_FC2  (WT_FC1 + 256 * 256)

// ---------------- helpers ----------------
__device__ __forceinline__ uint32_t smem_u32(const void* p) {
    uint32_t a;
    asm("{ .reg .u64 t; cvta.to.shared.u64 t, %1; cvt.u32.u64 %0, t; }" : "=r"(a) : "l"(p));
    return a;
}
__device__ __forceinline__ void mma_bf16(float c[4],
                                         uint32_t a0, uint32_t a1, uint32_t a2, uint32_t a3,
                                         uint32_t b0, uint32_t b1) {
    asm volatile(
        "mma.sync.aligned.m16n8k16.row.col.f32.bf16.bf16.f32 "
        "{%0,%1,%2,%3}, {%4,%5,%6,%7}, {%8,%9}, {%0,%1,%2,%3};"
        : "+f"(c[0]), "+f"(c[1]), "+f"(c[2]), "+f"(c[3])
        : "r"(a0), "r"(a1), "r"(a2), "r"(a3), "r"(b0), "r"(b1));
}
__device__ __forceinline__ uint32_t pack_bf16(float x, float y) {
    bf162 v = __floats2bfloat162_rn(x, y);
    return *(uint32_t*)&v;
}
#define CP16(dst, src) \
    asm volatile("cp.async.cg.shared.global [%0], [%1], 16;" :: "r"(dst), "l"(src) : "memory")
#define CP_COMMIT() asm volatile("cp.async.commit_group;" ::: "memory")
#define CP_WAIT1()  asm volatile("cp.async.wait_group 1;" ::: "memory")
#define CP_WAIT0()  asm volatile("cp.async.wait_group 0;" ::: "memory")

// windowed row -> original token row (reverse shift)
__device__ __forceinline__ long unwin_row(long wr) {
    int batch = (int)(wr >> 14);
    int win   = ((int)wr >> 6) & 255;
    int token = (int)wr & 63;
    int ys = ((win >> 4) << 3) + (token >> 3);
    int xs = ((win & 15) << 3) + (token & 7);
    int y  = (ys + SSHIFT) & 127;
    int xx = (xs + SSHIFT) & 127;
    return (long)batch * 16384 + y * 128 + xx;
}

// ================ fused LN1 + QKV GEMM + windowed attention (unchanged) =========
#define QA_A    0
#define QA_B    67584
#define QA_QS   168960
#define QA_KS   179200
#define QA_VST  189440
#define QA_PS   199168
#define QA_LUT  217600
#define QA_QB   218624
#define QA_SMEM 221696

__global__ __launch_bounds__(256)
void qkv_attn(const float* __restrict__ x,
              const float* __restrict__ g1, const float* __restrict__ b1v,
              const bf16* __restrict__ Wt3, const float* __restrict__ qkvb,
              const float* __restrict__ rel_bias, bf16* __restrict__ out)
{
    extern __shared__ char smc[];
    float*    smF = (float*)smc;
    uint32_t* smW = (uint32_t*)smc;
    bf16*     smH = (bf16*)smc;
    uint32_t  sm0 = smem_u32(smc);

    int tid = threadIdx.x, warp = tid >> 5, lane = tid & 31;
    int g = lane >> 2, t = lane & 3;
    long bm = (long)blockIdx.x * 128;

    float* qb  = smF + QA_QB / 4;
    float* lut = smF + QA_LUT / 4;

    #pragma unroll
    for (int i = 0; i < 3; i++) qb[tid + i * 256] = qkvb[tid + i * 256];

    for (int i = 0; i < 16; i++) {
        int r = warp * 16 + i;
        long srow = unwin_row(bm + r);
        const float4* px = (const float4*)(x + srow * 256);
        float4 v0 = px[lane * 2], v1 = px[lane * 2 + 1];
        float s  = v0.x + v0.y + v0.z + v0.w + v1.x + v1.y + v1.z + v1.w;
        float s2 = v0.x*v0.x + v0.y*v0.y + v0.z*v0.z + v0.w*v0.w
                 + v1.x*v1.x + v1.y*v1.y + v1.z*v1.z + v1.w*v1.w;
        #pragma unroll
        for (int o = 16; o > 0; o >>= 1) {
            s  += __shfl_xor_sync(0xffffffffu, s,  o);
            s2 += __shfl_xor_sync(0xffffffffu, s2, o);
        }
        float mean = s * (1.0f / 256.0f);
        float inv = rsqrtf(s2 * (1.0f / 256.0f) - mean * mean + EPS_F);
        float4 ga = *(const float4*)(g1 + lane * 8);
        float4 gb = *(const float4*)(g1 + lane * 8 + 4);
        float4 ba = *(const float4*)(b1v + lane * 8);
        float4 bb = *(const float4*)(b1v + lane * 8 + 4);
        uint4 o4;
        o4.x = pack_bf16((v0.x - mean) * inv * ga.x + ba.x, (v0.y - mean) * inv * ga.y + ba.y);
        o4.y = pack_bf16((v0.z - mean) * inv * ga.z + ba.z, (v0.w - mean) * inv * ga.w + ba.w);
        o4.z = pack_bf16((v1.x - mean) * inv * gb.x + bb.x, (v1.y - mean) * inv * gb.y + bb.y);
        o4.w = pack_bf16((v1.z - mean) * inv * gb.z + bb.z, (v1.w - mean) * inv * gb.w + bb.w);
        *(uint4*)(smH + r * 264 + lane * 8) = o4;
    }
    __syncthreads();

    auto loadB = [&](int buf, int h) {
        uint32_t Bs = sm0 + QA_B + buf * 50688;
        const bf16* src = Wt3 + (size_t)h * 96 * 256;
        #pragma unroll
        for (int i = 0; i < 12; i++) {
            int e = tid + i * 256;
            int row = e >> 5, off = (e & 31) * 8;
            CP16(Bs + row * 528 + off * 2, src + row * 256 + off);
        }
    };

    int wm = (warp & 3) * 32;
    int wn = (warp >> 2) * 48;
    int w  = warp >> 2;
    int wm2 = (warp & 3) * 16;

    loadB(0, 0); CP_COMMIT();

    for (int h = 0; h < 8; h++) {
        if (h < 7) { loadB((h + 1) & 1, h + 1); CP_COMMIT(); CP_WAIT1(); }
        else CP_WAIT0();
        __syncthreads();

        float c[2][6][4];
        #pragma unroll
        for (int mi = 0; mi < 2; mi++)
            #pragma unroll
            for (int ni = 0; ni < 6; ni++)
                #pragma unroll
                for (int r = 0; r < 4; r++) c[mi][ni][r] = 0.f;

        {
            const uint32_t* As = smW;
            const uint32_t* Bs = smW + QA_B / 4 + (h & 1) * 12672;
            #pragma unroll
            for (int ks = 0; ks < 16; ks++) {
                int kw = ks * 8;
                uint32_t a[2][4];
                #pragma unroll
                for (int mi = 0; mi < 2; mi++) {
                    const uint32_t* ar = As + (wm + mi * 16) * 132 + kw + t;
                    a[mi][0] = ar[g * 132];
                    a[mi][1] = ar[(g + 8) * 132];
                    a[mi][2] = ar[g * 132 + 4];
                    a[mi][3] = ar[(g + 8) * 132 + 4];
                }
                #pragma unroll
                for (int ni = 0; ni < 6; ni++) {
                    const uint32_t* br = Bs + (wn + ni * 8 + g) * 132 + kw + t;
                    uint32_t b0 = br[0];
                    uint32_t b1 = br[4];
                    mma_bf16(c[0][ni], a[0][0], a[0][1], a[0][2], a[0][3], b0, b1);
                    mma_bf16(c[1][ni], a[1][0], a[1][1], a[1][2], a[1][3], b0, b1);
                }
            }
        }
        __syncthreads();

        #pragma unroll
        for (int mi = 0; mi < 2; mi++) {
            int lr0 = wm + mi * 16 + g, lr1 = lr0 + 8;
            #pragma unroll
            for (int ni = 0; ni < 6; ni++) {
                int col = wn + ni * 8 + 2 * t;
                int mat = col >> 5, cj = col & 31;
                float bb0 = qb[mat * 256 + h * 32 + cj];
                float bb1 = qb[mat * 256 + h * 32 + cj + 1];
                float v0 = c[mi][ni][0] + bb0, v1 = c[mi][ni][1] + bb1;
                float v2 = c[mi][ni][2] + bb0, v3 = c[mi][ni][3] + bb1;
                if (mat == 0) {
                    smW[QA_QS / 4 + lr0 * 20 + (cj >> 1)] = pack_bf16(v0, v1);
                    smW[QA_QS / 4 + lr1 * 20 + (cj >> 1)] = pack_bf16(v2, v3);
                } else if (mat == 1) {
                    smW[QA_KS / 4 + lr0 * 20 + (cj >> 1)] = pack_bf16(v0, v1);
                    smW[QA_KS / 4 + lr1 * 20 + (cj >> 1)] = pack_bf16(v2, v3);
                } else {
                    bf16* ve = smH + QA_VST / 2;
                    ve[cj * 152 + lr0]       = __float2bfloat16_rn(v0);
                    ve[(cj + 1) * 152 + lr0] = __float2bfloat16_rn(v1);
                    ve[cj * 152 + lr1]       = __float2bfloat16_rn(v2);
                    ve[(cj + 1) * 152 + lr1] = __float2bfloat16_rn(v3);
                }
            }
        }
        if (tid < 225) lut[tid] = rel_bias[tid * 8 + h];
        __syncthreads();

        float s[8][4];
        #pragma unroll
        for (int ni = 0; ni < 8; ni++)
            #pragma unroll
            for (int r = 0; r < 4; r++) s[ni][r] = 0.f;

        #pragma unroll
        for (int kt = 0; kt < 2; kt++) {
            int kw = kt * 8;
            uint32_t a0 = smW[QA_QS / 4 + (w * 64 + wm2 + g) * 20 + kw + t];
            uint32_t a1 = smW[QA_QS / 4 + (w * 64 + wm2 + g + 8) * 20 + kw + t];
            uint32_t a2 = smW[QA_QS / 4 + (w * 64 + wm2 + g) * 20 + kw + t + 4];
            uint32_t a3 = smW[QA_QS / 4 + (w * 64 + wm2 + g + 8) * 20 + kw + t + 4];
            #pragma unroll
            for (int ni = 0; ni < 8; ni++) {
                uint32_t b0 = smW[QA_KS / 4 + (w * 64 + ni * 8 + g) * 20 + kw + t];
                uint32_t b1 = smW[QA_KS / 4 + (w * 64 + ni * 8 + g) * 20 + kw + t + 4];
                mma_bf16(s[ni], a0, a1, a2, a3, b0, b1);
            }
        }

        int r0 = wm2 + g, r1 = wm2 + g + 8;
        int rh0 = r0 >> 3, rw0 = r0 & 7;
        int rh1 = r1 >> 3, rw1 = r1 & 7;
        float mx0 = -1e30f, mx1 = -1e30f;
        #pragma unroll
        for (int ni = 0; ni < 8; ni++) {
            #pragma unroll
            for (int cc2 = 0; cc2 < 2; cc2++) {
                int col = ni * 8 + 2 * t + cc2;
                int mh = col >> 3, mw = col & 7;
                s[ni][cc2]     = s[ni][cc2]     * SCALE_F + lut[(rh0 - mh + 7) * 15 + (rw0 - mw + 7)];
                s[ni][2 + cc2] = s[ni][2 + cc2] * SCALE_F + lut[(rh1 - mh + 7) * 15 + (rw1 - mw + 7)];
                mx0 = fmaxf(mx0, s[ni][cc2]);
                mx1 = fmaxf(mx1, s[ni][2 + cc2]);
            }
        }
        mx0 = fmaxf(mx0, __shfl_xor_sync(0xffffffffu, mx0, 1));
        mx0 = fmaxf(mx0, __shfl_xor_sync(0xffffffffu, mx0, 2));
        mx1 = fmaxf(mx1, __shfl_xor_sync(0xffffffffu, mx1, 1));
        mx1 = fmaxf(mx1, __shfl_xor_sync(0xffffffffu, mx1, 2));
        float sum0 = 0.f, sum1 = 0.f;
        #pragma unroll
        for (int ni = 0; ni < 8; ni++) {
            s[ni][0] = __expf(s[ni][0] - mx0); sum0 += s[ni][0];
            s[ni][1] = __expf(s[ni][1] - mx0); sum0 += s[ni][1];
            s[ni][2] = __expf(s[ni][2] - mx1); sum1 += s[ni][2];
            s[ni][3] = __expf(s[ni][3] - mx1); sum1 += s[ni][3];
        }
        sum0 += __shfl_xor_sync(0xffffffffu, sum0, 1);
        sum0 += __shfl_xor_sync(0xffffffffu, sum0, 2);
        sum1 += __shfl_xor_sync(0xffffffffu, sum1, 1);
        sum1 += __shfl_xor_sync(0xffffffffu, sum1, 2);
        float inv0 = 1.0f / sum0, inv1 = 1.0f / sum1;
        #pragma unroll
        for (int ni = 0; ni < 8; ni++) {
            smW[QA_PS / 4 + (w * 64 + r0) * 36 + ni * 4 + t] = pack_bf16(s[ni][0] * inv0, s[ni][1] * inv0);
            smW[QA_PS / 4 + (w * 64 + r1) * 36 + ni * 4 + t] = pack_bf16(s[ni][2] * inv1, s[ni][3] * inv1);
        }
        __syncwarp();

        float o[4][4];
        #pragma unroll
        for (int ni = 0; ni < 4; ni++)
            #pragma unroll
            for (int r = 0; r < 4; r++) o[ni][r] = 0.f;
        #pragma unroll
        for (int kt = 0; kt < 4; kt++) {
            int kw = kt * 8;
            uint32_t a0 = smW[QA_PS / 4 + (w * 64 + wm2 + g) * 36 + kw + t];
            uint32_t a1 = smW[QA_PS / 4 + (w * 64 + wm2 + g + 8) * 36 + kw + t];
            uint32_t a2 = smW[QA_PS / 4 + (w * 64 + wm2 + g) * 36 + kw + t + 4];
            uint32_t a3 = smW[QA_PS / 4 + (w * 64 + wm2 + g + 8) * 36 + kw + t + 4];
            #pragma unroll
            for (int ni = 0; ni < 4; ni++) {
                uint32_t b0 = smW[QA_VST / 4 + (ni * 8 + g) * 76 + w * 32 + kw + t];
                uint32_t b1 = smW[QA_VST / 4 + (ni * 8 + g) * 76 + w * 32 + kw + t + 4];
                mma_bf16(o[ni], a0, a1, a2, a3, b0, b1);
            }
        }
        size_t ob0 = (size_t)(bm + w * 64 + r0) * 256 + h * 32;
        size_t ob1 = (size_t)(bm + w * 64 + r1) * 256 + h * 32;
        #pragma unroll
        for (int ni = 0; ni < 4; ni++) {
            int col = ni * 8 + 2 * t;
            *(uint32_t*)(out + ob0 + col) = pack_bf16(o[ni][0], o[ni][1]);
            *(uint32_t*)(out + ob1 + col) = pack_bf16(o[ni][2], o[ni][3]);
        }
    }
}

// ================ block2: proj + residual + LN2 + fc1 + GELU + fc2 + residual ====
// 64-row windowed tile; x2 lives in d_out between phases (same-thread RAW).
#define B2_STAGE 25600                 // per stage: A 64x80B + B 256x80B
#define B2_LN    76800                 // ln/h tile: 64 x 132 words (bf16 x 264)
#define B2_RED   110592                // LN reduction: 64 x 8 floats
#define B2_SMEM  112640

__global__ __launch_bounds__(256, 2)
void block2(const bf16* __restrict__ Aob, const bf16* __restrict__ Wp,
            const float* __restrict__ pbias, const float* __restrict__ x,
            const float* __restrict__ g2, const float* __restrict__ b2,
            const bf16* __restrict__ W1, const float* __restrict__ fb1,
            const bf16* __restrict__ W2, const float* __restrict__ fb2,
            float* __restrict__ out)
{
    extern __shared__ char smc[];
    uint32_t sm0 = smem_u32(smc);
    uint32_t* lnW = (uint32_t*)(smc + B2_LN);
    float*    red = (float*)(smc + B2_RED);

    int tid = threadIdx.x, warp = tid >> 5, lane = tid & 31;
    int g = lane >> 2, t = lane & 3;
    long bm = (long)blockIdx.x * 64;
    int wm = (warp & 1) * 32, wn = (warp >> 1) * 64, wnid = warp >> 1;
    const int lrow = tid >> 2, lch = (tid & 3) * 8;

    int lr0[2], lr1[2];
    long t0[2], t1[2];
    #pragma unroll
    for (int mi = 0; mi < 2; mi++) {
        lr0[mi] = wm + mi * 16 + g;
        lr1[mi] = lr0[mi] + 8;
        t0[mi] = unwin_row(bm + lr0[mi]);
        t1[mi] = unwin_row(bm + lr1[mi]);
    }

    float c[2][8][4];

    // ---- generic compute over stage buf (B) with A from stage (phase1) ----
    auto comp1 = [&](int buf) {
        const uint32_t* As = (const uint32_t*)(smc + buf * B2_STAGE);
        const uint32_t* Bs = As + 1280;
        #pragma unroll
        for (int kt = 0; kt < 2; kt++) {
            int kw = kt * 8;
            uint32_t a[2][4];
            #pragma unroll
            for (int mi = 0; mi < 2; mi++) {
                const uint32_t* ar = As + (wm + mi * 16) * 20 + kw + t;
                a[mi][0] = ar[g * 20];
                a[mi][1] = ar[(g + 8) * 20];
                a[mi][2] = ar[g * 20 + 4];
                a[mi][3] = ar[(g + 8) * 20 + 4];
            }
            #pragma unroll
            for (int ni = 0; ni < 8; ni++) {
                const uint32_t* br = Bs + (wn + ni * 8 + g) * 20 + kw + t;
                uint32_t b0 = br[0];
                uint32_t b1 = br[4];
                mma_bf16(c[0][ni], a[0][0], a[0][1], a[0][2], a[0][3], b0, b1);
                mma_bf16(c[1][ni], a[1][0], a[1][1], a[1][2], a[1][3], b0, b1);
            }
        }
    };
    // ---- compute with A from persistent ln/h tile at k-chunk itk ----
    auto compS = [&](int buf, int itk) {
        const uint32_t* Bs = (const uint32_t*)(smc + buf * B2_STAGE + 5120);
        #pragma unroll
        for (int kt = 0; kt < 2; kt++) {
            int kw = itk * 16 + kt * 8;
            uint32_t a[2][4];
            #pragma unroll
            for (int mi = 0; mi < 2; mi++) {
                const uint32_t* ar = lnW + (wm + mi * 16) * 132 + kw + t;
                a[mi][0] = ar[g * 132];
                a[mi][1] = ar[(g + 8) * 132];
                a[mi][2] = ar[g * 132 + 4];
                a[mi][3] = ar[(g + 8) * 132 + 4];
            }
            #pragma unroll
            for (int ni = 0; ni < 8; ni++) {
                const uint32_t* br = Bs + (wn + ni * 8 + g) * 20 + kt * 8 + t;
                uint32_t b0 = br[0];
                uint32_t b1 = br[4];
                mma_bf16(c[0][ni], a[0][0], a[0][1], a[0][2], a[0][3], b0, b1);
                mma_bf16(c[1][ni], a[1][0], a[1][1], a[1][2], a[1][3], b0, b1);
            }
        }
    };
    auto loadW = [&](int buf, int k0, const bf16* W) {
        uint32_t Bs = sm0 + buf * B2_STAGE + 5120;
        #pragma unroll
        for (int i = 0; i < 4; i++) {
            int row = lrow + i * 64;
            CP16(Bs + row * 80 + lch * 2, W + (size_t)row * 256 + k0 + lch);
        }
    };
    auto zeroC = [&]() {
        #pragma unroll
        for (int mi = 0; mi < 2; mi++)
            #pragma unroll
            for (int ni = 0; ni < 8; ni++)
                #pragma unroll
                for (int r = 0; r < 4; r++) c[mi][ni][r] = 0.f;
    };

    // ================= phase 1: proj GEMM =================
    zeroC();
    auto load1 = [&](int buf, int k0) {
        uint32_t As = sm0 + buf * B2_STAGE;
        CP16(As + lrow * 80 + lch * 2, Aob + (size_t)(bm + lrow) * 256 + k0 + lch);
        loadW(buf, k0, Wp);
    };
    load1(0, 0); CP_COMMIT();
    load1(1, 32); CP_COMMIT();
    CP_WAIT1();
    __syncthreads();
    for (int it = 0; it < 8; ++it) {
        if (it + 2 < 8) load1((it + 2) % 3, (it + 2) * 32);
        CP_COMMIT();
        comp1(it % 3);
        CP_WAIT1();
        __syncthreads();
    }

    // ---- epilogue 1: bias + x residual -> x2 (to out), LN stats ----
    {
        float s0[2] = {0.f, 0.f}, q0[2] = {0.f, 0.f};
        float s1[2] = {0.f, 0.f}, q1[2] = {0.f, 0.f};
        #pragma unroll
        for (int mi = 0; mi < 2; mi++) {
            #pragma unroll
            for (int ni = 0; ni < 8; ni++) {
                int col = wn + ni * 8 + 2 * t;
                float b0 = pbias[col], b1 = pbias[col + 1];
                float2 ra = *(const float2*)(x + t0[mi] * 256 + col);
                float2 rb = *(const float2*)(x + t1[mi] * 256 + col);
                float v0 = c[mi][ni][0] + b0 + ra.x;
                float v1 = c[mi][ni][1] + b1 + ra.y;
                float v2 = c[mi][ni][2] + b0 + rb.x;
                float v3 = c[mi][ni][3] + b1 + rb.y;
                *(float2*)(out + t0[mi] * 256 + col) = make_float2(v0, v1);
                *(float2*)(out + t1[mi] * 256 + col) = make_float2(v2, v3);
                c[mi][ni][0] = v0; c[mi][ni][1] = v1;
                c[mi][ni][2] = v2; c[mi][ni][3] = v3;
                s0[mi] += v0 + v1; q0[mi] += v0 * v0 + v1 * v1;
                s1[mi] += v2 + v3; q1[mi] += v2 * v2 + v3 * v3;
            }
        }
        #pragma unroll
        for (int o = 1; o < 4; o <<= 1) {
            #pragma unroll
            for (int mi = 0; mi < 2; mi++) {
                s0[mi] += __shfl_xor_sync(0xffffffffu, s0[mi], o);
                q0[mi] += __shfl_xor_sync(0xffffffffu, q0[mi], o);
                s1[mi] += __shfl_xor_sync(0xffffffffu, s1[mi], o);
                q1[mi] += __shfl_xor_sync(0xffffffffu, q1[mi], o);
            }
        }
        if (t == 0) {
            #pragma unroll
            for (int mi = 0; mi < 2; mi++) {
                red[lr0[mi] * 8 + wnid * 2]     = s0[mi];
                red[lr0[mi] * 8 + wnid * 2 + 1] = q0[mi];
                red[lr1[mi] * 8 + wnid * 2]     = s1[mi];
                red[lr1[mi] * 8 + wnid * 2 + 1] = q1[mi];
            }
        }
        __syncthreads();
        #pragma unroll
        for (int mi = 0; mi < 2; mi++) {
            float sa = 0.f, qa = 0.f, sb = 0.f, qb2 = 0.f;
            #pragma unroll
            for (int j = 0; j < 4; j++) {
                sa  += red[lr0[mi] * 8 + j * 2];
                qa  += red[lr0[mi] * 8 + j * 2 + 1];
                sb  += red[lr1[mi] * 8 + j * 2];
                qb2 += red[lr1[mi] * 8 + j * 2 + 1];
            }
            float m0 = sa * (1.0f / 256.0f);
            float i0 = rsqrtf(qa * (1.0f / 256.0f) - m0 * m0 + EPS_F);
            float m1 = sb * (1.0f / 256.0f);
            float i1 = rsqrtf(qb2 * (1.0f / 256.0f) - m1 * m1 + EPS_F);
            #pragma unroll
            for (int ni = 0; ni < 8; ni++) {
                int col = wn + ni * 8 + 2 * t;
                float2 gg = *(const float2*)(g2 + col);
                float2 bb = *(const float2*)(b2 + col);
                lnW[lr0[mi] * 132 + (col >> 1)] =
                    pack_bf16((c[mi][ni][0] - m0) * i0 * gg.x + bb.x,
                              (c[mi][ni][1] - m0) * i0 * gg.y + bb.y);
                lnW[lr1[mi] * 132 + (col >> 1)] =
                    pack_bf16((c[mi][ni][2] - m1) * i1 * gg.x + bb.x,
                              (c[mi][ni][3] - m1) * i1 * gg.y + bb.y);
            }
        }
    }
    __syncthreads();

    // ================= phase 2: fc1 + GELU =================
    zeroC();
    loadW(0, 0, W1); CP_COMMIT();
    loadW(1, 32, W1); CP_COMMIT();
    CP_WAIT1();
    __syncthreads();
    for (int it = 0; it < 8; ++it) {
        if (it + 2 < 8) loadW((it + 2) % 3, (it + 2) * 32, W1);
        CP_COMMIT();
        compS(it % 3, it);
        CP_WAIT1();
        __syncthreads();
    }
    // epilogue 2: GELU -> overwrite ln tile with h (all reads of ln are done)
    #pragma unroll
    for (int mi = 0; mi < 2; mi++) {
        #pragma unroll
        for (int ni = 0; ni < 8; ni++) {
            int col = wn + ni * 8 + 2 * t;
            float b0 = fb1[col], b1 = fb1[col + 1];
            float v0 = c[mi][ni][0] + b0;
            float v1 = c[mi][ni][1] + b1;
            float v2 = c[mi][ni][2] + b0;
            float v3 = c[mi][ni][3] + b1;
            v0 = 0.5f * v0 * (1.0f + erff(v0 * 0.70710678118654752f));
            v1 = 0.5f * v1 * (1.0f + erff(v1 * 0.70710678118654752f));
            v2 = 0.5f * v2 * (1.0f + erff(v2 * 0.70710678118654752f));
            v3 = 0.5f * v3 * (1.0f + erff(v3 * 0.70710678118654752f));
            lnW[lr0[mi] * 132 + (col >> 1)] = pack_bf16(v0, v1);
            lnW[lr1[mi] * 132 + (col >> 1)] = pack_bf16(v2, v3);
        }
    }
    __syncthreads();

    // ================= phase 3: fc2 + residual (x2 from out) =================
    zeroC();
    loadW(0, 0, W2); CP_COMMIT();
    loadW(1, 32, W2); CP_COMMIT();
    CP_WAIT1();
    __syncthreads();
    for (int it = 0; it < 8; ++it) {
        if (it + 2 < 8) loadW((it + 2) % 3, (it + 2) * 32, W2);
        CP_COMMIT();
        compS(it % 3, it);
        CP_WAIT1();
        __syncthreads();
    }
    #pragma unroll
    for (int mi = 0; mi < 2; mi++) {
        #pragma unroll
        for (int ni = 0; ni < 8; ni++) {
            int col = wn + ni * 8 + 2 * t;
            float b0 = fb2[col], b1 = fb2[col + 1];
            float2 ra = *(const float2*)(out + t0[mi] * 256 + col);
            float2 rb = *(const float2*)(out + t1[mi] * 256 + col);
            *(float2*)(out + t0[mi] * 256 + col) =
                make_float2(c[mi][ni][0] + b0 + ra.x, c[mi][ni][1] + b1 + ra.y);
            *(float2*)(out + t1[mi] * 256 + col) =
                make_float2(c[mi][ni][2] + b0 + rb.x, c[mi][ni][3] + b1 + rb.y);
        }
    }
}

// ================ weight converts ================
__global__ void cvt_w(const float* __restrict__ W, bf16* __restrict__ Wt, int K, int N)
{
    __shared__ float tsm[32][33];
    int k0 = blockIdx.y * 32, n0 = blockIdx.x * 32;
    int tx = threadIdx.x, ty = threadIdx.y;
    tsm[ty][tx] = W[(size_t)(k0 + ty) * N + n0 + tx];
    __syncthreads();
    Wt[(size_t)(n0 + ty) * K + k0 + tx] = __float2bfloat16_rn(tsm[tx][ty]);
}

__global__ void cvt_wqkv(const float* __restrict__ W, bf16* __restrict__ Wt3)
{
    __shared__ float tsm[32][33];
    int n0 = blockIdx.x * 32, k0 = blockIdx.y * 32;
    int tx = threadIdx.x, ty = threadIdx.y;
    int n = n0 + tx;
    int h = n / 96, j = n % 96;
    int cidx = (j >> 5) * 256 + h * 32 + (j & 31);
    tsm[ty][tx] = W[(size_t)(k0 + ty) * 768 + cidx];
    __syncthreads();
    Wt3[(size_t)(n0 + ty) * 256 + k0 + tx] = __float2bfloat16_rn(tsm[tx][ty]);
}

// ---------------- launch ----------------
extern "C" void kernel_launch(void* const* d_in, const int* in_sizes, int n_in,
                              void* d_out, int out_size)
{
    const float* x       = (const float*)d_in[0];
    const float* norm1_g = (const float*)d_in[1];
    const float* norm1_b = (const float*)d_in[2];
    const float* qkv_w   = (const float*)d_in[3];
    const float* qkv_b   = (const float*)d_in[4];
    const float* rel_b   = (const float*)d_in[5];
    const float* proj_w  = (const float*)d_in[6];
    const float* proj_b  = (const float*)d_in[7];
    const float* norm2_g = (const float*)d_in[8];
    const float* norm2_b = (const float*)d_in[9];
    const float* fc1_w   = (const float*)d_in[10];
    const float* fc1_b   = (const float*)d_in[11];
    const float* fc2_w   = (const float*)d_in[12];
    const float* fc2_b   = (const float*)d_in[13];
    float* out = (float*)d_out;

    bf16 *p_ob, *p_wt;
    cudaGetSymbolAddress((void**)&p_ob, g_ob);
    cudaGetSymbolAddress((void**)&p_wt, g_wt);

    cudaFuncSetAttribute(qkv_attn, cudaFuncAttributeMaxDynamicSharedMemorySize, QA_SMEM);
    cudaFuncSetAttribute(block2,   cudaFuncAttributeMaxDynamicSharedMemorySize, B2_SMEM);

    // 0) weight converts
    dim3 cb(32, 32);
    cvt_wqkv<<<dim3(768 / 32, 256 / 32), cb>>>(qkv_w, p_wt + WT_QKV);
    cvt_w<<<dim3(256 / 32, 256 / 32), cb>>>(proj_w, p_wt + WT_PROJ, 256, 256);
    cvt_w<<<dim3(256 / 32, 256 / 32), cb>>>(fc1_w,  p_wt + WT_FC1, 256, 256);
    cvt_w<<<dim3(256 / 32, 256 / 32), cb>>>(fc2_w,  p_wt + WT_FC2, 256, 256);

    // 1) fused LN1 + QKV + attention -> attn out bf16 (windowed)
    qkv_attn<<<TTOT / 128, 256, QA_SMEM>>>(
        x, norm1_g, norm1_b, p_wt + WT_QKV, qkv_b, rel_b, p_ob);

    // 2) fused proj + residual + LN2 + fc1 + GELU + fc2 + residual -> out
    block2<<<TTOT / 64, 256, B2_SMEM>>>(
        p_ob, p_wt + WT_PROJ, proj_b, x, norm2_g, norm2_b,
        p_wt + WT_FC1, fc1_b, p_wt + WT_FC2, fc2_b, out);
}

// round 9
// speedup vs baseline: 6.9041x; 1.1161x over previous
#include <cuda_runtime.h>
#include <cuda_bf16.h>
#include <math.h>
#include <stdint.h>

// ---------------- problem constants ----------------
#define CC      256
#define NHEAD   8
#define HDIM    32
#define SSHIFT  4
#define NWIN    2048
#define TTOT    131072
#define SCALE_F 0.1767766952966369f
#define EPS_F   1e-5f

typedef __nv_bfloat16 bf16;
typedef __nv_bfloat162 bf162;

// ---------------- scratch ----------------
__device__ __align__(16) bf16  g_ob[TTOT * CC];          // attn out (bf16, windowed)
__device__ __align__(16) bf16  g_wt[768 * 256 + 3 * 256 * 256]; // bf16 weights

#define WT_QKV  0
#define WT_PROJ (768 * 256)
#define WT_FC1  (WT_PROJ + 256 * 256)
#define WT_FC2  (WT_FC1 + 256 * 256)

// ---------------- helpers ----------------
__device__ __forceinline__ uint32_t smem_u32(const void* p) {
    uint32_t a;
    asm("{ .reg .u64 t; cvta.to.shared.u64 t, %1; cvt.u32.u64 %0, t; }" : "=r"(a) : "l"(p));
    return a;
}
__device__ __forceinline__ void mma_bf16(float c[4],
                                         uint32_t a0, uint32_t a1, uint32_t a2, uint32_t a3,
                                         uint32_t b0, uint32_t b1) {
    asm volatile(
        "mma.sync.aligned.m16n8k16.row.col.f32.bf16.bf16.f32 "
        "{%0,%1,%2,%3}, {%4,%5,%6,%7}, {%8,%9}, {%0,%1,%2,%3};"
        : "+f"(c[0]), "+f"(c[1]), "+f"(c[2]), "+f"(c[3])
        : "r"(a0), "r"(a1), "r"(a2), "r"(a3), "r"(b0), "r"(b1));
}
__device__ __forceinline__ void ldsm_x4(uint32_t& r0, uint32_t& r1, uint32_t& r2, uint32_t& r3,
                                        uint32_t addr) {
    asm volatile("ldmatrix.sync.aligned.m8n8.x4.shared.b16 {%0,%1,%2,%3}, [%4];"
        : "=r"(r0), "=r"(r1), "=r"(r2), "=r"(r3) : "r"(addr));
}
__device__ __forceinline__ void ldsm_x2(uint32_t& r0, uint32_t& r1, uint32_t addr) {
    asm volatile("ldmatrix.sync.aligned.m8n8.x2.shared.b16 {%0,%1}, [%2];"
        : "=r"(r0), "=r"(r1) : "r"(addr));
}
__device__ __forceinline__ uint32_t pack_bf16(float x, float y) {
    bf162 v = __floats2bfloat162_rn(x, y);
    return *(uint32_t*)&v;
}
#define CP16(dst, src) \
    asm volatile("cp.async.cg.shared.global [%0], [%1], 16;" :: "r"(dst), "l"(src) : "memory")
#define CP_COMMIT() asm volatile("cp.async.commit_group;" ::: "memory")
#define CP_WAIT1()  asm volatile("cp.async.wait_group 1;" ::: "memory")
#define CP_WAIT0()  asm volatile("cp.async.wait_group 0;" ::: "memory")

// windowed row -> original token row (reverse shift)
__device__ __forceinline__ long unwin_row(long wr) {
    int batch = (int)(wr >> 14);
    int win   = ((int)wr >> 6) & 255;
    int token = (int)wr & 63;
    int ys = ((win >> 4) << 3) + (token >> 3);
    int xs = ((win & 15) << 3) + (token & 7);
    int y  = (ys + SSHIFT) & 127;
    int xx = (xs + SSHIFT) & 127;
    return (long)batch * 16384 + y * 128 + xx;
}

// ================ fused LN1 + QKV GEMM + windowed attention =========
#define QA_A    0
#define QA_B    67584
#define QA_QS   168960
#define QA_KS   179200
#define QA_VST  189440
#define QA_PS   199168
#define QA_LUT  217600
#define QA_QB   218624
#define QA_SMEM 221696

__global__ __launch_bounds__(256)
void qkv_attn(const float* __restrict__ x,
              const float* __restrict__ g1, const float* __restrict__ b1v,
              const bf16* __restrict__ Wt3, const float* __restrict__ qkvb,
              const float* __restrict__ rel_bias, bf16* __restrict__ out)
{
    extern __shared__ char smc[];
    float*    smF = (float*)smc;
    uint32_t* smW = (uint32_t*)smc;
    bf16*     smH = (bf16*)smc;
    uint32_t  sm0 = smem_u32(smc);

    int tid = threadIdx.x, warp = tid >> 5, lane = tid & 31;
    int g = lane >> 2, t = lane & 3;
    int lr  = lane & 7;
    int x4r = lr + ((lane >> 3) & 1) * 8;
    int x4c = ((lane >> 4) & 1) * 4;
    int x2c = ((lane >> 3) & 1) * 4;
    long bm = (long)blockIdx.x * 128;

    float* qb  = smF + QA_QB / 4;
    float* lut = smF + QA_LUT / 4;

    #pragma unroll
    for (int i = 0; i < 3; i++) qb[tid + i * 256] = qkvb[tid + i * 256];

    for (int i = 0; i < 16; i++) {
        int r = warp * 16 + i;
        long srow = unwin_row(bm + r);
        const float4* px = (const float4*)(x + srow * 256);
        float4 v0 = px[lane * 2], v1 = px[lane * 2 + 1];
        float s  = v0.x + v0.y + v0.z + v0.w + v1.x + v1.y + v1.z + v1.w;
        float s2 = v0.x*v0.x + v0.y*v0.y + v0.z*v0.z + v0.w*v0.w
                 + v1.x*v1.x + v1.y*v1.y + v1.z*v1.z + v1.w*v1.w;
        #pragma unroll
        for (int o = 16; o > 0; o >>= 1) {
            s  += __shfl_xor_sync(0xffffffffu, s,  o);
            s2 += __shfl_xor_sync(0xffffffffu, s2, o);
        }
        float mean = s * (1.0f / 256.0f);
        float inv = rsqrtf(s2 * (1.0f / 256.0f) - mean * mean + EPS_F);
        float4 ga = *(const float4*)(g1 + lane * 8);
        float4 gb = *(const float4*)(g1 + lane * 8 + 4);
        float4 ba = *(const float4*)(b1v + lane * 8);
        float4 bb = *(const float4*)(b1v + lane * 8 + 4);
        uint4 o4;
        o4.x = pack_bf16((v0.x - mean) * inv * ga.x + ba.x, (v0.y - mean) * inv * ga.y + ba.y);
        o4.y = pack_bf16((v0.z - mean) * inv * ga.z + ba.z, (v0.w - mean) * inv * ga.w + ba.w);
        o4.z = pack_bf16((v1.x - mean) * inv * gb.x + bb.x, (v1.y - mean) * inv * gb.y + bb.y);
        o4.w = pack_bf16((v1.z - mean) * inv * gb.z + bb.z, (v1.w - mean) * inv * gb.w + bb.w);
        *(uint4*)(smH + r * 264 + lane * 8) = o4;
    }
    __syncthreads();

    auto loadB = [&](int buf, int h) {
        uint32_t Bs = sm0 + QA_B + buf * 50688;
        const bf16* src = Wt3 + (size_t)h * 96 * 256;
        #pragma unroll
        for (int i = 0; i < 12; i++) {
            int e = tid + i * 256;
            int row = e >> 5, off = (e & 31) * 8;
            CP16(Bs + row * 528 + off * 2, src + row * 256 + off);
        }
    };

    int wm = (warp & 3) * 32;
    int wn = (warp >> 2) * 48;
    int w  = warp >> 2;
    int wm2 = (warp & 3) * 16;

    loadB(0, 0); CP_COMMIT();

    for (int h = 0; h < 8; h++) {
        if (h < 7) { loadB((h + 1) & 1, h + 1); CP_COMMIT(); CP_WAIT1(); }
        else CP_WAIT0();
        __syncthreads();

        float c[2][6][4];
        #pragma unroll
        for (int mi = 0; mi < 2; mi++)
            #pragma unroll
            for (int ni = 0; ni < 6; ni++)
                #pragma unroll
                for (int r = 0; r < 4; r++) c[mi][ni][r] = 0.f;

        {
            uint32_t Bb = sm0 + QA_B + (h & 1) * 50688;
            #pragma unroll
            for (int ks = 0; ks < 16; ks++) {
                int kw = ks * 8;
                uint32_t a[2][4];
                #pragma unroll
                for (int mi = 0; mi < 2; mi++)
                    ldsm_x4(a[mi][0], a[mi][1], a[mi][2], a[mi][3],
                            sm0 + ((wm + mi * 16 + x4r) * 132 + kw + x4c) * 4);
                #pragma unroll
                for (int ni = 0; ni < 6; ni++) {
                    uint32_t b0, b1;
                    ldsm_x2(b0, b1, Bb + ((wn + ni * 8 + lr) * 132 + kw + x2c) * 4);
                    mma_bf16(c[0][ni], a[0][0], a[0][1], a[0][2], a[0][3], b0, b1);
                    mma_bf16(c[1][ni], a[1][0], a[1][1], a[1][2], a[1][3], b0, b1);
                }
            }
        }
        __syncthreads();

        #pragma unroll
        for (int mi = 0; mi < 2; mi++) {
            int lr0 = wm + mi * 16 + g, lr1 = lr0 + 8;
            #pragma unroll
            for (int ni = 0; ni < 6; ni++) {
                int col = wn + ni * 8 + 2 * t;
                int mat = col >> 5, cj = col & 31;
                float bb0 = qb[mat * 256 + h * 32 + cj];
                float bb1 = qb[mat * 256 + h * 32 + cj + 1];
                float v0 = c[mi][ni][0] + bb0, v1 = c[mi][ni][1] + bb1;
                float v2 = c[mi][ni][2] + bb0, v3 = c[mi][ni][3] + bb1;
                if (mat == 0) {
                    smW[QA_QS / 4 + lr0 * 20 + (cj >> 1)] = pack_bf16(v0, v1);
                    smW[QA_QS / 4 + lr1 * 20 + (cj >> 1)] = pack_bf16(v2, v3);
                } else if (mat == 1) {
                    smW[QA_KS / 4 + lr0 * 20 + (cj >> 1)] = pack_bf16(v0, v1);
                    smW[QA_KS / 4 + lr1 * 20 + (cj >> 1)] = pack_bf16(v2, v3);
                } else {
                    bf16* ve = smH + QA_VST / 2;
                    ve[cj * 152 + lr0]       = __float2bfloat16_rn(v0);
                    ve[(cj + 1) * 152 + lr0] = __float2bfloat16_rn(v1);
                    ve[cj * 152 + lr1]       = __float2bfloat16_rn(v2);
                    ve[(cj + 1) * 152 + lr1] = __float2bfloat16_rn(v3);
                }
            }
        }
        if (tid < 225) lut[tid] = rel_bias[tid * 8 + h];
        __syncthreads();

        float s[8][4];
        #pragma unroll
        for (int ni = 0; ni < 8; ni++)
            #pragma unroll
            for (int r = 0; r < 4; r++) s[ni][r] = 0.f;

        #pragma unroll
        for (int kt = 0; kt < 2; kt++) {
            int kw = kt * 8;
            uint32_t a0, a1, a2, a3;
            ldsm_x4(a0, a1, a2, a3,
                    sm0 + QA_QS + ((w * 64 + wm2 + x4r) * 20 + kw + x4c) * 4);
            #pragma unroll
            for (int ni = 0; ni < 8; ni++) {
                uint32_t b0, b1;
                ldsm_x2(b0, b1, sm0 + QA_KS + ((w * 64 + ni * 8 + lr) * 20 + kw + x2c) * 4);
                mma_bf16(s[ni], a0, a1, a2, a3, b0, b1);
            }
        }

        int r0 = wm2 + g, r1 = wm2 + g + 8;
        int rh0 = r0 >> 3, rw0 = r0 & 7;
        int rh1 = r1 >> 3, rw1 = r1 & 7;
        float mx0 = -1e30f, mx1 = -1e30f;
        #pragma unroll
        for (int ni = 0; ni < 8; ni++) {
            #pragma unroll
            for (int cc2 = 0; cc2 < 2; cc2++) {
                int col = ni * 8 + 2 * t + cc2;
                int mh = col >> 3, mw = col & 7;
                s[ni][cc2]     = s[ni][cc2]     * SCALE_F + lut[(rh0 - mh + 7) * 15 + (rw0 - mw + 7)];
                s[ni][2 + cc2] = s[ni][2 + cc2] * SCALE_F + lut[(rh1 - mh + 7) * 15 + (rw1 - mw + 7)];
                mx0 = fmaxf(mx0, s[ni][cc2]);
                mx1 = fmaxf(mx1, s[ni][2 + cc2]);
            }
        }
        mx0 = fmaxf(mx0, __shfl_xor_sync(0xffffffffu, mx0, 1));
        mx0 = fmaxf(mx0, __shfl_xor_sync(0xffffffffu, mx0, 2));
        mx1 = fmaxf(mx1, __shfl_xor_sync(0xffffffffu, mx1, 1));
        mx1 = fmaxf(mx1, __shfl_xor_sync(0xffffffffu, mx1, 2));
        float sum0 = 0.f, sum1 = 0.f;
        #pragma unroll
        for (int ni = 0; ni < 8; ni++) {
            s[ni][0] = __expf(s[ni][0] - mx0); sum0 += s[ni][0];
            s[ni][1] = __expf(s[ni][1] - mx0); sum0 += s[ni][1];
            s[ni][2] = __expf(s[ni][2] - mx1); sum1 += s[ni][2];
            s[ni][3] = __expf(s[ni][3] - mx1); sum1 += s[ni][3];
        }
        sum0 += __shfl_xor_sync(0xffffffffu, sum0, 1);
        sum0 += __shfl_xor_sync(0xffffffffu, sum0, 2);
        sum1 += __shfl_xor_sync(0xffffffffu, sum1, 1);
        sum1 += __shfl_xor_sync(0xffffffffu, sum1, 2);
        float inv0 = 1.0f / sum0, inv1 = 1.0f / sum1;
        #pragma unroll
        for (int ni = 0; ni < 8; ni++) {
            smW[QA_PS / 4 + (w * 64 + r0) * 36 + ni * 4 + t] = pack_bf16(s[ni][0] * inv0, s[ni][1] * inv0);
            smW[QA_PS / 4 + (w * 64 + r1) * 36 + ni * 4 + t] = pack_bf16(s[ni][2] * inv1, s[ni][3] * inv1);
        }
        __syncwarp();

        float o[4][4];
        #pragma unroll
        for (int ni = 0; ni < 4; ni++)
            #pragma unroll
            for (int r = 0; r < 4; r++) o[ni][r] = 0.f;
        #pragma unroll
        for (int kt = 0; kt < 4; kt++) {
            int kw = kt * 8;
            uint32_t a0, a1, a2, a3;
            ldsm_x4(a0, a1, a2, a3,
                    sm0 + QA_PS + ((w * 64 + wm2 + x4r) * 36 + kw + x4c) * 4);
            #pragma unroll
            for (int ni = 0; ni < 4; ni++) {
                uint32_t b0, b1;
                ldsm_x2(b0, b1, sm0 + QA_VST + ((ni * 8 + lr) * 76 + w * 32 + kw + x2c) * 4);
                mma_bf16(o[ni], a0, a1, a2, a3, b0, b1);
            }
        }
        size_t ob0 = (size_t)(bm + w * 64 + r0) * 256 + h * 32;
        size_t ob1 = (size_t)(bm + w * 64 + r1) * 256 + h * 32;
        #pragma unroll
        for (int ni = 0; ni < 4; ni++) {
            int col = ni * 8 + 2 * t;
            *(uint32_t*)(out + ob0 + col) = pack_bf16(o[ni][0], o[ni][1]);
            *(uint32_t*)(out + ob1 + col) = pack_bf16(o[ni][2], o[ni][3]);
        }
    }
}

// ================ block2: proj + residual + LN2 + fc1 + GELU + fc2 + residual ====
#define B2_STAGE 25600
#define B2_LN    76800
#define B2_RED   110592
#define B2_SMEM  112640

__global__ __launch_bounds__(256, 2)
void block2(const bf16* __restrict__ Aob, const bf16* __restrict__ Wp,
            const float* __restrict__ pbias, const float* __restrict__ x,
            const float* __restrict__ g2, const float* __restrict__ b2,
            const bf16* __restrict__ W1, const float* __restrict__ fb1,
            const bf16* __restrict__ W2, const float* __restrict__ fb2,
            float* __restrict__ out)
{
    extern __shared__ char smc[];
    uint32_t sm0 = smem_u32(smc);
    uint32_t* lnW = (uint32_t*)(smc + B2_LN);
    float*    red = (float*)(smc + B2_RED);

    int tid = threadIdx.x, warp = tid >> 5, lane = tid & 31;
    int g = lane >> 2, t = lane & 3;
    int lr  = lane & 7;
    int x4r = lr + ((lane >> 3) & 1) * 8;
    int x4c = ((lane >> 4) & 1) * 4;
    int x2c = ((lane >> 3) & 1) * 4;
    long bm = (long)blockIdx.x * 64;
    int wm = (warp & 1) * 32, wn = (warp >> 1) * 64, wnid = warp >> 1;
    const int lrow = tid >> 2, lch = (tid & 3) * 8;

    int lr0[2], lr1[2];
    long t0[2], t1[2];
    #pragma unroll
    for (int mi = 0; mi < 2; mi++) {
        lr0[mi] = wm + mi * 16 + g;
        lr1[mi] = lr0[mi] + 8;
        t0[mi] = unwin_row(bm + lr0[mi]);
        t1[mi] = unwin_row(bm + lr1[mi]);
    }

    float c[2][8][4];

    auto comp1 = [&](int buf) {
        uint32_t Ab = sm0 + buf * B2_STAGE;
        uint32_t Bb = Ab + 5120;
        #pragma unroll
        for (int kt = 0; kt < 2; kt++) {
            int kw = kt * 8;
            uint32_t a[2][4];
            #pragma unroll
            for (int mi = 0; mi < 2; mi++)
                ldsm_x4(a[mi][0], a[mi][1], a[mi][2], a[mi][3],
                        Ab + ((wm + mi * 16 + x4r) * 20 + kw + x4c) * 4);
            #pragma unroll
            for (int ni = 0; ni < 8; ni++) {
                uint32_t b0, b1;
                ldsm_x2(b0, b1, Bb + ((wn + ni * 8 + lr) * 20 + kw + x2c) * 4);
                mma_bf16(c[0][ni], a[0][0], a[0][1], a[0][2], a[0][3], b0, b1);
                mma_bf16(c[1][ni], a[1][0], a[1][1], a[1][2], a[1][3], b0, b1);
            }
        }
    };
    auto compS = [&](int buf, int itk) {
        uint32_t Bb = sm0 + buf * B2_STAGE + 5120;
        #pragma unroll
        for (int kt = 0; kt < 2; kt++) {
            int kwg = itk * 16 + kt * 8;
            int kw = kt * 8;
            uint32_t a[2][4];
            #pragma unroll
            for (int mi = 0; mi < 2; mi++)
                ldsm_x4(a[mi][0], a[mi][1], a[mi][2], a[mi][3],
                        sm0 + B2_LN + ((wm + mi * 16 + x4r) * 132 + kwg + x4c) * 4);
            #pragma unroll
            for (int ni = 0; ni < 8; ni++) {
                uint32_t b0, b1;
                ldsm_x2(b0, b1, Bb + ((wn + ni * 8 + lr) * 20 + kw + x2c) * 4);
                mma_bf16(c[0][ni], a[0][0], a[0][1], a[0][2], a[0][3], b0, b1);
                mma_bf16(c[1][ni], a[1][0], a[1][1], a[1][2], a[1][3], b0, b1);
            }
        }
    };
    auto loadW = [&](int buf, int k0, const bf16* W) {
        uint32_t Bs = sm0 + buf * B2_STAGE + 5120;
        #pragma unroll
        for (int i = 0; i < 4; i++) {
            int row = lrow + i * 64;
            CP16(Bs + row * 80 + lch * 2, W + (size_t)row * 256 + k0 + lch);
        }
    };
    auto zeroC = [&]() {
        #pragma unroll
        for (int mi = 0; mi < 2; mi++)
            #pragma unroll
            for (int ni = 0; ni < 8; ni++)
                #pragma unroll
                for (int r = 0; r < 4; r++) c[mi][ni][r] = 0.f;
    };

    // ================= phase 1: proj GEMM =================
    zeroC();
    auto load1 = [&](int buf, int k0) {
        uint32_t As = sm0 + buf * B2_STAGE;
        CP16(As + lrow * 80 + lch * 2, Aob + (size_t)(bm + lrow) * 256 + k0 + lch);
        loadW(buf, k0, Wp);
    };
    load1(0, 0); CP_COMMIT();
    load1(1, 32); CP_COMMIT();
    CP_WAIT1();
    __syncthreads();
    for (int it = 0; it < 8; ++it) {
        if (it + 2 < 8) load1((it + 2) % 3, (it + 2) * 32);
        CP_COMMIT();
        comp1(it % 3);
        CP_WAIT1();
        __syncthreads();
    }

    // ---- epilogue 1: bias + x residual -> x2 (to out), LN stats ----
    {
        float s0[2] = {0.f, 0.f}, q0[2] = {0.f, 0.f};
        float s1[2] = {0.f, 0.f}, q1[2] = {0.f, 0.f};
        #pragma unroll
        for (int mi = 0; mi < 2; mi++) {
            #pragma unroll
            for (int ni = 0; ni < 8; ni++) {
                int col = wn + ni * 8 + 2 * t;
                float b0 = pbias[col], b1 = pbias[col + 1];
                float2 ra = *(const float2*)(x + t0[mi] * 256 + col);
                float2 rb = *(const float2*)(x + t1[mi] * 256 + col);
                float v0 = c[mi][ni][0] + b0 + ra.x;
                float v1 = c[mi][ni][1] + b1 + ra.y;
                float v2 = c[mi][ni][2] + b0 + rb.x;
                float v3 = c[mi][ni][3] + b1 + rb.y;
                *(float2*)(out + t0[mi] * 256 + col) = make_float2(v0, v1);
                *(float2*)(out + t1[mi] * 256 + col) = make_float2(v2, v3);
                c[mi][ni][0] = v0; c[mi][ni][1] = v1;
                c[mi][ni][2] = v2; c[mi][ni][3] = v3;
                s0[mi] += v0 + v1; q0[mi] += v0 * v0 + v1 * v1;
                s1[mi] += v2 + v3; q1[mi] += v2 * v2 + v3 * v3;
            }
        }
        #pragma unroll
        for (int o = 1; o < 4; o <<= 1) {
            #pragma unroll
            for (int mi = 0; mi < 2; mi++) {
                s0[mi] += __shfl_xor_sync(0xffffffffu, s0[mi], o);
                q0[mi] += __shfl_xor_sync(0xffffffffu, q0[mi], o);
                s1[mi] += __shfl_xor_sync(0xffffffffu, s1[mi], o);
                q1[mi] += __shfl_xor_sync(0xffffffffu, q1[mi], o);
            }
        }
        if (t == 0) {
            #pragma unroll
            for (int mi = 0; mi < 2; mi++) {
                red[lr0[mi] * 8 + wnid * 2]     = s0[mi];
                red[lr0[mi] * 8 + wnid * 2 + 1] = q0[mi];
                red[lr1[mi] * 8 + wnid * 2]     = s1[mi];
                red[lr1[mi] * 8 + wnid * 2 + 1] = q1[mi];
            }
        }
        __syncthreads();
        #pragma unroll
        for (int mi = 0; mi < 2; mi++) {
            float sa = 0.f, qa = 0.f, sb = 0.f, qb2 = 0.f;
            #pragma unroll
            for (int j = 0; j < 4; j++) {
                sa  += red[lr0[mi] * 8 + j * 2];
                qa  += red[lr0[mi] * 8 + j * 2 + 1];
                sb  += red[lr1[mi] * 8 + j * 2];
                qb2 += red[lr1[mi] * 8 + j * 2 + 1];
            }
            float m0 = sa * (1.0f / 256.0f);
            float i0 = rsqrtf(qa * (1.0f / 256.0f) - m0 * m0 + EPS_F);
            float m1 = sb * (1.0f / 256.0f);
            float i1 = rsqrtf(qb2 * (1.0f / 256.0f) - m1 * m1 + EPS_F);
            #pragma unroll
            for (int ni = 0; ni < 8; ni++) {
                int col = wn + ni * 8 + 2 * t;
                float2 gg = *(const float2*)(g2 + col);
                float2 bb = *(const float2*)(b2 + col);
                lnW[lr0[mi] * 132 + (col >> 1)] =
                    pack_bf16((c[mi][ni][0] - m0) * i0 * gg.x + bb.x,
                              (c[mi][ni][1] - m0) * i0 * gg.y + bb.y);
                lnW[lr1[mi] * 132 + (col >> 1)] =
                    pack_bf16((c[mi][ni][2] - m1) * i1 * gg.x + bb.x,
                              (c[mi][ni][3] - m1) * i1 * gg.y + bb.y);
            }
        }
    }
    __syncthreads();

    // ================= phase 2: fc1 + GELU =================
    zeroC();
    loadW(0, 0, W1); CP_COMMIT();
    loadW(1, 32, W1); CP_COMMIT();
    CP_WAIT1();
    __syncthreads();
    for (int it = 0; it < 8; ++it) {
        if (it + 2 < 8) loadW((it + 2) % 3, (it + 2) * 32, W1);
        CP_COMMIT();
        compS(it % 3, it);
        CP_WAIT1();
        __syncthreads();
    }
    #pragma unroll
    for (int mi = 0; mi < 2; mi++) {
        #pragma unroll
        for (int ni = 0; ni < 8; ni++) {
            int col = wn + ni * 8 + 2 * t;
            float b0 = fb1[col], b1 = fb1[col + 1];
            float v0 = c[mi][ni][0] + b0;
            float v1 = c[mi][ni][1] + b1;
            float v2 = c[mi][ni][2] + b0;
            float v3 = c[mi][ni][3] + b1;
            v0 = 0.5f * v0 * (1.0f + erff(v0 * 0.70710678118654752f));
            v1 = 0.5f * v1 * (1.0f + erff(v1 * 0.70710678118654752f));
            v2 = 0.5f * v2 * (1.0f + erff(v2 * 0.70710678118654752f));
            v3 = 0.5f * v3 * (1.0f + erff(v3 * 0.70710678118654752f));
            lnW[lr0[mi] * 132 + (col >> 1)] = pack_bf16(v0, v1);
            lnW[lr1[mi] * 132 + (col >> 1)] = pack_bf16(v2, v3);
        }
    }
    __syncthreads();

    // ================= phase 3: fc2 + residual (x2 from out) =================
    zeroC();
    loadW(0, 0, W2); CP_COMMIT();
    loadW(1, 32, W2); CP_COMMIT();
    CP_WAIT1();
    __syncthreads();
    for (int it = 0; it < 8; ++it) {
        if (it + 2 < 8) loadW((it + 2) % 3, (it + 2) * 32, W2);
        CP_COMMIT();
        compS(it % 3, it);
        CP_WAIT1();
        __syncthreads();
    }
    #pragma unroll
    for (int mi = 0; mi < 2; mi++) {
        #pragma unroll
        for (int ni = 0; ni < 8; ni++) {
            int col = wn + ni * 8 + 2 * t;
            float b0 = fb2[col], b1 = fb2[col + 1];
            float2 ra = *(const float2*)(out + t0[mi] * 256 + col);
            float2 rb = *(const float2*)(out + t1[mi] * 256 + col);
            *(float2*)(out + t0[mi] * 256 + col) =
                make_float2(c[mi][ni][0] + b0 + ra.x, c[mi][ni][1] + b1 + ra.y);
            *(float2*)(out + t1[mi] * 256 + col) =
                make_float2(c[mi][ni][2] + b0 + rb.x, c[mi][ni][3] + b1 + rb.y);
        }
    }
}

// ================ weight converts ================
__global__ void cvt_w(const float* __restrict__ W, bf16* __restrict__ Wt, int K, int N)
{
    __shared__ float tsm[32][33];
    int k0 = blockIdx.y * 32, n0 = blockIdx.x * 32;
    int tx = threadIdx.x, ty = threadIdx.y;
    tsm[ty][tx] = W[(size_t)(k0 + ty) * N + n0 + tx];
    __syncthreads();
    Wt[(size_t)(n0 + ty) * K + k0 + tx] = __float2bfloat16_rn(tsm[tx][ty]);
}

__global__ void cvt_wqkv(const float* __restrict__ W, bf16* __restrict__ Wt3)
{
    __shared__ float tsm[32][33];
    int n0 = blockIdx.x * 32, k0 = blockIdx.y * 32;
    int tx = threadIdx.x, ty = threadIdx.y;
    int n = n0 + tx;
    int h = n / 96, j = n % 96;
    int cidx = (j >> 5) * 256 + h * 32 + (j & 31);
    tsm[ty][tx] = W[(size_t)(k0 + ty) * 768 + cidx];
    __syncthreads();
    Wt3[(size_t)(n0 + ty) * 256 + k0 + tx] = __float2bfloat16_rn(tsm[tx][ty]);
}

// ---------------- launch ----------------
extern "C" void kernel_launch(void* const* d_in, const int* in_sizes, int n_in,
                              void* d_out, int out_size)
{
    const float* x       = (const float*)d_in[0];
    const float* norm1_g = (const float*)d_in[1];
    const float* norm1_b = (const float*)d_in[2];
    const float* qkv_w   = (const float*)d_in[3];
    const float* qkv_b   = (const float*)d_in[4];
    const float* rel_b   = (const float*)d_in[5];
    const float* proj_w  = (const float*)d_in[6];
    const float* proj_b  = (const float*)d_in[7];
    const float* norm2_g = (const float*)d_in[8];
    const float* norm2_b = (const float*)d_in[9];
    const float* fc1_w   = (const float*)d_in[10];
    const float* fc1_b   = (const float*)d_in[11];
    const float* fc2_w   = (const float*)d_in[12];
    const float* fc2_b   = (const float*)d_in[13];
    float* out = (float*)d_out;

    bf16 *p_ob, *p_wt;
    cudaGetSymbolAddress((void**)&p_ob, g_ob);
    cudaGetSymbolAddress((void**)&p_wt, g_wt);

    cudaFuncSetAttribute(qkv_attn, cudaFuncAttributeMaxDynamicSharedMemorySize, QA_SMEM);
    cudaFuncSetAttribute(block2,   cudaFuncAttributeMaxDynamicSharedMemorySize, B2_SMEM);

    // 0) weight converts
    dim3 cb(32, 32);
    cvt_wqkv<<<dim3(768 / 32, 256 / 32), cb>>>(qkv_w, p_wt + WT_QKV);
    cvt_w<<<dim3(256 / 32, 256 / 32), cb>>>(proj_w, p_wt + WT_PROJ, 256, 256);
    cvt_w<<<dim3(256 / 32, 256 / 32), cb>>>(fc1_w,  p_wt + WT_FC1, 256, 256);
    cvt_w<<<dim3(256 / 32, 256 / 32), cb>>>(fc2_w,  p_wt + WT_FC2, 256, 256);

    // 1) fused LN1 + QKV + attention -> attn out bf16 (windowed)
    qkv_attn<<<TTOT / 128, 256, QA_SMEM>>>(
        x, norm1_g, norm1_b, p_wt + WT_QKV, qkv_b, rel_b, p_ob);

    // 2) fused proj + residual + LN2 + fc1 + GELU + fc2 + residual -> out
    block2<<<TTOT / 64, 256, B2_SMEM>>>(
        p_ob, p_wt + WT_PROJ, proj_b, x, norm2_g, norm2_b,
        p_wt + WT_FC1, fc1_b, p_wt + WT_FC2, fc2_b, out);
}